// round 9
// baseline (speedup 1.0000x reference)
#include <cuda_runtime.h>
#include <cuda_bf16.h>
#include <math.h>
#include <stdint.h>

#define D_MODEL 1024
#define NH      16
#define DK      64
#define BATCH   2
#define SEQ     1024
#define BHT     (BATCH*NH)          // 32
#define MTOT    (BATCH*SEQ)         // 2048
#define ELEN    (2*SEQ-1)           // 2047

// ---------------- scratch (device globals; no allocation allowed) ----------
__device__ __nv_bfloat16 g_xh[MTOT*D_MODEL];
__device__ __nv_bfloat16 g_xl[MTOT*D_MODEL];
__device__ __nv_bfloat16 g_wh[4*D_MODEL*D_MODEL];  // Wq|Wk|Wv|Wo stacked rows
__device__ __nv_bfloat16 g_wl[4*D_MODEL*D_MODEL];
__device__ __nv_bfloat16 g_oh[MTOT*D_MODEL];
__device__ __nv_bfloat16 g_ol[MTOT*D_MODEL];

__device__ __nv_bfloat16 g_Qh[BHT*SEQ*DK];   // [bh][s][d], pre-scaled 1/8
__device__ __nv_bfloat16 g_Ql[BHT*SEQ*DK];
__device__ __nv_bfloat16 g_Kh[BHT*SEQ*DK];
__device__ __nv_bfloat16 g_Kl[BHT*SEQ*DK];
__device__ __nv_bfloat16 g_Vth[BHT*DK*SEQ];  // [bh][d][s]  (transposed)
__device__ __nv_bfloat16 g_Vtl[BHT*DK*SEQ];
__device__ __nv_bfloat16 g_Eh[ELEN*DK];
__device__ __nv_bfloat16 g_El[ELEN*DK];

// ---------------- helpers ---------------------------------------------------
__device__ __forceinline__ uint32_t smem_u32(const void* p) {
    uint32_t a;
    asm("{ .reg .u64 t; cvta.to.shared.u64 t, %1; cvt.u32.u64 %0, t; }"
        : "=r"(a) : "l"(p));
    return a;
}

#define CPA16(dst_u32, src_ptr) \
    asm volatile("cp.async.ca.shared.global [%0], [%1], 16;" \
                 :: "r"(dst_u32), "l"(src_ptr) : "memory")
#define CP_COMMIT() asm volatile("cp.async.commit_group;" ::: "memory")
#define CP_WAIT0()  asm volatile("cp.async.wait_group 0;" ::: "memory")
#define CP_WAIT1()  asm volatile("cp.async.wait_group 1;" ::: "memory")
#define CP_WAIT2()  asm volatile("cp.async.wait_group 2;" ::: "memory")
#define CP_WAIT3()  asm volatile("cp.async.wait_group 3;" ::: "memory")

#define LDMATRIX_X4(r0, r1, r2, r3, addr) \
    asm volatile("ldmatrix.sync.aligned.m8n8.x4.shared.b16 {%0,%1,%2,%3}, [%4];" \
                 : "=r"(r0), "=r"(r1), "=r"(r2), "=r"(r3) : "r"(addr))

#define MMA_BF16(c, a, b) \
    asm volatile("mma.sync.aligned.m16n8k16.row.col.f32.bf16.bf16.f32 " \
                 "{%0,%1,%2,%3}, {%4,%5,%6,%7}, {%8,%9}, {%0,%1,%2,%3};" \
                 : "+f"((c)[0]), "+f"((c)[1]), "+f"((c)[2]), "+f"((c)[3]) \
                 : "r"((a)[0]), "r"((a)[1]), "r"((a)[2]), "r"((a)[3]), \
                   "r"((b)[0]), "r"((b)[1]))

// Load B-fragments for TWO n-frags with one ldmatrix.x4.
__device__ __forceinline__ void ldmB(const __nv_bfloat16* base, int stride,
                                     int row0, int kcol, int lane, uint32_t* r)
{
    int sel = (lane >> 4) & 1;
    int row = row0 + sel * 8 + (lane & 7);
    int col = kcol + ((lane >> 3) & 1) * 8;
    uint32_t a = smem_u32(base + row * stride + col);
    LDMATRIX_X4(r[0], r[1], r[2], r[3], a);
}

__device__ __forceinline__ uint32_t pack_bf2(float lo, float hi) {
    __nv_bfloat162 t = __floats2bfloat162_rn(lo, hi);
    return *(uint32_t*)&t;
}
__device__ __forceinline__ void split_bf(float v, __nv_bfloat16& h, __nv_bfloat16& l) {
    h = __float2bfloat16_rn(v);
    l = __float2bfloat16_rn(v - __bfloat162float(h));
}

// ---------------------------------------------------------------------------
// fp32 -> bf16 hi/lo split conversion (x, 4 weights, Er)
// ---------------------------------------------------------------------------
__global__ void convert_xw_kernel(const float* __restrict__ x,
                                  const float* __restrict__ Wq, const float* __restrict__ Wk,
                                  const float* __restrict__ Wv, const float* __restrict__ Wo,
                                  const float* __restrict__ Er)
{
    const int NX = MTOT * D_MODEL / 4;
    const int NW = D_MODEL * D_MODEL / 4;
    const int NE = ELEN * DK / 4;
    int g = blockIdx.x * blockDim.x + threadIdx.x;
    if (g >= NX + 4 * NW + NE) return;
    const float* src;
    __nv_bfloat16 *dh, *dl;
    if (g < NX) { src = x + g * 4; dh = g_xh + g * 4; dl = g_xl + g * 4; }
    else if (g < NX + 4 * NW) {
        int wi = g - NX;
        int which = wi / NW;
        int off = wi - which * NW;
        const float* W = (which == 0) ? Wq : (which == 1) ? Wk : (which == 2) ? Wv : Wo;
        src = W + off * 4;
        dh = g_wh + (size_t)which * NW * 4 + off * 4;
        dl = g_wl + (size_t)which * NW * 4 + off * 4;
    } else {
        int ei = g - NX - 4 * NW;
        src = Er + ei * 4; dh = g_Eh + ei * 4; dl = g_El + ei * 4;
    }
    float4 v = *(const float4*)src;
    __nv_bfloat16 hv[4], lv[4];
    split_bf(v.x, hv[0], lv[0]); split_bf(v.y, hv[1], lv[1]);
    split_bf(v.z, hv[2], lv[2]); split_bf(v.w, hv[3], lv[3]);
    *(uint2*)dh = *(uint2*)hv;
    *(uint2*)dl = *(uint2*)lv;
}

// ---------------------------------------------------------------------------
// Split-bf16 mma.sync GEMM: 5-stage cp.async.ca pipeline, BK=32.
// ---------------------------------------------------------------------------
#define HSTR 40
#define MAT_HALVES (128*HSTR)
#define BUF_HALVES (4*MAT_HALVES)
#define GSTAGES 5
#define GEMM_DYN_SMEM (GSTAGES*BUF_HALVES*2)   // 204800 B

__global__ __launch_bounds__(256, 1)
void gemm_bf16_kernel(const __nv_bfloat16* __restrict__ Ah, const __nv_bfloat16* __restrict__ Al,
                      const __nv_bfloat16* __restrict__ Bh, const __nv_bfloat16* __restrict__ Bl,
                      const float* __restrict__ bias0, const float* __restrict__ bias1,
                      const float* __restrict__ bias2,
                      float* __restrict__ Cout, int mode)
{
    extern __shared__ __nv_bfloat16 sm[];

    const int tid  = threadIdx.x;
    const int wid  = tid >> 5;
    const int lane = tid & 31;
    const int warp_m = wid >> 2;
    const int warp_n = wid & 3;
    const int m0 = blockIdx.y * 128;
    const int n0 = blockIdx.x * 128;
    const int which = n0 >> 10;
    const int n0m = n0 & 1023;
    const float* biasm = (which == 0) ? bias0 : (which == 1) ? bias1 : bias2;

    float acc[4][4][4];
#pragma unroll
    for (int f = 0; f < 4; f++)
#pragma unroll
        for (int g = 0; g < 4; g++)
#pragma unroll
            for (int e = 0; e < 4; e++) acc[f][g][e] = 0.f;

    const int lrow = tid >> 2;          // 0..63
    const int lk   = (tid & 3) * 8;     // 0,8,16,24
    const uint32_t smb = smem_u32(sm);

    auto issue = [&](int c) {
        uint32_t bb = smb + (c % GSTAGES) * BUF_HALVES * 2;
        int kg = c * 32 + lk;
#pragma unroll
        for (int i = 0; i < 2; i++) {
            int row = lrow + i * 64;
            uint32_t doff = (row * HSTR + lk) * 2;
            CPA16(bb + 0 * MAT_HALVES * 2 + doff, Ah + (size_t)(m0 + row) * 1024 + kg);
            CPA16(bb + 1 * MAT_HALVES * 2 + doff, Al + (size_t)(m0 + row) * 1024 + kg);
            CPA16(bb + 2 * MAT_HALVES * 2 + doff, Bh + (size_t)(n0 + row) * 1024 + kg);
            CPA16(bb + 3 * MAT_HALVES * 2 + doff, Bl + (size_t)(n0 + row) * 1024 + kg);
        }
        CP_COMMIT();
    };

    issue(0); issue(1); issue(2); issue(3);

    const int a_r   = lane & 15;
    const int a_kof = (lane >> 4) * 8;

    for (int c = 0; c < 32; c++) {
        // ensure group c complete: outstanding groups are c..min(c+3,31)
        if (c < 29)      CP_WAIT3();
        else if (c == 29) CP_WAIT2();
        else if (c == 30) CP_WAIT1();
        else              CP_WAIT0();
        __syncthreads();
        if (c + 4 < 32) issue(c + 4);   // overlaps compute(c); writes buf (c-1)%5

        __nv_bfloat16* cb = sm + (c % GSTAGES) * BUF_HALVES;
#pragma unroll
        for (int ks = 0; ks < 2; ks++) {
            uint32_t aH[4][4], aL[4][4], bH[2][4], bL[2][4];
#pragma unroll
            for (int f = 0; f < 4; f++) {
                int row = warp_m * 64 + f * 16 + a_r;
                uint32_t addrH = smem_u32(&cb[0 * MAT_HALVES + row * HSTR + ks * 16 + a_kof]);
                LDMATRIX_X4(aH[f][0], aH[f][1], aH[f][2], aH[f][3], addrH);
                uint32_t addrL = smem_u32(&cb[1 * MAT_HALVES + row * HSTR + ks * 16 + a_kof]);
                LDMATRIX_X4(aL[f][0], aL[f][1], aL[f][2], aL[f][3], addrL);
            }
            ldmB(&cb[2 * MAT_HALVES], HSTR, warp_n * 32 +  0, ks * 16, lane, bH[0]);
            ldmB(&cb[2 * MAT_HALVES], HSTR, warp_n * 32 + 16, ks * 16, lane, bH[1]);
            ldmB(&cb[3 * MAT_HALVES], HSTR, warp_n * 32 +  0, ks * 16, lane, bL[0]);
            ldmB(&cb[3 * MAT_HALVES], HSTR, warp_n * 32 + 16, ks * 16, lane, bL[1]);
#pragma unroll
            for (int f = 0; f < 4; f++)
#pragma unroll
                for (int g = 0; g < 4; g++) {
                    const uint32_t* ph = &bH[g >> 1][(g & 1) * 2];
                    const uint32_t* pls = &bL[g >> 1][(g & 1) * 2];
                    MMA_BF16(acc[f][g], aH[f], ph);
                    MMA_BF16(acc[f][g], aH[f], pls);
                    MMA_BF16(acc[f][g], aL[f], ph);
                }
        }
        __syncthreads();
    }

    if (mode == 0) {
        const float scale = (which == 0) ? 0.125f : 1.0f;
#pragma unroll
        for (int f = 0; f < 4; f++) {
            int mrow0 = m0 + warp_m * 64 + f * 16 + (lane >> 2);
#pragma unroll
            for (int g = 0; g < 4; g++) {
                int ncol = n0m + warp_n * 32 + g * 8 + (lane & 3) * 2;
#pragma unroll
                for (int e = 0; e < 4; e++) {
                    int m = mrow0 + (e >> 1) * 8;
                    int nm = ncol + (e & 1);
                    int b = m >> 10, s = m & 1023;
                    int h = nm >> 6, d = nm & 63;
                    float val = (acc[f][g][e] + biasm[nm]) * scale;
                    __nv_bfloat16 vh, vl;
                    split_bf(val, vh, vl);
                    if (which == 2) {
                        size_t idx = ((size_t)(b * NH + h) * DK + d) * SEQ + s;
                        g_Vth[idx] = vh; g_Vtl[idx] = vl;
                    } else if (which == 0) {
                        size_t idx = ((size_t)(b * NH + h) * SEQ + s) * DK + d;
                        g_Qh[idx] = vh; g_Ql[idx] = vl;
                    } else {
                        size_t idx = ((size_t)(b * NH + h) * SEQ + s) * DK + d;
                        g_Kh[idx] = vh; g_Kl[idx] = vl;
                    }
                }
            }
        }
    } else {
#pragma unroll
        for (int f = 0; f < 4; f++) {
            int mrow0 = m0 + warp_m * 64 + f * 16 + (lane >> 2);
#pragma unroll
            for (int g = 0; g < 4; g++) {
                int ncol = n0 + warp_n * 32 + g * 8 + (lane & 3) * 2;
#pragma unroll
                for (int e = 0; e < 4; e++) {
                    int m = mrow0 + (e >> 1) * 8;
                    int n = ncol + (e & 1);
                    Cout[(size_t)m * D_MODEL + n] = acc[f][g][e] + biasm[n];
                }
            }
        }
    }
}

// ---------------------------------------------------------------------------
// Pipelined MMA flash-attention with rolling circular E buffer (256 rows).
// K/V double-buffered; E loaded incrementally (64 new rows per tile).
// Physical E row = er mod 256 (er = absolute Er row index).
// ---------------------------------------------------------------------------
#define ASTR  72
#define GBSTR 84
#define KV_STAGE_HALVES (4*64*ASTR)             // 18432 halves per stage
#define ST_KH 0
#define ST_KL (64*ASTR)
#define ST_VH (2*64*ASTR)
#define ST_VL (3*64*ASTR)
#define E_OFF_HALVES (2*KV_STAGE_HALVES)        // 36864
#define EH_OFF E_OFF_HALVES
#define EL_OFF (E_OFF_HALVES + 256*ASTR)
#define G_OFF_HALVES (E_OFF_HALVES + 2*256*ASTR) // 73728
#define ATTN_SMEM (G_OFF_HALVES*2 + 8*16*GBSTR*4)  // 147456 + 43008 = 190464 B

__device__ __forceinline__ void attn_issue_tile(
    uint32_t smb, int jt, int tid, int i0,
    const __nv_bfloat16* Khg, const __nv_bfloat16* Klg,
    const __nv_bfloat16* Vhg, const __nv_bfloat16* Vlg)
{
    const int j0 = jt * 64;
    const uint32_t kvbase = smb + (jt & 1) * KV_STAGE_HALVES * 2;
    for (int t = tid; t < 512; t += 256) {
        int r = t >> 3, c8 = (t & 7) * 8;
        uint32_t doff = (r * ASTR + c8) * 2;
        CPA16(kvbase + ST_KH * 2 + doff, Khg + (size_t)(j0 + r) * DK + c8);
        CPA16(kvbase + ST_KL * 2 + doff, Klg + (size_t)(j0 + r) * DK + c8);
        CPA16(kvbase + ST_VH * 2 + doff, Vhg + (size_t)r * SEQ + j0 + c8);
        CPA16(kvbase + ST_VL * 2 + doff, Vlg + (size_t)r * SEQ + j0 + c8);
    }
    // E rows: tile 0 loads the whole 192-row window; later tiles load the 64
    // new low rows [rbase_jt, rbase_jt+64).  er >= 0 always (min is 0).
    const int rlo = (SEQ - 1) + i0 - j0 - 63;
    const int cnt8 = (jt == 0) ? 1536 : 512;     // rows*8 uint4 transfers
    for (int t = tid; t < cnt8; t += 256) {
        int r = t >> 3, c8 = (t & 7) * 8;
        int er = rlo + r;
        int ers = (er > ELEN - 1) ? (ELEN - 1) : er;  // overflow rows never gathered
        uint32_t phys = (uint32_t)er & 255u;
        uint32_t doff = (phys * ASTR + c8) * 2;
        CPA16(smb + EH_OFF * 2 + doff, g_Eh + (size_t)ers * DK + c8);
        CPA16(smb + EL_OFF * 2 + doff, g_El + (size_t)ers * DK + c8);
    }
    CP_COMMIT();
}

__global__ __launch_bounds__(256)
void attn_mma_kernel()
{
    extern __shared__ __nv_bfloat16 smh[];
    float* sG = (float*)(smh + G_OFF_HALVES);
    __nv_bfloat16* sQh = (__nv_bfloat16*)sG;           // staging overlay (36864B<43008B)
    __nv_bfloat16* sQl = sQh + 128 * ASTR;
    __nv_bfloat16* sEh = smh + EH_OFF;
    __nv_bfloat16* sEl = smh + EL_OFF;

    const int tid  = threadIdx.x;
    const int lane = tid & 31;
    const int w    = tid >> 5;
    const int bh = blockIdx.y;
    const int i0 = blockIdx.x * 128;
    const int b = bh >> 4, h = bh & 15;

    const __nv_bfloat16* Qhg = g_Qh + (size_t)bh * SEQ * DK;
    const __nv_bfloat16* Qlg = g_Ql + (size_t)bh * SEQ * DK;
    const __nv_bfloat16* Khg = g_Kh + (size_t)bh * SEQ * DK;
    const __nv_bfloat16* Klg = g_Kl + (size_t)bh * SEQ * DK;
    const __nv_bfloat16* Vhg = g_Vth + (size_t)bh * DK * SEQ;
    const __nv_bfloat16* Vlg = g_Vtl + (size_t)bh * DK * SEQ;
    const uint32_t smb = smem_u32(smh);

    for (int t = tid; t < 1024; t += 256) {
        int r = t >> 3, c8 = (t & 7) * 8;
        *(uint4*)&sQh[r * ASTR + c8] = *(const uint4*)(Qhg + (size_t)(i0 + r) * DK + c8);
        *(uint4*)&sQl[r * ASTR + c8] = *(const uint4*)(Qlg + (size_t)(i0 + r) * DK + c8);
    }
    __syncthreads();
    uint32_t qh[4][4], ql[4][4];
#pragma unroll
    for (int ks = 0; ks < 4; ks++) {
        uint32_t aH = smem_u32(&sQh[(w * 16 + (lane & 15)) * ASTR + ks * 16 + (lane >> 4) * 8]);
        LDMATRIX_X4(qh[ks][0], qh[ks][1], qh[ks][2], qh[ks][3], aH);
        uint32_t aL = smem_u32(&sQl[(w * 16 + (lane & 15)) * ASTR + ks * 16 + (lane >> 4) * 8]);
        LDMATRIX_X4(ql[ks][0], ql[ks][1], ql[ks][2], ql[ks][3], aL);
    }
    __syncthreads();

    attn_issue_tile(smb, 0, tid, i0, Khg, Klg, Vhg, Vlg);

    float accO[8][4];
#pragma unroll
    for (int nf = 0; nf < 8; nf++)
#pragma unroll
        for (int e = 0; e < 4; e++) accO[nf][e] = 0.f;
    float rmax0 = -1e30f, rmax1 = -1e30f, rsum0 = 0.f, rsum1 = 0.f;

    const int r0 = lane >> 2;
    const int c0 = (lane & 3) * 2;
    float* sGw = sG + w * 16 * GBSTR;

    for (int jt = 0; jt < 16; jt++) {
        if (jt < 15) {
            attn_issue_tile(smb, jt + 1, tid, i0, Khg, Klg, Vhg, Vlg);
            CP_WAIT1();
        } else {
            CP_WAIT0();
        }
        __syncthreads();

        __nv_bfloat16* st = smh + (jt & 1) * KV_STAGE_HALVES;
        __nv_bfloat16* sKh = st + ST_KH;
        __nv_bfloat16* sKl = st + ST_KL;
        __nv_bfloat16* sVh = st + ST_VH;
        __nv_bfloat16* sVl = st + ST_VL;

        const int rbase = (SEQ - 1) + i0 - jt * 64 - 63;  // window low edge
        const int rb255 = rbase & 255;

        // ---- G = Q * Eband^T, band-limited: nf in [2w, 2w+10) ----
        float gac[10][4];
#pragma unroll
        for (int bi = 0; bi < 10; bi++)
#pragma unroll
            for (int e = 0; e < 4; e++) gac[bi][e] = 0.f;
#pragma unroll
        for (int ks = 0; ks < 4; ks++) {
#pragma unroll
            for (int bp = 0; bp < 5; bp++) {
                uint32_t eh4[4], el4[4];
                int row0 = (rb255 + (2 * w + 2 * bp) * 8) & 255;  // phys, no intra-block wrap
                ldmB(sEh, ASTR, row0, ks * 16, lane, eh4);
                ldmB(sEl, ASTR, row0, ks * 16, lane, el4);
                MMA_BF16(gac[2 * bp], qh[ks], eh4);
                MMA_BF16(gac[2 * bp], qh[ks], el4);
                MMA_BF16(gac[2 * bp], ql[ks], eh4);
                MMA_BF16(gac[2 * bp + 1], qh[ks], eh4 + 2);
                MMA_BF16(gac[2 * bp + 1], qh[ks], el4 + 2);
                MMA_BF16(gac[2 * bp + 1], ql[ks], eh4 + 2);
            }
        }
#pragma unroll
        for (int bi = 0; bi < 10; bi++) {
            *(float2*)&sGw[r0 * GBSTR + bi * 8 + c0] = make_float2(gac[bi][0], gac[bi][1]);
            *(float2*)&sGw[(r0 + 8) * GBSTR + bi * 8 + c0] = make_float2(gac[bi][2], gac[bi][3]);
        }

        // ---- S = Q * K^T ----
        float s[8][4];
#pragma unroll
        for (int nf = 0; nf < 8; nf++)
#pragma unroll
            for (int e = 0; e < 4; e++) s[nf][e] = 0.f;
#pragma unroll
        for (int ks = 0; ks < 4; ks++) {
#pragma unroll
            for (int gp = 0; gp < 4; gp++) {
                uint32_t kh4[4], kl4[4];
                ldmB(sKh, ASTR, gp * 16, ks * 16, lane, kh4);
                ldmB(sKl, ASTR, gp * 16, ks * 16, lane, kl4);
                MMA_BF16(s[2 * gp], qh[ks], kh4);
                MMA_BF16(s[2 * gp], qh[ks], kl4);
                MMA_BF16(s[2 * gp], ql[ks], kh4);
                MMA_BF16(s[2 * gp + 1], qh[ks], kh4 + 2);
                MMA_BF16(s[2 * gp + 1], qh[ks], kl4 + 2);
                MMA_BF16(s[2 * gp + 1], ql[ks], kh4 + 2);
            }
        }
        __syncwarp();

        // ---- gather BD from G band and add ----
#pragma unroll
        for (int nf = 0; nf < 8; nf++)
#pragma unroll
            for (int e = 0; e < 4; e++) {
                int iw = r0 + ((e >> 1) << 3);
                int jl = nf * 8 + c0 + (e & 1);
                s[nf][e] += sGw[iw * GBSTR + (iw - jl + 63)];
            }

        // ---- online softmax ----
        float mx0 = -1e30f, mx1 = -1e30f;
#pragma unroll
        for (int nf = 0; nf < 8; nf++) {
            mx0 = fmaxf(mx0, fmaxf(s[nf][0], s[nf][1]));
            mx1 = fmaxf(mx1, fmaxf(s[nf][2], s[nf][3]));
        }
#pragma unroll
        for (int o = 1; o <= 2; o <<= 1) {
            mx0 = fmaxf(mx0, __shfl_xor_sync(0xffffffffu, mx0, o));
            mx1 = fmaxf(mx1, __shfl_xor_sync(0xffffffffu, mx1, o));
        }
        float nm0 = fmaxf(rmax0, mx0), nm1 = fmaxf(rmax1, mx1);
        float al0 = __expf(rmax0 - nm0), al1 = __expf(rmax1 - nm1);
        rmax0 = nm0; rmax1 = nm1;
        float ls0 = 0.f, ls1 = 0.f;
#pragma unroll
        for (int nf = 0; nf < 8; nf++) {
            s[nf][0] = __expf(s[nf][0] - nm0);
            s[nf][1] = __expf(s[nf][1] - nm0);
            s[nf][2] = __expf(s[nf][2] - nm1);
            s[nf][3] = __expf(s[nf][3] - nm1);
            ls0 += s[nf][0] + s[nf][1];
            ls1 += s[nf][2] + s[nf][3];
        }
#pragma unroll
        for (int o = 1; o <= 2; o <<= 1) {
            ls0 += __shfl_xor_sync(0xffffffffu, ls0, o);
            ls1 += __shfl_xor_sync(0xffffffffu, ls1, o);
        }
        rsum0 = rsum0 * al0 + ls0;
        rsum1 = rsum1 * al1 + ls1;
#pragma unroll
        for (int nf = 0; nf < 8; nf++) {
            accO[nf][0] *= al0; accO[nf][1] *= al0;
            accO[nf][2] *= al1; accO[nf][3] *= al1;
        }

        // ---- pack P fragments (hi + residual-lo) ----
        uint32_t ph[4][4], pl[4][4];
#pragma unroll
        for (int ks = 0; ks < 4; ks++) {
            int f0 = 2 * ks, f1 = 2 * ks + 1;
            float rlo2[8];
#pragma unroll
            for (int e = 0; e < 4; e++) {
                rlo2[e]     = s[f0][e] - __bfloat162float(__float2bfloat16_rn(s[f0][e]));
                rlo2[4 + e] = s[f1][e] - __bfloat162float(__float2bfloat16_rn(s[f1][e]));
            }
            ph[ks][0] = pack_bf2(s[f0][0], s[f0][1]);
            ph[ks][1] = pack_bf2(s[f0][2], s[f0][3]);
            ph[ks][2] = pack_bf2(s[f1][0], s[f1][1]);
            ph[ks][3] = pack_bf2(s[f1][2], s[f1][3]);
            pl[ks][0] = pack_bf2(rlo2[0], rlo2[1]);
            pl[ks][1] = pack_bf2(rlo2[2], rlo2[3]);
            pl[ks][2] = pack_bf2(rlo2[4], rlo2[5]);
            pl[ks][3] = pack_bf2(rlo2[6], rlo2[7]);
        }

        // ---- O += P * V ----
#pragma unroll
        for (int ks = 0; ks < 4; ks++) {
#pragma unroll
            for (int gp = 0; gp < 4; gp++) {
                uint32_t vh4[4], vl4[4];
                ldmB(sVh, ASTR, gp * 16, ks * 16, lane, vh4);
                ldmB(sVl, ASTR, gp * 16, ks * 16, lane, vl4);
                MMA_BF16(accO[2 * gp], ph[ks], vh4);
                MMA_BF16(accO[2 * gp], ph[ks], vl4);
                MMA_BF16(accO[2 * gp], pl[ks], vh4);
                MMA_BF16(accO[2 * gp + 1], ph[ks], vh4 + 2);
                MMA_BF16(accO[2 * gp + 1], ph[ks], vl4 + 2);
                MMA_BF16(accO[2 * gp + 1], pl[ks], vh4 + 2);
            }
        }
        __syncthreads();
    }

    // ---- epilogue ----
    float inv0 = 1.0f / rsum0, inv1 = 1.0f / rsum1;
#pragma unroll
    for (int nf = 0; nf < 8; nf++)
#pragma unroll
        for (int e = 0; e < 4; e++) {
            int i = i0 + w * 16 + r0 + ((e >> 1) << 3);
            int d = nf * 8 + c0 + (e & 1);
            float v = accO[nf][e] * ((e < 2) ? inv0 : inv1);
            __nv_bfloat16 vh, vl;
            split_bf(v, vh, vl);
            size_t idx = ((size_t)(b * SEQ + i)) * D_MODEL + h * DK + d;
            g_oh[idx] = vh; g_ol[idx] = vl;
        }
}

// ---------------------------------------------------------------------------
extern "C" void kernel_launch(void* const* d_in, const int* in_sizes, int n_in,
                              void* d_out, int out_size)
{
    const float* x  = (const float*)d_in[0];
    const float* Wq = (const float*)d_in[1];
    const float* bq = (const float*)d_in[2];
    const float* Wk = (const float*)d_in[3];
    const float* bk = (const float*)d_in[4];
    const float* Wv = (const float*)d_in[5];
    const float* bv = (const float*)d_in[6];
    const float* Wo = (const float*)d_in[7];
    const float* bo = (const float*)d_in[8];
    const float* Er = (const float*)d_in[9];
    float* out = (float*)d_out;

    cudaFuncSetAttribute(gemm_bf16_kernel,
                         cudaFuncAttributeMaxDynamicSharedMemorySize, GEMM_DYN_SMEM);
    cudaFuncSetAttribute(attn_mma_kernel,
                         cudaFuncAttributeMaxDynamicSharedMemorySize, ATTN_SMEM);

    __nv_bfloat16 *xh, *xl, *wh, *wl, *oh, *ol;
    cudaGetSymbolAddress((void**)&xh, g_xh);
    cudaGetSymbolAddress((void**)&xl, g_xl);
    cudaGetSymbolAddress((void**)&wh, g_wh);
    cudaGetSymbolAddress((void**)&wl, g_wl);
    cudaGetSymbolAddress((void**)&oh, g_oh);
    cudaGetSymbolAddress((void**)&ol, g_ol);

    // 0) split x, weights, Er into bf16 hi/lo
    {
        int total = (MTOT * D_MODEL + 4 * D_MODEL * D_MODEL + ELEN * DK) / 4;
        convert_xw_kernel<<<(total + 255) / 256, 256>>>(x, Wq, Wk, Wv, Wo, Er);
    }
    // 1) fused QKV projection -> split-bf16 Q/K (head-major) + V^T
    {
        dim3 grid(3072 / 128, MTOT / 128);
        gemm_bf16_kernel<<<grid, 256, GEMM_DYN_SMEM>>>(
            xh, xl, wh, wl, bq, bk, bv, nullptr, 0);
    }
    // 2) pipelined MMA attention -> split-bf16 O
    {
        dim3 grid(SEQ / 128, BHT);           // 8 x 32
        attn_mma_kernel<<<grid, 256, ATTN_SMEM>>>();
    }
    // 3) output projection -> out
    {
        dim3 grid(D_MODEL / 128, MTOT / 128);
        gemm_bf16_kernel<<<grid, 256, GEMM_DYN_SMEM>>>(
            oh, ol, wh + (size_t)3 * D_MODEL * D_MODEL, wl + (size_t)3 * D_MODEL * D_MODEL,
            bo, bo, bo, out, 1);
    }
}

// round 10
// speedup vs baseline: 1.0887x; 1.0887x over previous
#include <cuda_runtime.h>
#include <cuda_bf16.h>
#include <math.h>
#include <stdint.h>

#define D_MODEL 1024
#define NH      16
#define DK      64
#define BATCH   2
#define SEQ     1024
#define BHT     (BATCH*NH)          // 32
#define MTOT    (BATCH*SEQ)         // 2048
#define ELEN    (2*SEQ-1)           // 2047

// ---------------- scratch (device globals; no allocation allowed) ----------
__device__ __nv_bfloat16 g_xh[MTOT*D_MODEL];
__device__ __nv_bfloat16 g_xl[MTOT*D_MODEL];
__device__ __nv_bfloat16 g_wh[4*D_MODEL*D_MODEL];  // Wq|Wk|Wv|Wo stacked rows
__device__ __nv_bfloat16 g_wl[4*D_MODEL*D_MODEL];
__device__ __nv_bfloat16 g_oh[MTOT*D_MODEL];
__device__ __nv_bfloat16 g_ol[MTOT*D_MODEL];

__device__ __nv_bfloat16 g_Qh[BHT*SEQ*DK];   // [bh][s][d], pre-scaled 1/8
__device__ __nv_bfloat16 g_Ql[BHT*SEQ*DK];
__device__ __nv_bfloat16 g_Kh[BHT*SEQ*DK];
__device__ __nv_bfloat16 g_Kl[BHT*SEQ*DK];
__device__ __nv_bfloat16 g_Vth[BHT*DK*SEQ];  // [bh][d][s]  (transposed)
__device__ __nv_bfloat16 g_Vtl[BHT*DK*SEQ];
__device__ __nv_bfloat16 g_Eh[ELEN*DK];
__device__ __nv_bfloat16 g_El[ELEN*DK];

// ---------------- helpers ---------------------------------------------------
__device__ __forceinline__ uint32_t smem_u32(const void* p) {
    uint32_t a;
    asm("{ .reg .u64 t; cvta.to.shared.u64 t, %1; cvt.u32.u64 %0, t; }"
        : "=r"(a) : "l"(p));
    return a;
}

#define CPA16(dst_u32, src_ptr) \
    asm volatile("cp.async.ca.shared.global [%0], [%1], 16;" \
                 :: "r"(dst_u32), "l"(src_ptr) : "memory")
#define CP_COMMIT() asm volatile("cp.async.commit_group;" ::: "memory")
#define CP_WAIT0()  asm volatile("cp.async.wait_group 0;" ::: "memory")
#define CP_WAIT1()  asm volatile("cp.async.wait_group 1;" ::: "memory")

#define LDMATRIX_X4(r0, r1, r2, r3, addr) \
    asm volatile("ldmatrix.sync.aligned.m8n8.x4.shared.b16 {%0,%1,%2,%3}, [%4];" \
                 : "=r"(r0), "=r"(r1), "=r"(r2), "=r"(r3) : "r"(addr))

#define MMA_BF16(c, a, b) \
    asm volatile("mma.sync.aligned.m16n8k16.row.col.f32.bf16.bf16.f32 " \
                 "{%0,%1,%2,%3}, {%4,%5,%6,%7}, {%8,%9}, {%0,%1,%2,%3};" \
                 : "+f"((c)[0]), "+f"((c)[1]), "+f"((c)[2]), "+f"((c)[3]) \
                 : "r"((a)[0]), "r"((a)[1]), "r"((a)[2]), "r"((a)[3]), \
                   "r"((b)[0]), "r"((b)[1]))

// Load B-fragments for TWO n-frags with one ldmatrix.x4.
__device__ __forceinline__ void ldmB(const __nv_bfloat16* base, int stride,
                                     int row0, int kcol, int lane, uint32_t* r)
{
    int sel = (lane >> 4) & 1;
    int row = row0 + sel * 8 + (lane & 7);
    int col = kcol + ((lane >> 3) & 1) * 8;
    uint32_t a = smem_u32(base + row * stride + col);
    LDMATRIX_X4(r[0], r[1], r[2], r[3], a);
}

__device__ __forceinline__ uint32_t pack_bf2(float lo, float hi) {
    __nv_bfloat162 t = __floats2bfloat162_rn(lo, hi);
    return *(uint32_t*)&t;
}
__device__ __forceinline__ void split_bf(float v, __nv_bfloat16& h, __nv_bfloat16& l) {
    h = __float2bfloat16_rn(v);
    l = __float2bfloat16_rn(v - __bfloat162float(h));
}

// ---------------------------------------------------------------------------
// fp32 -> bf16 hi/lo split conversion (x, 4 weights, Er)
// ---------------------------------------------------------------------------
__global__ void convert_xw_kernel(const float* __restrict__ x,
                                  const float* __restrict__ Wq, const float* __restrict__ Wk,
                                  const float* __restrict__ Wv, const float* __restrict__ Wo,
                                  const float* __restrict__ Er)
{
    const int NX = MTOT * D_MODEL / 4;
    const int NW = D_MODEL * D_MODEL / 4;
    const int NE = ELEN * DK / 4;
    int g = blockIdx.x * blockDim.x + threadIdx.x;
    if (g >= NX + 4 * NW + NE) return;
    const float* src;
    __nv_bfloat16 *dh, *dl;
    if (g < NX) { src = x + g * 4; dh = g_xh + g * 4; dl = g_xl + g * 4; }
    else if (g < NX + 4 * NW) {
        int wi = g - NX;
        int which = wi / NW;
        int off = wi - which * NW;
        const float* W = (which == 0) ? Wq : (which == 1) ? Wk : (which == 2) ? Wv : Wo;
        src = W + off * 4;
        dh = g_wh + (size_t)which * NW * 4 + off * 4;
        dl = g_wl + (size_t)which * NW * 4 + off * 4;
    } else {
        int ei = g - NX - 4 * NW;
        src = Er + ei * 4; dh = g_Eh + ei * 4; dl = g_El + ei * 4;
    }
    float4 v = *(const float4*)src;
    __nv_bfloat16 hv[4], lv[4];
    split_bf(v.x, hv[0], lv[0]); split_bf(v.y, hv[1], lv[1]);
    split_bf(v.z, hv[2], lv[2]); split_bf(v.w, hv[3], lv[3]);
    *(uint2*)dh = *(uint2*)hv;
    *(uint2*)dl = *(uint2*)lv;
}

// ---------------------------------------------------------------------------
// Split-bf16 mma.sync GEMM: 3-stage cp.async.ca pipeline, BK=32 (R8 config).
// ---------------------------------------------------------------------------
#define HSTR 40
#define MAT_HALVES (128*HSTR)
#define BUF_HALVES (4*MAT_HALVES)
#define GSTAGES 3
#define GEMM_DYN_SMEM (GSTAGES*BUF_HALVES*2)   // 122880 B  (leaves ~105KB L1D)

__global__ __launch_bounds__(256, 1)
void gemm_bf16_kernel(const __nv_bfloat16* __restrict__ Ah, const __nv_bfloat16* __restrict__ Al,
                      const __nv_bfloat16* __restrict__ Bh, const __nv_bfloat16* __restrict__ Bl,
                      const float* __restrict__ bias0, const float* __restrict__ bias1,
                      const float* __restrict__ bias2,
                      float* __restrict__ Cout, int mode)
{
    extern __shared__ __nv_bfloat16 sm[];

    const int tid  = threadIdx.x;
    const int wid  = tid >> 5;
    const int lane = tid & 31;
    const int warp_m = wid >> 2;
    const int warp_n = wid & 3;
    const int m0 = blockIdx.y * 128;
    const int n0 = blockIdx.x * 128;
    const int which = n0 >> 10;
    const int n0m = n0 & 1023;
    const float* biasm = (which == 0) ? bias0 : (which == 1) ? bias1 : bias2;

    float acc[4][4][4];
#pragma unroll
    for (int f = 0; f < 4; f++)
#pragma unroll
        for (int g = 0; g < 4; g++)
#pragma unroll
            for (int e = 0; e < 4; e++) acc[f][g][e] = 0.f;

    const int lrow = tid >> 2;          // 0..63
    const int lk   = (tid & 3) * 8;     // 0,8,16,24
    const uint32_t smb = smem_u32(sm);

    auto issue = [&](int c) {
        uint32_t bb = smb + (c % GSTAGES) * BUF_HALVES * 2;
        int kg = c * 32 + lk;
#pragma unroll
        for (int i = 0; i < 2; i++) {
            int row = lrow + i * 64;
            uint32_t doff = (row * HSTR + lk) * 2;
            CPA16(bb + 0 * MAT_HALVES * 2 + doff, Ah + (size_t)(m0 + row) * 1024 + kg);
            CPA16(bb + 1 * MAT_HALVES * 2 + doff, Al + (size_t)(m0 + row) * 1024 + kg);
            CPA16(bb + 2 * MAT_HALVES * 2 + doff, Bh + (size_t)(n0 + row) * 1024 + kg);
            CPA16(bb + 3 * MAT_HALVES * 2 + doff, Bl + (size_t)(n0 + row) * 1024 + kg);
        }
        CP_COMMIT();
    };

    issue(0);
    issue(1);

    const int a_r   = lane & 15;
    const int a_kof = (lane >> 4) * 8;

    for (int c = 0; c < 32; c++) {
        if (c < 31) CP_WAIT1(); else CP_WAIT0();
        __syncthreads();
        if (c + 2 < 32) issue(c + 2);

        __nv_bfloat16* cb = sm + (c % GSTAGES) * BUF_HALVES;
#pragma unroll
        for (int ks = 0; ks < 2; ks++) {
            uint32_t aH[4][4], aL[4][4], bH[2][4], bL[2][4];
#pragma unroll
            for (int f = 0; f < 4; f++) {
                int row = warp_m * 64 + f * 16 + a_r;
                uint32_t addrH = smem_u32(&cb[0 * MAT_HALVES + row * HSTR + ks * 16 + a_kof]);
                LDMATRIX_X4(aH[f][0], aH[f][1], aH[f][2], aH[f][3], addrH);
                uint32_t addrL = smem_u32(&cb[1 * MAT_HALVES + row * HSTR + ks * 16 + a_kof]);
                LDMATRIX_X4(aL[f][0], aL[f][1], aL[f][2], aL[f][3], addrL);
            }
            ldmB(&cb[2 * MAT_HALVES], HSTR, warp_n * 32 +  0, ks * 16, lane, bH[0]);
            ldmB(&cb[2 * MAT_HALVES], HSTR, warp_n * 32 + 16, ks * 16, lane, bH[1]);
            ldmB(&cb[3 * MAT_HALVES], HSTR, warp_n * 32 +  0, ks * 16, lane, bL[0]);
            ldmB(&cb[3 * MAT_HALVES], HSTR, warp_n * 32 + 16, ks * 16, lane, bL[1]);
#pragma unroll
            for (int f = 0; f < 4; f++)
#pragma unroll
                for (int g = 0; g < 4; g++) {
                    const uint32_t* ph = &bH[g >> 1][(g & 1) * 2];
                    const uint32_t* pls = &bL[g >> 1][(g & 1) * 2];
                    MMA_BF16(acc[f][g], aH[f], ph);
                    MMA_BF16(acc[f][g], aH[f], pls);
                    MMA_BF16(acc[f][g], aL[f], ph);
                }
        }
        __syncthreads();
    }

    if (mode == 0) {
        const float scale = (which == 0) ? 0.125f : 1.0f;
#pragma unroll
        for (int f = 0; f < 4; f++) {
            int mrow0 = m0 + warp_m * 64 + f * 16 + (lane >> 2);
#pragma unroll
            for (int g = 0; g < 4; g++) {
                int ncol = n0m + warp_n * 32 + g * 8 + (lane & 3) * 2;
#pragma unroll
                for (int e = 0; e < 4; e++) {
                    int m = mrow0 + (e >> 1) * 8;
                    int nm = ncol + (e & 1);
                    int b = m >> 10, s = m & 1023;
                    int h = nm >> 6, d = nm & 63;
                    float val = (acc[f][g][e] + biasm[nm]) * scale;
                    __nv_bfloat16 vh, vl;
                    split_bf(val, vh, vl);
                    if (which == 2) {
                        size_t idx = ((size_t)(b * NH + h) * DK + d) * SEQ + s;
                        g_Vth[idx] = vh; g_Vtl[idx] = vl;
                    } else if (which == 0) {
                        size_t idx = ((size_t)(b * NH + h) * SEQ + s) * DK + d;
                        g_Qh[idx] = vh; g_Ql[idx] = vl;
                    } else {
                        size_t idx = ((size_t)(b * NH + h) * SEQ + s) * DK + d;
                        g_Kh[idx] = vh; g_Kl[idx] = vl;
                    }
                }
            }
        }
    } else {
#pragma unroll
        for (int f = 0; f < 4; f++) {
            int mrow0 = m0 + warp_m * 64 + f * 16 + (lane >> 2);
#pragma unroll
            for (int g = 0; g < 4; g++) {
                int ncol = n0 + warp_n * 32 + g * 8 + (lane & 3) * 2;
#pragma unroll
                for (int e = 0; e < 4; e++) {
                    int m = mrow0 + (e >> 1) * 8;
                    int n = ncol + (e & 1);
                    Cout[(size_t)m * D_MODEL + n] = acc[f][g][e] + biasm[n];
                }
            }
        }
    }
}

// ---------------------------------------------------------------------------
// Pipelined MMA flash-attention with rolling circular E buffer (R9 version).
// ---------------------------------------------------------------------------
#define ASTR  72
#define GBSTR 84
#define KV_STAGE_HALVES (4*64*ASTR)             // 18432 halves per stage
#define ST_KH 0
#define ST_KL (64*ASTR)
#define ST_VH (2*64*ASTR)
#define ST_VL (3*64*ASTR)
#define E_OFF_HALVES (2*KV_STAGE_HALVES)        // 36864
#define EH_OFF E_OFF_HALVES
#define EL_OFF (E_OFF_HALVES + 256*ASTR)
#define G_OFF_HALVES (E_OFF_HALVES + 2*256*ASTR) // 73728
#define ATTN_SMEM (G_OFF_HALVES*2 + 8*16*GBSTR*4)  // 190464 B

__device__ __forceinline__ void attn_issue_tile(
    uint32_t smb, int jt, int tid, int i0,
    const __nv_bfloat16* Khg, const __nv_bfloat16* Klg,
    const __nv_bfloat16* Vhg, const __nv_bfloat16* Vlg)
{
    const int j0 = jt * 64;
    const uint32_t kvbase = smb + (jt & 1) * KV_STAGE_HALVES * 2;
    for (int t = tid; t < 512; t += 256) {
        int r = t >> 3, c8 = (t & 7) * 8;
        uint32_t doff = (r * ASTR + c8) * 2;
        CPA16(kvbase + ST_KH * 2 + doff, Khg + (size_t)(j0 + r) * DK + c8);
        CPA16(kvbase + ST_KL * 2 + doff, Klg + (size_t)(j0 + r) * DK + c8);
        CPA16(kvbase + ST_VH * 2 + doff, Vhg + (size_t)r * SEQ + j0 + c8);
        CPA16(kvbase + ST_VL * 2 + doff, Vlg + (size_t)r * SEQ + j0 + c8);
    }
    const int rlo = (SEQ - 1) + i0 - j0 - 63;
    const int cnt8 = (jt == 0) ? 1536 : 512;
    for (int t = tid; t < cnt8; t += 256) {
        int r = t >> 3, c8 = (t & 7) * 8;
        int er = rlo + r;
        int ers = (er > ELEN - 1) ? (ELEN - 1) : er;
        uint32_t phys = (uint32_t)er & 255u;
        uint32_t doff = (phys * ASTR + c8) * 2;
        CPA16(smb + EH_OFF * 2 + doff, g_Eh + (size_t)ers * DK + c8);
        CPA16(smb + EL_OFF * 2 + doff, g_El + (size_t)ers * DK + c8);
    }
    CP_COMMIT();
}

__global__ __launch_bounds__(256)
void attn_mma_kernel()
{
    extern __shared__ __nv_bfloat16 smh[];
    float* sG = (float*)(smh + G_OFF_HALVES);
    __nv_bfloat16* sQh = (__nv_bfloat16*)sG;
    __nv_bfloat16* sQl = sQh + 128 * ASTR;
    __nv_bfloat16* sEh = smh + EH_OFF;
    __nv_bfloat16* sEl = smh + EL_OFF;

    const int tid  = threadIdx.x;
    const int lane = tid & 31;
    const int w    = tid >> 5;
    const int bh = blockIdx.y;
    const int i0 = blockIdx.x * 128;
    const int b = bh >> 4, h = bh & 15;

    const __nv_bfloat16* Qhg = g_Qh + (size_t)bh * SEQ * DK;
    const __nv_bfloat16* Qlg = g_Ql + (size_t)bh * SEQ * DK;
    const __nv_bfloat16* Khg = g_Kh + (size_t)bh * SEQ * DK;
    const __nv_bfloat16* Klg = g_Kl + (size_t)bh * SEQ * DK;
    const __nv_bfloat16* Vhg = g_Vth + (size_t)bh * DK * SEQ;
    const __nv_bfloat16* Vlg = g_Vtl + (size_t)bh * DK * SEQ;
    const uint32_t smb = smem_u32(smh);

    for (int t = tid; t < 1024; t += 256) {
        int r = t >> 3, c8 = (t & 7) * 8;
        *(uint4*)&sQh[r * ASTR + c8] = *(const uint4*)(Qhg + (size_t)(i0 + r) * DK + c8);
        *(uint4*)&sQl[r * ASTR + c8] = *(const uint4*)(Qlg + (size_t)(i0 + r) * DK + c8);
    }
    __syncthreads();
    uint32_t qh[4][4], ql[4][4];
#pragma unroll
    for (int ks = 0; ks < 4; ks++) {
        uint32_t aH = smem_u32(&sQh[(w * 16 + (lane & 15)) * ASTR + ks * 16 + (lane >> 4) * 8]);
        LDMATRIX_X4(qh[ks][0], qh[ks][1], qh[ks][2], qh[ks][3], aH);
        uint32_t aL = smem_u32(&sQl[(w * 16 + (lane & 15)) * ASTR + ks * 16 + (lane >> 4) * 8]);
        LDMATRIX_X4(ql[ks][0], ql[ks][1], ql[ks][2], ql[ks][3], aL);
    }
    __syncthreads();

    attn_issue_tile(smb, 0, tid, i0, Khg, Klg, Vhg, Vlg);

    float accO[8][4];
#pragma unroll
    for (int nf = 0; nf < 8; nf++)
#pragma unroll
        for (int e = 0; e < 4; e++) accO[nf][e] = 0.f;
    float rmax0 = -1e30f, rmax1 = -1e30f, rsum0 = 0.f, rsum1 = 0.f;

    const int r0 = lane >> 2;
    const int c0 = (lane & 3) * 2;
    float* sGw = sG + w * 16 * GBSTR;

    for (int jt = 0; jt < 16; jt++) {
        if (jt < 15) {
            attn_issue_tile(smb, jt + 1, tid, i0, Khg, Klg, Vhg, Vlg);
            CP_WAIT1();
        } else {
            CP_WAIT0();
        }
        __syncthreads();

        __nv_bfloat16* st = smh + (jt & 1) * KV_STAGE_HALVES;
        __nv_bfloat16* sKh = st + ST_KH;
        __nv_bfloat16* sKl = st + ST_KL;
        __nv_bfloat16* sVh = st + ST_VH;
        __nv_bfloat16* sVl = st + ST_VL;

        const int rbase = (SEQ - 1) + i0 - jt * 64 - 63;
        const int rb255 = rbase & 255;

        // ---- G = Q * Eband^T, band-limited: nf in [2w, 2w+10) ----
        float gac[10][4];
#pragma unroll
        for (int bi = 0; bi < 10; bi++)
#pragma unroll
            for (int e = 0; e < 4; e++) gac[bi][e] = 0.f;
#pragma unroll
        for (int ks = 0; ks < 4; ks++) {
#pragma unroll
            for (int bp = 0; bp < 5; bp++) {
                uint32_t eh4[4], el4[4];
                int row0 = (rb255 + (2 * w + 2 * bp) * 8) & 255;
                ldmB(sEh, ASTR, row0, ks * 16, lane, eh4);
                ldmB(sEl, ASTR, row0, ks * 16, lane, el4);
                MMA_BF16(gac[2 * bp], qh[ks], eh4);
                MMA_BF16(gac[2 * bp], qh[ks], el4);
                MMA_BF16(gac[2 * bp], ql[ks], eh4);
                MMA_BF16(gac[2 * bp + 1], qh[ks], eh4 + 2);
                MMA_BF16(gac[2 * bp + 1], qh[ks], el4 + 2);
                MMA_BF16(gac[2 * bp + 1], ql[ks], eh4 + 2);
            }
        }
#pragma unroll
        for (int bi = 0; bi < 10; bi++) {
            *(float2*)&sGw[r0 * GBSTR + bi * 8 + c0] = make_float2(gac[bi][0], gac[bi][1]);
            *(float2*)&sGw[(r0 + 8) * GBSTR + bi * 8 + c0] = make_float2(gac[bi][2], gac[bi][3]);
        }

        // ---- S = Q * K^T ----
        float s[8][4];
#pragma unroll
        for (int nf = 0; nf < 8; nf++)
#pragma unroll
            for (int e = 0; e < 4; e++) s[nf][e] = 0.f;
#pragma unroll
        for (int ks = 0; ks < 4; ks++) {
#pragma unroll
            for (int gp = 0; gp < 4; gp++) {
                uint32_t kh4[4], kl4[4];
                ldmB(sKh, ASTR, gp * 16, ks * 16, lane, kh4);
                ldmB(sKl, ASTR, gp * 16, ks * 16, lane, kl4);
                MMA_BF16(s[2 * gp], qh[ks], kh4);
                MMA_BF16(s[2 * gp], qh[ks], kl4);
                MMA_BF16(s[2 * gp], ql[ks], kh4);
                MMA_BF16(s[2 * gp + 1], qh[ks], kh4 + 2);
                MMA_BF16(s[2 * gp + 1], qh[ks], kl4 + 2);
                MMA_BF16(s[2 * gp + 1], ql[ks], kh4 + 2);
            }
        }
        __syncwarp();

        // ---- gather BD from G band and add ----
#pragma unroll
        for (int nf = 0; nf < 8; nf++)
#pragma unroll
            for (int e = 0; e < 4; e++) {
                int iw = r0 + ((e >> 1) << 3);
                int jl = nf * 8 + c0 + (e & 1);
                s[nf][e] += sGw[iw * GBSTR + (iw - jl + 63)];
            }

        // ---- online softmax ----
        float mx0 = -1e30f, mx1 = -1e30f;
#pragma unroll
        for (int nf = 0; nf < 8; nf++) {
            mx0 = fmaxf(mx0, fmaxf(s[nf][0], s[nf][1]));
            mx1 = fmaxf(mx1, fmaxf(s[nf][2], s[nf][3]));
        }
#pragma unroll
        for (int o = 1; o <= 2; o <<= 1) {
            mx0 = fmaxf(mx0, __shfl_xor_sync(0xffffffffu, mx0, o));
            mx1 = fmaxf(mx1, __shfl_xor_sync(0xffffffffu, mx1, o));
        }
        float nm0 = fmaxf(rmax0, mx0), nm1 = fmaxf(rmax1, mx1);
        float al0 = __expf(rmax0 - nm0), al1 = __expf(rmax1 - nm1);
        rmax0 = nm0; rmax1 = nm1;
        float ls0 = 0.f, ls1 = 0.f;
#pragma unroll
        for (int nf = 0; nf < 8; nf++) {
            s[nf][0] = __expf(s[nf][0] - nm0);
            s[nf][1] = __expf(s[nf][1] - nm0);
            s[nf][2] = __expf(s[nf][2] - nm1);
            s[nf][3] = __expf(s[nf][3] - nm1);
            ls0 += s[nf][0] + s[nf][1];
            ls1 += s[nf][2] + s[nf][3];
        }
#pragma unroll
        for (int o = 1; o <= 2; o <<= 1) {
            ls0 += __shfl_xor_sync(0xffffffffu, ls0, o);
            ls1 += __shfl_xor_sync(0xffffffffu, ls1, o);
        }
        rsum0 = rsum0 * al0 + ls0;
        rsum1 = rsum1 * al1 + ls1;
#pragma unroll
        for (int nf = 0; nf < 8; nf++) {
            accO[nf][0] *= al0; accO[nf][1] *= al0;
            accO[nf][2] *= al1; accO[nf][3] *= al1;
        }

        // ---- pack P fragments (hi + residual-lo) ----
        uint32_t ph[4][4], pl[4][4];
#pragma unroll
        for (int ks = 0; ks < 4; ks++) {
            int f0 = 2 * ks, f1 = 2 * ks + 1;
            float rlo2[8];
#pragma unroll
            for (int e = 0; e < 4; e++) {
                rlo2[e]     = s[f0][e] - __bfloat162float(__float2bfloat16_rn(s[f0][e]));
                rlo2[4 + e] = s[f1][e] - __bfloat162float(__float2bfloat16_rn(s[f1][e]));
            }
            ph[ks][0] = pack_bf2(s[f0][0], s[f0][1]);
            ph[ks][1] = pack_bf2(s[f0][2], s[f0][3]);
            ph[ks][2] = pack_bf2(s[f1][0], s[f1][1]);
            ph[ks][3] = pack_bf2(s[f1][2], s[f1][3]);
            pl[ks][0] = pack_bf2(rlo2[0], rlo2[1]);
            pl[ks][1] = pack_bf2(rlo2[2], rlo2[3]);
            pl[ks][2] = pack_bf2(rlo2[4], rlo2[5]);
            pl[ks][3] = pack_bf2(rlo2[6], rlo2[7]);
        }

        // ---- O += P * V ----
#pragma unroll
        for (int ks = 0; ks < 4; ks++) {
#pragma unroll
            for (int gp = 0; gp < 4; gp++) {
                uint32_t vh4[4], vl4[4];
                ldmB(sVh, ASTR, gp * 16, ks * 16, lane, vh4);
                ldmB(sVl, ASTR, gp * 16, ks * 16, lane, vl4);
                MMA_BF16(accO[2 * gp], ph[ks], vh4);
                MMA_BF16(accO[2 * gp], ph[ks], vl4);
                MMA_BF16(accO[2 * gp], pl[ks], vh4);
                MMA_BF16(accO[2 * gp + 1], ph[ks], vh4 + 2);
                MMA_BF16(accO[2 * gp + 1], ph[ks], vl4 + 2);
                MMA_BF16(accO[2 * gp + 1], pl[ks], vh4 + 2);
            }
        }
        __syncthreads();
    }

    // ---- epilogue ----
    float inv0 = 1.0f / rsum0, inv1 = 1.0f / rsum1;
#pragma unroll
    for (int nf = 0; nf < 8; nf++)
#pragma unroll
        for (int e = 0; e < 4; e++) {
            int i = i0 + w * 16 + r0 + ((e >> 1) << 3);
            int d = nf * 8 + c0 + (e & 1);
            float v = accO[nf][e] * ((e < 2) ? inv0 : inv1);
            __nv_bfloat16 vh, vl;
            split_bf(v, vh, vl);
            size_t idx = ((size_t)(b * SEQ + i)) * D_MODEL + h * DK + d;
            g_oh[idx] = vh; g_ol[idx] = vl;
        }
}

// ---------------------------------------------------------------------------
extern "C" void kernel_launch(void* const* d_in, const int* in_sizes, int n_in,
                              void* d_out, int out_size)
{
    const float* x  = (const float*)d_in[0];
    const float* Wq = (const float*)d_in[1];
    const float* bq = (const float*)d_in[2];
    const float* Wk = (const float*)d_in[3];
    const float* bk = (const float*)d_in[4];
    const float* Wv = (const float*)d_in[5];
    const float* bv = (const float*)d_in[6];
    const float* Wo = (const float*)d_in[7];
    const float* bo = (const float*)d_in[8];
    const float* Er = (const float*)d_in[9];
    float* out = (float*)d_out;

    cudaFuncSetAttribute(gemm_bf16_kernel,
                         cudaFuncAttributeMaxDynamicSharedMemorySize, GEMM_DYN_SMEM);
    cudaFuncSetAttribute(attn_mma_kernel,
                         cudaFuncAttributeMaxDynamicSharedMemorySize, ATTN_SMEM);

    __nv_bfloat16 *xh, *xl, *wh, *wl, *oh, *ol;
    cudaGetSymbolAddress((void**)&xh, g_xh);
    cudaGetSymbolAddress((void**)&xl, g_xl);
    cudaGetSymbolAddress((void**)&wh, g_wh);
    cudaGetSymbolAddress((void**)&wl, g_wl);
    cudaGetSymbolAddress((void**)&oh, g_oh);
    cudaGetSymbolAddress((void**)&ol, g_ol);

    // 0) split x, weights, Er into bf16 hi/lo
    {
        int total = (MTOT * D_MODEL + 4 * D_MODEL * D_MODEL + ELEN * DK) / 4;
        convert_xw_kernel<<<(total + 255) / 256, 256>>>(x, Wq, Wk, Wv, Wo, Er);
    }
    // 1) fused QKV projection -> split-bf16 Q/K (head-major) + V^T
    {
        dim3 grid(3072 / 128, MTOT / 128);
        gemm_bf16_kernel<<<grid, 256, GEMM_DYN_SMEM>>>(
            xh, xl, wh, wl, bq, bk, bv, nullptr, 0);
    }
    // 2) pipelined MMA attention -> split-bf16 O
    {
        dim3 grid(SEQ / 128, BHT);           // 8 x 32
        attn_mma_kernel<<<grid, 256, ATTN_SMEM>>>();
    }
    // 3) output projection -> out
    {
        dim3 grid(D_MODEL / 128, MTOT / 128);
        gemm_bf16_kernel<<<grid, 256, GEMM_DYN_SMEM>>>(
            oh, ol, wh + (size_t)3 * D_MODEL * D_MODEL, wl + (size_t)3 * D_MODEL * D_MODEL,
            bo, bo, bo, out, 1);
    }
}

// round 12
// speedup vs baseline: 1.1134x; 1.0228x over previous
#include <cuda_runtime.h>
#include <cuda_bf16.h>
#include <math.h>
#include <stdint.h>

#define D_MODEL 1024
#define NH      16
#define DK      64
#define BATCH   2
#define SEQ     1024
#define BHT     (BATCH*NH)          // 32
#define MTOT    (BATCH*SEQ)         // 2048
#define ELEN    (2*SEQ-1)           // 2047

// ---------------- scratch (device globals; no allocation allowed) ----------
__device__ __nv_bfloat16 g_xh[MTOT*D_MODEL];
__device__ __nv_bfloat16 g_xl[MTOT*D_MODEL];
__device__ __nv_bfloat16 g_wh[4*D_MODEL*D_MODEL];  // Wq|Wk|Wv|Wo stacked rows
__device__ __nv_bfloat16 g_wl[4*D_MODEL*D_MODEL];
__device__ __nv_bfloat16 g_oh[MTOT*D_MODEL];
__device__ __nv_bfloat16 g_ol[MTOT*D_MODEL];

__device__ __nv_bfloat16 g_Qh[BHT*SEQ*DK];   // [bh][s][d], pre-scaled 1/8
__device__ __nv_bfloat16 g_Ql[BHT*SEQ*DK];
__device__ __nv_bfloat16 g_Kh[BHT*SEQ*DK];
__device__ __nv_bfloat16 g_Kl[BHT*SEQ*DK];
__device__ __nv_bfloat16 g_Vth[BHT*DK*SEQ];  // [bh][d][s]  (transposed)
__device__ __nv_bfloat16 g_Vtl[BHT*DK*SEQ];
__device__ __nv_bfloat16 g_Eh[ELEN*DK];
__device__ __nv_bfloat16 g_El[ELEN*DK];

// ---------------- helpers ---------------------------------------------------
__device__ __forceinline__ uint32_t smem_u32(const void* p) {
    uint32_t a;
    asm("{ .reg .u64 t; cvta.to.shared.u64 t, %1; cvt.u32.u64 %0, t; }"
        : "=r"(a) : "l"(p));
    return a;
}

#define CPA16(dst_u32, src_ptr) \
    asm volatile("cp.async.ca.shared.global [%0], [%1], 16;" \
                 :: "r"(dst_u32), "l"(src_ptr) : "memory")
#define CP_COMMIT() asm volatile("cp.async.commit_group;" ::: "memory")
#define CP_WAIT0()  asm volatile("cp.async.wait_group 0;" ::: "memory")
#define CP_WAIT1()  asm volatile("cp.async.wait_group 1;" ::: "memory")

// NOTE: not volatile — lets ptxas hoist/interleave fragment loads across MMA
// groups (register data-deps preserve correctness; __syncthreads / cp.async
// waits are compiler memory barriers that bound the motion).
#define LDMATRIX_X4(r0, r1, r2, r3, addr) \
    asm("ldmatrix.sync.aligned.m8n8.x4.shared.b16 {%0,%1,%2,%3}, [%4];" \
        : "=r"(r0), "=r"(r1), "=r"(r2), "=r"(r3) : "r"(addr))

#define MMA_BF16(c, a, b) \
    asm("mma.sync.aligned.m16n8k16.row.col.f32.bf16.bf16.f32 " \
        "{%0,%1,%2,%3}, {%4,%5,%6,%7}, {%8,%9}, {%0,%1,%2,%3};" \
        : "+f"((c)[0]), "+f"((c)[1]), "+f"((c)[2]), "+f"((c)[3]) \
        : "r"((a)[0]), "r"((a)[1]), "r"((a)[2]), "r"((a)[3]), \
          "r"((b)[0]), "r"((b)[1]))

// Load B-fragments for TWO n-frags with one ldmatrix.x4.
__device__ __forceinline__ void ldmB(const __nv_bfloat16* base, int stride,
                                     int row0, int kcol, int lane, uint32_t* r)
{
    int sel = (lane >> 4) & 1;
    int row = row0 + sel * 8 + (lane & 7);
    int col = kcol + ((lane >> 3) & 1) * 8;
    uint32_t a = smem_u32(base + row * stride + col);
    LDMATRIX_X4(r[0], r[1], r[2], r[3], a);
}

__device__ __forceinline__ uint32_t pack_bf2(float lo, float hi) {
    __nv_bfloat162 t = __floats2bfloat162_rn(lo, hi);
    return *(uint32_t*)&t;
}
__device__ __forceinline__ void split_bf(float v, __nv_bfloat16& h, __nv_bfloat16& l) {
    h = __float2bfloat16_rn(v);
    l = __float2bfloat16_rn(v - __bfloat162float(h));
}
// split two values, return packed hi-pair and lo-pair (for vectorized stores)
__device__ __forceinline__ void split_bf2(float v0, float v1,
                                          uint32_t& hp, uint32_t& lp) {
    __nv_bfloat16 h0, l0, h1, l1;
    split_bf(v0, h0, l0);
    split_bf(v1, h1, l1);
    __nv_bfloat162 hh; hh.x = h0; hh.y = h1;
    __nv_bfloat162 ll; ll.x = l0; ll.y = l1;
    hp = *(uint32_t*)&hh;
    lp = *(uint32_t*)&ll;
}

// ---------------------------------------------------------------------------
// fp32 -> bf16 hi/lo split conversion (x, 4 weights, Er)
// ---------------------------------------------------------------------------
__global__ void convert_xw_kernel(const float* __restrict__ x,
                                  const float* __restrict__ Wq, const float* __restrict__ Wk,
                                  const float* __restrict__ Wv, const float* __restrict__ Wo,
                                  const float* __restrict__ Er)
{
    const int NX = MTOT * D_MODEL / 4;
    const int NW = D_MODEL * D_MODEL / 4;
    const int NE = ELEN * DK / 4;
    int g = blockIdx.x * blockDim.x + threadIdx.x;
    if (g >= NX + 4 * NW + NE) return;
    const float* src;
    __nv_bfloat16 *dh, *dl;
    if (g < NX) { src = x + g * 4; dh = g_xh + g * 4; dl = g_xl + g * 4; }
    else if (g < NX + 4 * NW) {
        int wi = g - NX;
        int which = wi / NW;
        int off = wi - which * NW;
        const float* W = (which == 0) ? Wq : (which == 1) ? Wk : (which == 2) ? Wv : Wo;
        src = W + off * 4;
        dh = g_wh + (size_t)which * NW * 4 + off * 4;
        dl = g_wl + (size_t)which * NW * 4 + off * 4;
    } else {
        int ei = g - NX - 4 * NW;
        src = Er + ei * 4; dh = g_Eh + ei * 4; dl = g_El + ei * 4;
    }
    float4 v = *(const float4*)src;
    __nv_bfloat16 hv[4], lv[4];
    split_bf(v.x, hv[0], lv[0]); split_bf(v.y, hv[1], lv[1]);
    split_bf(v.z, hv[2], lv[2]); split_bf(v.w, hv[3], lv[3]);
    *(uint2*)dh = *(uint2*)hv;
    *(uint2*)dl = *(uint2*)lv;
}

// ---------------------------------------------------------------------------
// Split-bf16 mma.sync GEMM: 3-stage cp.async.ca pipeline, BK=32.
// ---------------------------------------------------------------------------
#define HSTR 40
#define MAT_HALVES (128*HSTR)
#define BUF_HALVES (4*MAT_HALVES)
#define GSTAGES 3
#define GEMM_DYN_SMEM (GSTAGES*BUF_HALVES*2)   // 122880 B

__global__ __launch_bounds__(256, 1)
void gemm_bf16_kernel(const __nv_bfloat16* __restrict__ Ah, const __nv_bfloat16* __restrict__ Al,
                      const __nv_bfloat16* __restrict__ Bh, const __nv_bfloat16* __restrict__ Bl,
                      const float* __restrict__ bias0, const float* __restrict__ bias1,
                      const float* __restrict__ bias2,
                      float* __restrict__ Cout, int mode)
{
    extern __shared__ __nv_bfloat16 sm[];

    const int tid  = threadIdx.x;
    const int wid  = tid >> 5;
    const int lane = tid & 31;
    const int warp_m = wid >> 2;
    const int warp_n = wid & 3;
    const int m0 = blockIdx.y * 128;
    const int n0 = blockIdx.x * 128;
    const int which = n0 >> 10;
    const int n0m = n0 & 1023;
    const float* biasm = (which == 0) ? bias0 : (which == 1) ? bias1 : bias2;

    float acc[4][4][4];
#pragma unroll
    for (int f = 0; f < 4; f++)
#pragma unroll
        for (int g = 0; g < 4; g++)
#pragma unroll
            for (int e = 0; e < 4; e++) acc[f][g][e] = 0.f;

    const int lrow = tid >> 2;          // 0..63
    const int lk   = (tid & 3) * 8;     // 0,8,16,24
    const uint32_t smb = smem_u32(sm);

    auto issue = [&](int c) {
        uint32_t bb = smb + (c % GSTAGES) * BUF_HALVES * 2;
        int kg = c * 32 + lk;
#pragma unroll
        for (int i = 0; i < 2; i++) {
            int row = lrow + i * 64;
            uint32_t doff = (row * HSTR + lk) * 2;
            CPA16(bb + 0 * MAT_HALVES * 2 + doff, Ah + (size_t)(m0 + row) * 1024 + kg);
            CPA16(bb + 1 * MAT_HALVES * 2 + doff, Al + (size_t)(m0 + row) * 1024 + kg);
            CPA16(bb + 2 * MAT_HALVES * 2 + doff, Bh + (size_t)(n0 + row) * 1024 + kg);
            CPA16(bb + 3 * MAT_HALVES * 2 + doff, Bl + (size_t)(n0 + row) * 1024 + kg);
        }
        CP_COMMIT();
    };

    issue(0);
    issue(1);

    const int a_r   = lane & 15;
    const int a_kof = (lane >> 4) * 8;

    for (int c = 0; c < 32; c++) {
        if (c < 31) CP_WAIT1(); else CP_WAIT0();
        __syncthreads();
        if (c + 2 < 32) issue(c + 2);

        __nv_bfloat16* cb = sm + (c % GSTAGES) * BUF_HALVES;
#pragma unroll
        for (int ks = 0; ks < 2; ks++) {
            uint32_t aH[4][4], aL[4][4], bH[2][4], bL[2][4];
#pragma unroll
            for (int f = 0; f < 4; f++) {
                int row = warp_m * 64 + f * 16 + a_r;
                uint32_t addrH = smem_u32(&cb[0 * MAT_HALVES + row * HSTR + ks * 16 + a_kof]);
                LDMATRIX_X4(aH[f][0], aH[f][1], aH[f][2], aH[f][3], addrH);
                uint32_t addrL = smem_u32(&cb[1 * MAT_HALVES + row * HSTR + ks * 16 + a_kof]);
                LDMATRIX_X4(aL[f][0], aL[f][1], aL[f][2], aL[f][3], addrL);
            }
            ldmB(&cb[2 * MAT_HALVES], HSTR, warp_n * 32 +  0, ks * 16, lane, bH[0]);
            ldmB(&cb[2 * MAT_HALVES], HSTR, warp_n * 32 + 16, ks * 16, lane, bH[1]);
            ldmB(&cb[3 * MAT_HALVES], HSTR, warp_n * 32 +  0, ks * 16, lane, bL[0]);
            ldmB(&cb[3 * MAT_HALVES], HSTR, warp_n * 32 + 16, ks * 16, lane, bL[1]);
#pragma unroll
            for (int f = 0; f < 4; f++)
#pragma unroll
                for (int g = 0; g < 4; g++) {
                    const uint32_t* ph = &bH[g >> 1][(g & 1) * 2];
                    const uint32_t* pls = &bL[g >> 1][(g & 1) * 2];
                    MMA_BF16(acc[f][g], aH[f], ph);
                    MMA_BF16(acc[f][g], aH[f], pls);
                    MMA_BF16(acc[f][g], aL[f], ph);
                }
        }
        __syncthreads();
    }

    if (mode == 0) {
        const float scale = (which == 0) ? 0.125f : 1.0f;
#pragma unroll
        for (int f = 0; f < 4; f++) {
            int mrow0 = m0 + warp_m * 64 + f * 16 + (lane >> 2);
#pragma unroll
            for (int g = 0; g < 4; g++) {
                int ncol = n0m + warp_n * 32 + g * 8 + (lane & 3) * 2;  // even
#pragma unroll
                for (int ep = 0; ep < 2; ep++) {                 // e pairs (0,1),(2,3)
                    int m = mrow0 + ep * 8;
                    int b = m >> 10, s = m & 1023;
                    float v0 = (acc[f][g][2 * ep + 0] + biasm[ncol]) * scale;
                    float v1 = (acc[f][g][2 * ep + 1] + biasm[ncol + 1]) * scale;
                    if (which == 2) {
                        // V transposed: not contiguous — scalar stores
                        int h = ncol >> 6;
#pragma unroll
                        for (int e = 0; e < 2; e++) {
                            int d = (ncol + e) & 63;
                            float val = e ? v1 : v0;
                            __nv_bfloat16 vh, vl;
                            split_bf(val, vh, vl);
                            size_t idx = ((size_t)(b * NH + h) * DK + d) * SEQ + s;
                            g_Vth[idx] = vh; g_Vtl[idx] = vl;
                        }
                    } else {
                        int h = ncol >> 6, d = ncol & 63;        // d even
                        uint32_t hp, lp;
                        split_bf2(v0, v1, hp, lp);
                        size_t idx = ((size_t)(b * NH + h) * SEQ + s) * DK + d;
                        if (which == 0) {
                            *(uint32_t*)&g_Qh[idx] = hp;
                            *(uint32_t*)&g_Ql[idx] = lp;
                        } else {
                            *(uint32_t*)&g_Kh[idx] = hp;
                            *(uint32_t*)&g_Kl[idx] = lp;
                        }
                    }
                }
            }
        }
    } else {
#pragma unroll
        for (int f = 0; f < 4; f++) {
            int mrow0 = m0 + warp_m * 64 + f * 16 + (lane >> 2);
#pragma unroll
            for (int g = 0; g < 4; g++) {
                int ncol = n0 + warp_n * 32 + g * 8 + (lane & 3) * 2;
#pragma unroll
                for (int ep = 0; ep < 2; ep++) {
                    int m = mrow0 + ep * 8;
                    float2 v = make_float2(acc[f][g][2 * ep] + biasm[ncol],
                                           acc[f][g][2 * ep + 1] + biasm[ncol + 1]);
                    *(float2*)&Cout[(size_t)m * D_MODEL + ncol] = v;
                }
            }
        }
    }
}

// ---------------------------------------------------------------------------
// Pipelined MMA flash-attention with rolling circular E buffer.
// ---------------------------------------------------------------------------
#define ASTR  72
#define GBSTR 84
#define KV_STAGE_HALVES (4*64*ASTR)
#define ST_KH 0
#define ST_KL (64*ASTR)
#define ST_VH (2*64*ASTR)
#define ST_VL (3*64*ASTR)
#define E_OFF_HALVES (2*KV_STAGE_HALVES)
#define EH_OFF E_OFF_HALVES
#define EL_OFF (E_OFF_HALVES + 256*ASTR)
#define G_OFF_HALVES (E_OFF_HALVES + 2*256*ASTR)
#define ATTN_SMEM (G_OFF_HALVES*2 + 8*16*GBSTR*4)  // 190464 B

__device__ __forceinline__ void attn_issue_tile(
    uint32_t smb, int jt, int tid, int i0,
    const __nv_bfloat16* Khg, const __nv_bfloat16* Klg,
    const __nv_bfloat16* Vhg, const __nv_bfloat16* Vlg)
{
    const int j0 = jt * 64;
    const uint32_t kvbase = smb + (jt & 1) * KV_STAGE_HALVES * 2;
    for (int t = tid; t < 512; t += 256) {
        int r = t >> 3, c8 = (t & 7) * 8;
        uint32_t doff = (r * ASTR + c8) * 2;
        CPA16(kvbase + ST_KH * 2 + doff, Khg + (size_t)(j0 + r) * DK + c8);
        CPA16(kvbase + ST_KL * 2 + doff, Klg + (size_t)(j0 + r) * DK + c8);
        CPA16(kvbase + ST_VH * 2 + doff, Vhg + (size_t)r * SEQ + j0 + c8);
        CPA16(kvbase + ST_VL * 2 + doff, Vlg + (size_t)r * SEQ + j0 + c8);
    }
    const int rlo = (SEQ - 1) + i0 - j0 - 63;
    const int cnt8 = (jt == 0) ? 1536 : 512;
    for (int t = tid; t < cnt8; t += 256) {
        int r = t >> 3, c8 = (t & 7) * 8;
        int er = rlo + r;
        int ers = (er > ELEN - 1) ? (ELEN - 1) : er;
        uint32_t phys = (uint32_t)er & 255u;
        uint32_t doff = (phys * ASTR + c8) * 2;
        CPA16(smb + EH_OFF * 2 + doff, g_Eh + (size_t)ers * DK + c8);
        CPA16(smb + EL_OFF * 2 + doff, g_El + (size_t)ers * DK + c8);
    }
    CP_COMMIT();
}

__global__ __launch_bounds__(256)
void attn_mma_kernel()
{
    extern __shared__ __nv_bfloat16 smh[];
    float* sG = (float*)(smh + G_OFF_HALVES);
    __nv_bfloat16* sQh = (__nv_bfloat16*)sG;
    __nv_bfloat16* sQl = sQh + 128 * ASTR;
    __nv_bfloat16* sEh = smh + EH_OFF;
    __nv_bfloat16* sEl = smh + EL_OFF;

    const int tid  = threadIdx.x;
    const int lane = tid & 31;
    const int w    = tid >> 5;
    const int bh = blockIdx.y;
    const int i0 = blockIdx.x * 128;
    const int b = bh >> 4, h = bh & 15;

    const __nv_bfloat16* Qhg = g_Qh + (size_t)bh * SEQ * DK;
    const __nv_bfloat16* Qlg = g_Ql + (size_t)bh * SEQ * DK;
    const __nv_bfloat16* Khg = g_Kh + (size_t)bh * SEQ * DK;
    const __nv_bfloat16* Klg = g_Kl + (size_t)bh * SEQ * DK;
    const __nv_bfloat16* Vhg = g_Vth + (size_t)bh * DK * SEQ;
    const __nv_bfloat16* Vlg = g_Vtl + (size_t)bh * DK * SEQ;
    const uint32_t smb = smem_u32(smh);

    for (int t = tid; t < 1024; t += 256) {
        int r = t >> 3, c8 = (t & 7) * 8;
        *(uint4*)&sQh[r * ASTR + c8] = *(const uint4*)(Qhg + (size_t)(i0 + r) * DK + c8);
        *(uint4*)&sQl[r * ASTR + c8] = *(const uint4*)(Qlg + (size_t)(i0 + r) * DK + c8);
    }
    __syncthreads();
    uint32_t qh[4][4], ql[4][4];
#pragma unroll
    for (int ks = 0; ks < 4; ks++) {
        uint32_t aH = smem_u32(&sQh[(w * 16 + (lane & 15)) * ASTR + ks * 16 + (lane >> 4) * 8]);
        LDMATRIX_X4(qh[ks][0], qh[ks][1], qh[ks][2], qh[ks][3], aH);
        uint32_t aL = smem_u32(&sQl[(w * 16 + (lane & 15)) * ASTR + ks * 16 + (lane >> 4) * 8]);
        LDMATRIX_X4(ql[ks][0], ql[ks][1], ql[ks][2], ql[ks][3], aL);
    }
    __syncthreads();

    attn_issue_tile(smb, 0, tid, i0, Khg, Klg, Vhg, Vlg);

    float accO[8][4];
#pragma unroll
    for (int nf = 0; nf < 8; nf++)
#pragma unroll
        for (int e = 0; e < 4; e++) accO[nf][e] = 0.f;
    float rmax0 = -1e30f, rmax1 = -1e30f, rsum0 = 0.f, rsum1 = 0.f;

    const int r0 = lane >> 2;
    const int c0 = (lane & 3) * 2;
    float* sGw = sG + w * 16 * GBSTR;

    for (int jt = 0; jt < 16; jt++) {
        if (jt < 15) {
            attn_issue_tile(smb, jt + 1, tid, i0, Khg, Klg, Vhg, Vlg);
            CP_WAIT1();
        } else {
            CP_WAIT0();
        }
        __syncthreads();

        __nv_bfloat16* st = smh + (jt & 1) * KV_STAGE_HALVES;
        __nv_bfloat16* sKh = st + ST_KH;
        __nv_bfloat16* sKl = st + ST_KL;
        __nv_bfloat16* sVh = st + ST_VH;
        __nv_bfloat16* sVl = st + ST_VL;

        const int rbase = (SEQ - 1) + i0 - jt * 64 - 63;
        const int rb255 = rbase & 255;

        // ---- G = Q * Eband^T, band-limited: nf in [2w, 2w+10) ----
        float gac[10][4];
#pragma unroll
        for (int bi = 0; bi < 10; bi++)
#pragma unroll
            for (int e = 0; e < 4; e++) gac[bi][e] = 0.f;
#pragma unroll
        for (int ks = 0; ks < 4; ks++) {
#pragma unroll
            for (int bp = 0; bp < 5; bp++) {
                uint32_t eh4[4], el4[4];
                int row0 = (rb255 + (2 * w + 2 * bp) * 8) & 255;
                ldmB(sEh, ASTR, row0, ks * 16, lane, eh4);
                ldmB(sEl, ASTR, row0, ks * 16, lane, el4);
                MMA_BF16(gac[2 * bp], qh[ks], eh4);
                MMA_BF16(gac[2 * bp], qh[ks], el4);
                MMA_BF16(gac[2 * bp], ql[ks], eh4);
                MMA_BF16(gac[2 * bp + 1], qh[ks], eh4 + 2);
                MMA_BF16(gac[2 * bp + 1], qh[ks], el4 + 2);
                MMA_BF16(gac[2 * bp + 1], ql[ks], eh4 + 2);
            }
        }
#pragma unroll
        for (int bi = 0; bi < 10; bi++) {
            *(float2*)&sGw[r0 * GBSTR + bi * 8 + c0] = make_float2(gac[bi][0], gac[bi][1]);
            *(float2*)&sGw[(r0 + 8) * GBSTR + bi * 8 + c0] = make_float2(gac[bi][2], gac[bi][3]);
        }

        // ---- S = Q * K^T ----
        float s[8][4];
#pragma unroll
        for (int nf = 0; nf < 8; nf++)
#pragma unroll
            for (int e = 0; e < 4; e++) s[nf][e] = 0.f;
#pragma unroll
        for (int ks = 0; ks < 4; ks++) {
#pragma unroll
            for (int gp = 0; gp < 4; gp++) {
                uint32_t kh4[4], kl4[4];
                ldmB(sKh, ASTR, gp * 16, ks * 16, lane, kh4);
                ldmB(sKl, ASTR, gp * 16, ks * 16, lane, kl4);
                MMA_BF16(s[2 * gp], qh[ks], kh4);
                MMA_BF16(s[2 * gp], qh[ks], kl4);
                MMA_BF16(s[2 * gp], ql[ks], kh4);
                MMA_BF16(s[2 * gp + 1], qh[ks], kh4 + 2);
                MMA_BF16(s[2 * gp + 1], qh[ks], kl4 + 2);
                MMA_BF16(s[2 * gp + 1], ql[ks], kh4 + 2);
            }
        }
        __syncwarp();

        // ---- gather BD from G band and add ----
#pragma unroll
        for (int nf = 0; nf < 8; nf++)
#pragma unroll
            for (int e = 0; e < 4; e++) {
                int iw = r0 + ((e >> 1) << 3);
                int jl = nf * 8 + c0 + (e & 1);
                s[nf][e] += sGw[iw * GBSTR + (iw - jl + 63)];
            }

        // ---- online softmax ----
        float mx0 = -1e30f, mx1 = -1e30f;
#pragma unroll
        for (int nf = 0; nf < 8; nf++) {
            mx0 = fmaxf(mx0, fmaxf(s[nf][0], s[nf][1]));
            mx1 = fmaxf(mx1, fmaxf(s[nf][2], s[nf][3]));
        }
#pragma unroll
        for (int o = 1; o <= 2; o <<= 1) {
            mx0 = fmaxf(mx0, __shfl_xor_sync(0xffffffffu, mx0, o));
            mx1 = fmaxf(mx1, __shfl_xor_sync(0xffffffffu, mx1, o));
        }
        float nm0 = fmaxf(rmax0, mx0), nm1 = fmaxf(rmax1, mx1);
        float al0 = __expf(rmax0 - nm0), al1 = __expf(rmax1 - nm1);
        rmax0 = nm0; rmax1 = nm1;
        float ls0 = 0.f, ls1 = 0.f;
#pragma unroll
        for (int nf = 0; nf < 8; nf++) {
            s[nf][0] = __expf(s[nf][0] - nm0);
            s[nf][1] = __expf(s[nf][1] - nm0);
            s[nf][2] = __expf(s[nf][2] - nm1);
            s[nf][3] = __expf(s[nf][3] - nm1);
            ls0 += s[nf][0] + s[nf][1];
            ls1 += s[nf][2] + s[nf][3];
        }
#pragma unroll
        for (int o = 1; o <= 2; o <<= 1) {
            ls0 += __shfl_xor_sync(0xffffffffu, ls0, o);
            ls1 += __shfl_xor_sync(0xffffffffu, ls1, o);
        }
        rsum0 = rsum0 * al0 + ls0;
        rsum1 = rsum1 * al1 + ls1;
#pragma unroll
        for (int nf = 0; nf < 8; nf++) {
            accO[nf][0] *= al0; accO[nf][1] *= al0;
            accO[nf][2] *= al1; accO[nf][3] *= al1;
        }

        // ---- pack P fragments (hi + residual-lo) ----
        uint32_t ph[4][4], pl[4][4];
#pragma unroll
        for (int ks = 0; ks < 4; ks++) {
            int f0 = 2 * ks, f1 = 2 * ks + 1;
            float rlo2[8];
#pragma unroll
            for (int e = 0; e < 4; e++) {
                rlo2[e]     = s[f0][e] - __bfloat162float(__float2bfloat16_rn(s[f0][e]));
                rlo2[4 + e] = s[f1][e] - __bfloat162float(__float2bfloat16_rn(s[f1][e]));
            }
            ph[ks][0] = pack_bf2(s[f0][0], s[f0][1]);
            ph[ks][1] = pack_bf2(s[f0][2], s[f0][3]);
            ph[ks][2] = pack_bf2(s[f1][0], s[f1][1]);
            ph[ks][3] = pack_bf2(s[f1][2], s[f1][3]);
            pl[ks][0] = pack_bf2(rlo2[0], rlo2[1]);
            pl[ks][1] = pack_bf2(rlo2[2], rlo2[3]);
            pl[ks][2] = pack_bf2(rlo2[4], rlo2[5]);
            pl[ks][3] = pack_bf2(rlo2[6], rlo2[7]);
        }

        // ---- O += P * V ----
#pragma unroll
        for (int ks = 0; ks < 4; ks++) {
#pragma unroll
            for (int gp = 0; gp < 4; gp++) {
                uint32_t vh4[4], vl4[4];
                ldmB(sVh, ASTR, gp * 16, ks * 16, lane, vh4);
                ldmB(sVl, ASTR, gp * 16, ks * 16, lane, vl4);
                MMA_BF16(accO[2 * gp], ph[ks], vh4);
                MMA_BF16(accO[2 * gp], ph[ks], vl4);
                MMA_BF16(accO[2 * gp], pl[ks], vh4);
                MMA_BF16(accO[2 * gp + 1], ph[ks], vh4 + 2);
                MMA_BF16(accO[2 * gp + 1], ph[ks], vl4 + 2);
                MMA_BF16(accO[2 * gp + 1], pl[ks], vh4 + 2);
            }
        }
        __syncthreads();
    }

    // ---- epilogue: vectorized pair stores (d, d+1 contiguous) ----
    float inv0 = 1.0f / rsum0, inv1 = 1.0f / rsum1;
#pragma unroll
    for (int nf = 0; nf < 8; nf++)
#pragma unroll
        for (int ep = 0; ep < 2; ep++) {
            int i = i0 + w * 16 + r0 + ep * 8;
            int d = nf * 8 + c0;                    // even
            float inv = ep ? inv1 : inv0;
            float v0 = accO[nf][2 * ep + 0] * inv;
            float v1 = accO[nf][2 * ep + 1] * inv;
            uint32_t hp, lp;
            split_bf2(v0, v1, hp, lp);
            size_t idx = ((size_t)(b * SEQ + i)) * D_MODEL + h * DK + d;
            *(uint32_t*)&g_oh[idx] = hp;
            *(uint32_t*)&g_ol[idx] = lp;
        }
}

// ---------------------------------------------------------------------------
extern "C" void kernel_launch(void* const* d_in, const int* in_sizes, int n_in,
                              void* d_out, int out_size)
{
    const float* x  = (const float*)d_in[0];
    const float* Wq = (const float*)d_in[1];
    const float* bq = (const float*)d_in[2];
    const float* Wk = (const float*)d_in[3];
    const float* bk = (const float*)d_in[4];
    const float* Wv = (const float*)d_in[5];
    const float* bv = (const float*)d_in[6];
    const float* Wo = (const float*)d_in[7];
    const float* bo = (const float*)d_in[8];
    const float* Er = (const float*)d_in[9];
    float* out = (float*)d_out;

    cudaFuncSetAttribute(gemm_bf16_kernel,
                         cudaFuncAttributeMaxDynamicSharedMemorySize, GEMM_DYN_SMEM);
    cudaFuncSetAttribute(attn_mma_kernel,
                         cudaFuncAttributeMaxDynamicSharedMemorySize, ATTN_SMEM);

    __nv_bfloat16 *xh, *xl, *wh, *wl, *oh, *ol;
    cudaGetSymbolAddress((void**)&xh, g_xh);
    cudaGetSymbolAddress((void**)&xl, g_xl);
    cudaGetSymbolAddress((void**)&wh, g_wh);
    cudaGetSymbolAddress((void**)&wl, g_wl);
    cudaGetSymbolAddress((void**)&oh, g_oh);
    cudaGetSymbolAddress((void**)&ol, g_ol);

    // 0) split x, weights, Er into bf16 hi/lo
    {
        int total = (MTOT * D_MODEL + 4 * D_MODEL * D_MODEL + ELEN * DK) / 4;
        convert_xw_kernel<<<(total + 255) / 256, 256>>>(x, Wq, Wk, Wv, Wo, Er);
    }
    // 1) fused QKV projection -> split-bf16 Q/K (head-major) + V^T
    {
        dim3 grid(3072 / 128, MTOT / 128);
        gemm_bf16_kernel<<<grid, 256, GEMM_DYN_SMEM>>>(
            xh, xl, wh, wl, bq, bk, bv, nullptr, 0);
    }
    // 2) pipelined MMA attention -> split-bf16 O
    {
        dim3 grid(SEQ / 128, BHT);           // 8 x 32
        attn_mma_kernel<<<grid, 256, ATTN_SMEM>>>();
    }
    // 3) output projection -> out
    {
        dim3 grid(D_MODEL / 128, MTOT / 128);
        gemm_bf16_kernel<<<grid, 256, GEMM_DYN_SMEM>>>(
            oh, ol, wh + (size_t)3 * D_MODEL * D_MODEL, wl + (size_t)3 * D_MODEL * D_MODEL,
            bo, bo, bo, out, 1);
    }
}

// round 13
// speedup vs baseline: 1.1484x; 1.0314x over previous
#include <cuda_runtime.h>
#include <cuda_bf16.h>
#include <math.h>
#include <stdint.h>

#define D_MODEL 1024
#define NH      16
#define DK      64
#define BATCH   2
#define SEQ     1024
#define BHT     (BATCH*NH)          // 32
#define MTOT    (BATCH*SEQ)         // 2048
#define ELEN    (2*SEQ-1)           // 2047

// ---------------- scratch (device globals; no allocation allowed) ----------
__device__ __nv_bfloat16 g_xh[MTOT*D_MODEL];
__device__ __nv_bfloat16 g_xl[MTOT*D_MODEL];
__device__ __nv_bfloat16 g_wh[4*D_MODEL*D_MODEL];  // Wq|Wk|Wv|Wo stacked rows
__device__ __nv_bfloat16 g_wl[4*D_MODEL*D_MODEL];
__device__ __nv_bfloat16 g_oh[MTOT*D_MODEL];
__device__ __nv_bfloat16 g_ol[MTOT*D_MODEL];

__device__ __nv_bfloat16 g_Qh[BHT*SEQ*DK];   // [bh][s][d], pre-scaled 1/8
__device__ __nv_bfloat16 g_Ql[BHT*SEQ*DK];
__device__ __nv_bfloat16 g_Kh[BHT*SEQ*DK];
__device__ __nv_bfloat16 g_Kl[BHT*SEQ*DK];
__device__ __nv_bfloat16 g_Vth[BHT*DK*SEQ];  // [bh][d][s]  (transposed)
__device__ __nv_bfloat16 g_Vtl[BHT*DK*SEQ];
__device__ __nv_bfloat16 g_Eh[ELEN*DK];
__device__ __nv_bfloat16 g_El[ELEN*DK];

// ---------------- helpers ---------------------------------------------------
__device__ __forceinline__ uint32_t smem_u32(const void* p) {
    uint32_t a;
    asm("{ .reg .u64 t; cvta.to.shared.u64 t, %1; cvt.u32.u64 %0, t; }"
        : "=r"(a) : "l"(p));
    return a;
}

#define CPA16(dst_u32, src_ptr) \
    asm volatile("cp.async.ca.shared.global [%0], [%1], 16;" \
                 :: "r"(dst_u32), "l"(src_ptr) : "memory")
#define CP_COMMIT() asm volatile("cp.async.commit_group;" ::: "memory")
#define CP_WAIT0()  asm volatile("cp.async.wait_group 0;" ::: "memory")
#define CP_WAIT1()  asm volatile("cp.async.wait_group 1;" ::: "memory")

#define LDMATRIX_X4(r0, r1, r2, r3, addr) \
    asm("ldmatrix.sync.aligned.m8n8.x4.shared.b16 {%0,%1,%2,%3}, [%4];" \
        : "=r"(r0), "=r"(r1), "=r"(r2), "=r"(r3) : "r"(addr))

#define MMA_BF16(c, a, b) \
    asm("mma.sync.aligned.m16n8k16.row.col.f32.bf16.bf16.f32 " \
        "{%0,%1,%2,%3}, {%4,%5,%6,%7}, {%8,%9}, {%0,%1,%2,%3};" \
        : "+f"((c)[0]), "+f"((c)[1]), "+f"((c)[2]), "+f"((c)[3]) \
        : "r"((a)[0]), "r"((a)[1]), "r"((a)[2]), "r"((a)[3]), \
          "r"((b)[0]), "r"((b)[1]))

// Load B-fragments for TWO n-frags with one ldmatrix.x4.
__device__ __forceinline__ void ldmB(const __nv_bfloat16* base, int stride,
                                     int row0, int kcol, int lane, uint32_t* r)
{
    int sel = (lane >> 4) & 1;
    int row = row0 + sel * 8 + (lane & 7);
    int col = kcol + ((lane >> 3) & 1) * 8;
    uint32_t a = smem_u32(base + row * stride + col);
    LDMATRIX_X4(r[0], r[1], r[2], r[3], a);
}

__device__ __forceinline__ uint32_t pack_bf2(float lo, float hi) {
    __nv_bfloat162 t = __floats2bfloat162_rn(lo, hi);
    return *(uint32_t*)&t;
}
__device__ __forceinline__ void split_bf(float v, __nv_bfloat16& h, __nv_bfloat16& l) {
    h = __float2bfloat16_rn(v);
    l = __float2bfloat16_rn(v - __bfloat162float(h));
}
__device__ __forceinline__ void split_bf2(float v0, float v1,
                                          uint32_t& hp, uint32_t& lp) {
    __nv_bfloat16 h0, l0, h1, l1;
    split_bf(v0, h0, l0);
    split_bf(v1, h1, l1);
    __nv_bfloat162 hh; hh.x = h0; hh.y = h1;
    __nv_bfloat162 ll; ll.x = l0; ll.y = l1;
    hp = *(uint32_t*)&hh;
    lp = *(uint32_t*)&ll;
}

// ---------------------------------------------------------------------------
// fp32 -> bf16 hi/lo split conversion (x, 4 weights, Er)
// ---------------------------------------------------------------------------
__global__ void convert_xw_kernel(const float* __restrict__ x,
                                  const float* __restrict__ Wq, const float* __restrict__ Wk,
                                  const float* __restrict__ Wv, const float* __restrict__ Wo,
                                  const float* __restrict__ Er)
{
    const int NX = MTOT * D_MODEL / 4;
    const int NW = D_MODEL * D_MODEL / 4;
    const int NE = ELEN * DK / 4;
    int g = blockIdx.x * blockDim.x + threadIdx.x;
    if (g >= NX + 4 * NW + NE) return;
    const float* src;
    __nv_bfloat16 *dh, *dl;
    if (g < NX) { src = x + g * 4; dh = g_xh + g * 4; dl = g_xl + g * 4; }
    else if (g < NX + 4 * NW) {
        int wi = g - NX;
        int which = wi / NW;
        int off = wi - which * NW;
        const float* W = (which == 0) ? Wq : (which == 1) ? Wk : (which == 2) ? Wv : Wo;
        src = W + off * 4;
        dh = g_wh + (size_t)which * NW * 4 + off * 4;
        dl = g_wl + (size_t)which * NW * 4 + off * 4;
    } else {
        int ei = g - NX - 4 * NW;
        src = Er + ei * 4; dh = g_Eh + ei * 4; dl = g_El + ei * 4;
    }
    float4 v = *(const float4*)src;
    __nv_bfloat16 hv[4], lv[4];
    split_bf(v.x, hv[0], lv[0]); split_bf(v.y, hv[1], lv[1]);
    split_bf(v.z, hv[2], lv[2]); split_bf(v.w, hv[3], lv[3]);
    *(uint2*)dh = *(uint2*)hv;
    *(uint2*)dl = *(uint2*)lv;
}

// ---------------------------------------------------------------------------
// Split-bf16 mma.sync GEMM: 512 threads / 16 warps, 128x128 tile, warp tile
// 32x32, 3-stage cp.async.ca pipeline, BK=32.  4 warps/SMSP feed the HMMA pipe.
// ---------------------------------------------------------------------------
#define HSTR 40
#define MAT_HALVES (128*HSTR)
#define BUF_HALVES (4*MAT_HALVES)
#define GSTAGES 3
#define GEMM_DYN_SMEM (GSTAGES*BUF_HALVES*2)   // 122880 B

__global__ __launch_bounds__(512, 1)
void gemm_bf16_kernel(const __nv_bfloat16* __restrict__ Ah, const __nv_bfloat16* __restrict__ Al,
                      const __nv_bfloat16* __restrict__ Bh, const __nv_bfloat16* __restrict__ Bl,
                      const float* __restrict__ bias0, const float* __restrict__ bias1,
                      const float* __restrict__ bias2,
                      float* __restrict__ Cout, int mode)
{
    extern __shared__ __nv_bfloat16 sm[];

    const int tid  = threadIdx.x;
    const int wid  = tid >> 5;          // 0..15
    const int lane = tid & 31;
    const int warp_m = wid >> 2;        // 0..3
    const int warp_n = wid & 3;         // 0..3
    const int m0 = blockIdx.y * 128;
    const int n0 = blockIdx.x * 128;
    const int which = n0 >> 10;
    const int n0m = n0 & 1023;
    const float* biasm = (which == 0) ? bias0 : (which == 1) ? bias1 : bias2;

    float acc[2][4][4];
#pragma unroll
    for (int f = 0; f < 2; f++)
#pragma unroll
        for (int g = 0; g < 4; g++)
#pragma unroll
            for (int e = 0; e < 4; e++) acc[f][g][e] = 0.f;

    const int lrow = tid >> 2;          // 0..127
    const int lk   = (tid & 3) * 8;     // 0,8,16,24
    const uint32_t smb = smem_u32(sm);

    auto issue = [&](int c) {
        uint32_t bb = smb + (c % GSTAGES) * BUF_HALVES * 2;
        int kg = c * 32 + lk;
        uint32_t doff = (lrow * HSTR + lk) * 2;
        CPA16(bb + 0 * MAT_HALVES * 2 + doff, Ah + (size_t)(m0 + lrow) * 1024 + kg);
        CPA16(bb + 1 * MAT_HALVES * 2 + doff, Al + (size_t)(m0 + lrow) * 1024 + kg);
        CPA16(bb + 2 * MAT_HALVES * 2 + doff, Bh + (size_t)(n0 + lrow) * 1024 + kg);
        CPA16(bb + 3 * MAT_HALVES * 2 + doff, Bl + (size_t)(n0 + lrow) * 1024 + kg);
        CP_COMMIT();
    };

    issue(0);
    issue(1);

    const int a_r   = lane & 15;
    const int a_kof = (lane >> 4) * 8;

    for (int c = 0; c < 32; c++) {
        if (c < 31) CP_WAIT1(); else CP_WAIT0();
        __syncthreads();
        if (c + 2 < 32) issue(c + 2);

        __nv_bfloat16* cb = sm + (c % GSTAGES) * BUF_HALVES;
#pragma unroll
        for (int ks = 0; ks < 2; ks++) {
            uint32_t aH[2][4], aL[2][4], bH[2][4], bL[2][4];
#pragma unroll
            for (int f = 0; f < 2; f++) {
                int row = warp_m * 32 + f * 16 + a_r;
                uint32_t addrH = smem_u32(&cb[0 * MAT_HALVES + row * HSTR + ks * 16 + a_kof]);
                LDMATRIX_X4(aH[f][0], aH[f][1], aH[f][2], aH[f][3], addrH);
                uint32_t addrL = smem_u32(&cb[1 * MAT_HALVES + row * HSTR + ks * 16 + a_kof]);
                LDMATRIX_X4(aL[f][0], aL[f][1], aL[f][2], aL[f][3], addrL);
            }
            ldmB(&cb[2 * MAT_HALVES], HSTR, warp_n * 32 +  0, ks * 16, lane, bH[0]);
            ldmB(&cb[2 * MAT_HALVES], HSTR, warp_n * 32 + 16, ks * 16, lane, bH[1]);
            ldmB(&cb[3 * MAT_HALVES], HSTR, warp_n * 32 +  0, ks * 16, lane, bL[0]);
            ldmB(&cb[3 * MAT_HALVES], HSTR, warp_n * 32 + 16, ks * 16, lane, bL[1]);
#pragma unroll
            for (int f = 0; f < 2; f++)
#pragma unroll
                for (int g = 0; g < 4; g++) {
                    const uint32_t* ph = &bH[g >> 1][(g & 1) * 2];
                    const uint32_t* pls = &bL[g >> 1][(g & 1) * 2];
                    MMA_BF16(acc[f][g], aH[f], ph);
                    MMA_BF16(acc[f][g], aH[f], pls);
                    MMA_BF16(acc[f][g], aL[f], ph);
                }
        }
        __syncthreads();
    }

    if (mode == 0) {
        const float scale = (which == 0) ? 0.125f : 1.0f;
#pragma unroll
        for (int f = 0; f < 2; f++) {
            int mrow0 = m0 + warp_m * 32 + f * 16 + (lane >> 2);
#pragma unroll
            for (int g = 0; g < 4; g++) {
                int ncol = n0m + warp_n * 32 + g * 8 + (lane & 3) * 2;  // even
#pragma unroll
                for (int ep = 0; ep < 2; ep++) {
                    int m = mrow0 + ep * 8;
                    int b = m >> 10, s = m & 1023;
                    float v0 = (acc[f][g][2 * ep + 0] + biasm[ncol]) * scale;
                    float v1 = (acc[f][g][2 * ep + 1] + biasm[ncol + 1]) * scale;
                    if (which == 2) {
                        int h = ncol >> 6;
#pragma unroll
                        for (int e = 0; e < 2; e++) {
                            int d = (ncol + e) & 63;
                            float val = e ? v1 : v0;
                            __nv_bfloat16 vh, vl;
                            split_bf(val, vh, vl);
                            size_t idx = ((size_t)(b * NH + h) * DK + d) * SEQ + s;
                            g_Vth[idx] = vh; g_Vtl[idx] = vl;
                        }
                    } else {
                        int h = ncol >> 6, d = ncol & 63;
                        uint32_t hp, lp;
                        split_bf2(v0, v1, hp, lp);
                        size_t idx = ((size_t)(b * NH + h) * SEQ + s) * DK + d;
                        if (which == 0) {
                            *(uint32_t*)&g_Qh[idx] = hp;
                            *(uint32_t*)&g_Ql[idx] = lp;
                        } else {
                            *(uint32_t*)&g_Kh[idx] = hp;
                            *(uint32_t*)&g_Kl[idx] = lp;
                        }
                    }
                }
            }
        }
    } else {
#pragma unroll
        for (int f = 0; f < 2; f++) {
            int mrow0 = m0 + warp_m * 32 + f * 16 + (lane >> 2);
#pragma unroll
            for (int g = 0; g < 4; g++) {
                int ncol = n0 + warp_n * 32 + g * 8 + (lane & 3) * 2;
#pragma unroll
                for (int ep = 0; ep < 2; ep++) {
                    int m = mrow0 + ep * 8;
                    float2 v = make_float2(acc[f][g][2 * ep] + biasm[ncol],
                                           acc[f][g][2 * ep + 1] + biasm[ncol + 1]);
                    *(float2*)&Cout[(size_t)m * D_MODEL + ncol] = v;
                }
            }
        }
    }
}

// ---------------------------------------------------------------------------
// Pipelined MMA flash-attention with rolling circular E buffer (unchanged).
// ---------------------------------------------------------------------------
#define ASTR  72
#define GBSTR 84
#define KV_STAGE_HALVES (4*64*ASTR)
#define ST_KH 0
#define ST_KL (64*ASTR)
#define ST_VH (2*64*ASTR)
#define ST_VL (3*64*ASTR)
#define E_OFF_HALVES (2*KV_STAGE_HALVES)
#define EH_OFF E_OFF_HALVES
#define EL_OFF (E_OFF_HALVES + 256*ASTR)
#define G_OFF_HALVES (E_OFF_HALVES + 2*256*ASTR)
#define ATTN_SMEM (G_OFF_HALVES*2 + 8*16*GBSTR*4)  // 190464 B

__device__ __forceinline__ void attn_issue_tile(
    uint32_t smb, int jt, int tid, int i0,
    const __nv_bfloat16* Khg, const __nv_bfloat16* Klg,
    const __nv_bfloat16* Vhg, const __nv_bfloat16* Vlg)
{
    const int j0 = jt * 64;
    const uint32_t kvbase = smb + (jt & 1) * KV_STAGE_HALVES * 2;
    for (int t = tid; t < 512; t += 256) {
        int r = t >> 3, c8 = (t & 7) * 8;
        uint32_t doff = (r * ASTR + c8) * 2;
        CPA16(kvbase + ST_KH * 2 + doff, Khg + (size_t)(j0 + r) * DK + c8);
        CPA16(kvbase + ST_KL * 2 + doff, Klg + (size_t)(j0 + r) * DK + c8);
        CPA16(kvbase + ST_VH * 2 + doff, Vhg + (size_t)r * SEQ + j0 + c8);
        CPA16(kvbase + ST_VL * 2 + doff, Vlg + (size_t)r * SEQ + j0 + c8);
    }
    const int rlo = (SEQ - 1) + i0 - j0 - 63;
    const int cnt8 = (jt == 0) ? 1536 : 512;
    for (int t = tid; t < cnt8; t += 256) {
        int r = t >> 3, c8 = (t & 7) * 8;
        int er = rlo + r;
        int ers = (er > ELEN - 1) ? (ELEN - 1) : er;
        uint32_t phys = (uint32_t)er & 255u;
        uint32_t doff = (phys * ASTR + c8) * 2;
        CPA16(smb + EH_OFF * 2 + doff, g_Eh + (size_t)ers * DK + c8);
        CPA16(smb + EL_OFF * 2 + doff, g_El + (size_t)ers * DK + c8);
    }
    CP_COMMIT();
}

__global__ __launch_bounds__(256)
void attn_mma_kernel()
{
    extern __shared__ __nv_bfloat16 smh[];
    float* sG = (float*)(smh + G_OFF_HALVES);
    __nv_bfloat16* sQh = (__nv_bfloat16*)sG;
    __nv_bfloat16* sQl = sQh + 128 * ASTR;
    __nv_bfloat16* sEh = smh + EH_OFF;
    __nv_bfloat16* sEl = smh + EL_OFF;

    const int tid  = threadIdx.x;
    const int lane = tid & 31;
    const int w    = tid >> 5;
    const int bh = blockIdx.y;
    const int i0 = blockIdx.x * 128;
    const int b = bh >> 4, h = bh & 15;

    const __nv_bfloat16* Qhg = g_Qh + (size_t)bh * SEQ * DK;
    const __nv_bfloat16* Qlg = g_Ql + (size_t)bh * SEQ * DK;
    const __nv_bfloat16* Khg = g_Kh + (size_t)bh * SEQ * DK;
    const __nv_bfloat16* Klg = g_Kl + (size_t)bh * SEQ * DK;
    const __nv_bfloat16* Vhg = g_Vth + (size_t)bh * DK * SEQ;
    const __nv_bfloat16* Vlg = g_Vtl + (size_t)bh * DK * SEQ;
    const uint32_t smb = smem_u32(smh);

    for (int t = tid; t < 1024; t += 256) {
        int r = t >> 3, c8 = (t & 7) * 8;
        *(uint4*)&sQh[r * ASTR + c8] = *(const uint4*)(Qhg + (size_t)(i0 + r) * DK + c8);
        *(uint4*)&sQl[r * ASTR + c8] = *(const uint4*)(Qlg + (size_t)(i0 + r) * DK + c8);
    }
    __syncthreads();
    uint32_t qh[4][4], ql[4][4];
#pragma unroll
    for (int ks = 0; ks < 4; ks++) {
        uint32_t aH = smem_u32(&sQh[(w * 16 + (lane & 15)) * ASTR + ks * 16 + (lane >> 4) * 8]);
        LDMATRIX_X4(qh[ks][0], qh[ks][1], qh[ks][2], qh[ks][3], aH);
        uint32_t aL = smem_u32(&sQl[(w * 16 + (lane & 15)) * ASTR + ks * 16 + (lane >> 4) * 8]);
        LDMATRIX_X4(ql[ks][0], ql[ks][1], ql[ks][2], ql[ks][3], aL);
    }
    __syncthreads();

    attn_issue_tile(smb, 0, tid, i0, Khg, Klg, Vhg, Vlg);

    float accO[8][4];
#pragma unroll
    for (int nf = 0; nf < 8; nf++)
#pragma unroll
        for (int e = 0; e < 4; e++) accO[nf][e] = 0.f;
    float rmax0 = -1e30f, rmax1 = -1e30f, rsum0 = 0.f, rsum1 = 0.f;

    const int r0 = lane >> 2;
    const int c0 = (lane & 3) * 2;
    float* sGw = sG + w * 16 * GBSTR;

    for (int jt = 0; jt < 16; jt++) {
        if (jt < 15) {
            attn_issue_tile(smb, jt + 1, tid, i0, Khg, Klg, Vhg, Vlg);
            CP_WAIT1();
        } else {
            CP_WAIT0();
        }
        __syncthreads();

        __nv_bfloat16* st = smh + (jt & 1) * KV_STAGE_HALVES;
        __nv_bfloat16* sKh = st + ST_KH;
        __nv_bfloat16* sKl = st + ST_KL;
        __nv_bfloat16* sVh = st + ST_VH;
        __nv_bfloat16* sVl = st + ST_VL;

        const int rbase = (SEQ - 1) + i0 - jt * 64 - 63;
        const int rb255 = rbase & 255;

        // ---- G = Q * Eband^T, band-limited: nf in [2w, 2w+10) ----
        float gac[10][4];
#pragma unroll
        for (int bi = 0; bi < 10; bi++)
#pragma unroll
            for (int e = 0; e < 4; e++) gac[bi][e] = 0.f;
#pragma unroll
        for (int ks = 0; ks < 4; ks++) {
#pragma unroll
            for (int bp = 0; bp < 5; bp++) {
                uint32_t eh4[4], el4[4];
                int row0 = (rb255 + (2 * w + 2 * bp) * 8) & 255;
                ldmB(sEh, ASTR, row0, ks * 16, lane, eh4);
                ldmB(sEl, ASTR, row0, ks * 16, lane, el4);
                MMA_BF16(gac[2 * bp], qh[ks], eh4);
                MMA_BF16(gac[2 * bp], qh[ks], el4);
                MMA_BF16(gac[2 * bp], ql[ks], eh4);
                MMA_BF16(gac[2 * bp + 1], qh[ks], eh4 + 2);
                MMA_BF16(gac[2 * bp + 1], qh[ks], el4 + 2);
                MMA_BF16(gac[2 * bp + 1], ql[ks], eh4 + 2);
            }
        }
#pragma unroll
        for (int bi = 0; bi < 10; bi++) {
            *(float2*)&sGw[r0 * GBSTR + bi * 8 + c0] = make_float2(gac[bi][0], gac[bi][1]);
            *(float2*)&sGw[(r0 + 8) * GBSTR + bi * 8 + c0] = make_float2(gac[bi][2], gac[bi][3]);
        }

        // ---- S = Q * K^T ----
        float s[8][4];
#pragma unroll
        for (int nf = 0; nf < 8; nf++)
#pragma unroll
            for (int e = 0; e < 4; e++) s[nf][e] = 0.f;
#pragma unroll
        for (int ks = 0; ks < 4; ks++) {
#pragma unroll
            for (int gp = 0; gp < 4; gp++) {
                uint32_t kh4[4], kl4[4];
                ldmB(sKh, ASTR, gp * 16, ks * 16, lane, kh4);
                ldmB(sKl, ASTR, gp * 16, ks * 16, lane, kl4);
                MMA_BF16(s[2 * gp], qh[ks], kh4);
                MMA_BF16(s[2 * gp], qh[ks], kl4);
                MMA_BF16(s[2 * gp], ql[ks], kh4);
                MMA_BF16(s[2 * gp + 1], qh[ks], kh4 + 2);
                MMA_BF16(s[2 * gp + 1], qh[ks], kl4 + 2);
                MMA_BF16(s[2 * gp + 1], ql[ks], kh4 + 2);
            }
        }
        __syncwarp();

        // ---- gather BD from G band and add ----
#pragma unroll
        for (int nf = 0; nf < 8; nf++)
#pragma unroll
            for (int e = 0; e < 4; e++) {
                int iw = r0 + ((e >> 1) << 3);
                int jl = nf * 8 + c0 + (e & 1);
                s[nf][e] += sGw[iw * GBSTR + (iw - jl + 63)];
            }

        // ---- online softmax ----
        float mx0 = -1e30f, mx1 = -1e30f;
#pragma unroll
        for (int nf = 0; nf < 8; nf++) {
            mx0 = fmaxf(mx0, fmaxf(s[nf][0], s[nf][1]));
            mx1 = fmaxf(mx1, fmaxf(s[nf][2], s[nf][3]));
        }
#pragma unroll
        for (int o = 1; o <= 2; o <<= 1) {
            mx0 = fmaxf(mx0, __shfl_xor_sync(0xffffffffu, mx0, o));
            mx1 = fmaxf(mx1, __shfl_xor_sync(0xffffffffu, mx1, o));
        }
        float nm0 = fmaxf(rmax0, mx0), nm1 = fmaxf(rmax1, mx1);
        float al0 = __expf(rmax0 - nm0), al1 = __expf(rmax1 - nm1);
        rmax0 = nm0; rmax1 = nm1;
        float ls0 = 0.f, ls1 = 0.f;
#pragma unroll
        for (int nf = 0; nf < 8; nf++) {
            s[nf][0] = __expf(s[nf][0] - nm0);
            s[nf][1] = __expf(s[nf][1] - nm0);
            s[nf][2] = __expf(s[nf][2] - nm1);
            s[nf][3] = __expf(s[nf][3] - nm1);
            ls0 += s[nf][0] + s[nf][1];
            ls1 += s[nf][2] + s[nf][3];
        }
#pragma unroll
        for (int o = 1; o <= 2; o <<= 1) {
            ls0 += __shfl_xor_sync(0xffffffffu, ls0, o);
            ls1 += __shfl_xor_sync(0xffffffffu, ls1, o);
        }
        rsum0 = rsum0 * al0 + ls0;
        rsum1 = rsum1 * al1 + ls1;
#pragma unroll
        for (int nf = 0; nf < 8; nf++) {
            accO[nf][0] *= al0; accO[nf][1] *= al0;
            accO[nf][2] *= al1; accO[nf][3] *= al1;
        }

        // ---- pack P fragments (hi + residual-lo) ----
        uint32_t ph[4][4], pl[4][4];
#pragma unroll
        for (int ks = 0; ks < 4; ks++) {
            int f0 = 2 * ks, f1 = 2 * ks + 1;
            float rlo2[8];
#pragma unroll
            for (int e = 0; e < 4; e++) {
                rlo2[e]     = s[f0][e] - __bfloat162float(__float2bfloat16_rn(s[f0][e]));
                rlo2[4 + e] = s[f1][e] - __bfloat162float(__float2bfloat16_rn(s[f1][e]));
            }
            ph[ks][0] = pack_bf2(s[f0][0], s[f0][1]);
            ph[ks][1] = pack_bf2(s[f0][2], s[f0][3]);
            ph[ks][2] = pack_bf2(s[f1][0], s[f1][1]);
            ph[ks][3] = pack_bf2(s[f1][2], s[f1][3]);
            pl[ks][0] = pack_bf2(rlo2[0], rlo2[1]);
            pl[ks][1] = pack_bf2(rlo2[2], rlo2[3]);
            pl[ks][2] = pack_bf2(rlo2[4], rlo2[5]);
            pl[ks][3] = pack_bf2(rlo2[6], rlo2[7]);
        }

        // ---- O += P * V ----
#pragma unroll
        for (int ks = 0; ks < 4; ks++) {
#pragma unroll
            for (int gp = 0; gp < 4; gp++) {
                uint32_t vh4[4], vl4[4];
                ldmB(sVh, ASTR, gp * 16, ks * 16, lane, vh4);
                ldmB(sVl, ASTR, gp * 16, ks * 16, lane, vl4);
                MMA_BF16(accO[2 * gp], ph[ks], vh4);
                MMA_BF16(accO[2 * gp], ph[ks], vl4);
                MMA_BF16(accO[2 * gp], pl[ks], vh4);
                MMA_BF16(accO[2 * gp + 1], ph[ks], vh4 + 2);
                MMA_BF16(accO[2 * gp + 1], ph[ks], vl4 + 2);
                MMA_BF16(accO[2 * gp + 1], pl[ks], vh4 + 2);
            }
        }
        __syncthreads();
    }

    // ---- epilogue: vectorized pair stores ----
    float inv0 = 1.0f / rsum0, inv1 = 1.0f / rsum1;
#pragma unroll
    for (int nf = 0; nf < 8; nf++)
#pragma unroll
        for (int ep = 0; ep < 2; ep++) {
            int i = i0 + w * 16 + r0 + ep * 8;
            int d = nf * 8 + c0;
            float inv = ep ? inv1 : inv0;
            float v0 = accO[nf][2 * ep + 0] * inv;
            float v1 = accO[nf][2 * ep + 1] * inv;
            uint32_t hp, lp;
            split_bf2(v0, v1, hp, lp);
            size_t idx = ((size_t)(b * SEQ + i)) * D_MODEL + h * DK + d;
            *(uint32_t*)&g_oh[idx] = hp;
            *(uint32_t*)&g_ol[idx] = lp;
        }
}

// ---------------------------------------------------------------------------
extern "C" void kernel_launch(void* const* d_in, const int* in_sizes, int n_in,
                              void* d_out, int out_size)
{
    const float* x  = (const float*)d_in[0];
    const float* Wq = (const float*)d_in[1];
    const float* bq = (const float*)d_in[2];
    const float* Wk = (const float*)d_in[3];
    const float* bk = (const float*)d_in[4];
    const float* Wv = (const float*)d_in[5];
    const float* bv = (const float*)d_in[6];
    const float* Wo = (const float*)d_in[7];
    const float* bo = (const float*)d_in[8];
    const float* Er = (const float*)d_in[9];
    float* out = (float*)d_out;

    cudaFuncSetAttribute(gemm_bf16_kernel,
                         cudaFuncAttributeMaxDynamicSharedMemorySize, GEMM_DYN_SMEM);
    cudaFuncSetAttribute(attn_mma_kernel,
                         cudaFuncAttributeMaxDynamicSharedMemorySize, ATTN_SMEM);

    __nv_bfloat16 *xh, *xl, *wh, *wl, *oh, *ol;
    cudaGetSymbolAddress((void**)&xh, g_xh);
    cudaGetSymbolAddress((void**)&xl, g_xl);
    cudaGetSymbolAddress((void**)&wh, g_wh);
    cudaGetSymbolAddress((void**)&wl, g_wl);
    cudaGetSymbolAddress((void**)&oh, g_oh);
    cudaGetSymbolAddress((void**)&ol, g_ol);

    // 0) split x, weights, Er into bf16 hi/lo
    {
        int total = (MTOT * D_MODEL + 4 * D_MODEL * D_MODEL + ELEN * DK) / 4;
        convert_xw_kernel<<<(total + 255) / 256, 256>>>(x, Wq, Wk, Wv, Wo, Er);
    }
    // 1) fused QKV projection -> split-bf16 Q/K (head-major) + V^T
    {
        dim3 grid(3072 / 128, MTOT / 128);
        gemm_bf16_kernel<<<grid, 512, GEMM_DYN_SMEM>>>(
            xh, xl, wh, wl, bq, bk, bv, nullptr, 0);
    }
    // 2) pipelined MMA attention -> split-bf16 O
    {
        dim3 grid(SEQ / 128, BHT);           // 8 x 32
        attn_mma_kernel<<<grid, 256, ATTN_SMEM>>>();
    }
    // 3) output projection -> out
    {
        dim3 grid(D_MODEL / 128, MTOT / 128);
        gemm_bf16_kernel<<<grid, 512, GEMM_DYN_SMEM>>>(
            oh, ol, wh + (size_t)3 * D_MODEL * D_MODEL, wl + (size_t)3 * D_MODEL * D_MODEL,
            bo, bo, bo, out, 1);
    }
}

// round 14
// speedup vs baseline: 1.5445x; 1.3449x over previous
#include <cuda_runtime.h>
#include <cuda_fp16.h>
#include <math.h>
#include <stdint.h>

#define D_MODEL 1024
#define NH      16
#define DK      64
#define BATCH   2
#define SEQ     1024
#define BHT     (BATCH*NH)          // 32
#define MTOT    (BATCH*SEQ)         // 2048
#define ELEN    (2*SEQ-1)           // 2047

// ---------------- scratch (device globals; no allocation allowed) ----------
__device__ __half g_xh[MTOT*D_MODEL];
__device__ __half g_xl[MTOT*D_MODEL];
__device__ __half g_wh[4*D_MODEL*D_MODEL];   // Wq|Wk|Wv|Wo (hi only)
__device__ __half g_oh[MTOT*D_MODEL];
__device__ __half g_ol[MTOT*D_MODEL];

__device__ __half g_Qh[BHT*SEQ*DK];   // [bh][s][d], pre-scaled 1/8 (split)
__device__ __half g_Ql[BHT*SEQ*DK];
__device__ __half g_Kh[BHT*SEQ*DK];   // hi only
__device__ __half g_Vth[BHT*DK*SEQ];  // [bh][d][s]  transposed, hi only
__device__ __half g_Eh[ELEN*DK];      // hi only

// ---------------- helpers ---------------------------------------------------
__device__ __forceinline__ uint32_t smem_u32(const void* p) {
    uint32_t a;
    asm("{ .reg .u64 t; cvta.to.shared.u64 t, %1; cvt.u32.u64 %0, t; }"
        : "=r"(a) : "l"(p));
    return a;
}

#define CPA16(dst_u32, src_ptr) \
    asm volatile("cp.async.ca.shared.global [%0], [%1], 16;" \
                 :: "r"(dst_u32), "l"(src_ptr) : "memory")
#define CP_COMMIT() asm volatile("cp.async.commit_group;" ::: "memory")
#define CP_WAIT0()  asm volatile("cp.async.wait_group 0;" ::: "memory")
#define CP_WAIT1()  asm volatile("cp.async.wait_group 1;" ::: "memory")

#define LDMATRIX_X4(r0, r1, r2, r3, addr) \
    asm("ldmatrix.sync.aligned.m8n8.x4.shared.b16 {%0,%1,%2,%3}, [%4];" \
        : "=r"(r0), "=r"(r1), "=r"(r2), "=r"(r3) : "r"(addr))

#define MMA_F16(c, a, b) \
    asm("mma.sync.aligned.m16n8k16.row.col.f32.f16.f16.f32 " \
        "{%0,%1,%2,%3}, {%4,%5,%6,%7}, {%8,%9}, {%0,%1,%2,%3};" \
        : "+f"((c)[0]), "+f"((c)[1]), "+f"((c)[2]), "+f"((c)[3]) \
        : "r"((a)[0]), "r"((a)[1]), "r"((a)[2]), "r"((a)[3]), \
          "r"((b)[0]), "r"((b)[1]))

// Load B-fragments for TWO n-frags with one ldmatrix.x4.
__device__ __forceinline__ void ldmB(const __half* base, int stride,
                                     int row0, int kcol, int lane, uint32_t* r)
{
    int sel = (lane >> 4) & 1;
    int row = row0 + sel * 8 + (lane & 7);
    int col = kcol + ((lane >> 3) & 1) * 8;
    uint32_t a = smem_u32(base + row * stride + col);
    LDMATRIX_X4(r[0], r[1], r[2], r[3], a);
}

__device__ __forceinline__ uint32_t pack_h2(float lo, float hi) {
    __half2 t = __floats2half2_rn(lo, hi);
    return *(uint32_t*)&t;
}
__device__ __forceinline__ void split_h(float v, __half& h, __half& l) {
    h = __float2half_rn(v);
    l = __float2half_rn(v - __half2float(h));
}
__device__ __forceinline__ void split_h2(float v0, float v1,
                                         uint32_t& hp, uint32_t& lp) {
    __half h0, l0, h1, l1;
    split_h(v0, h0, l0);
    split_h(v1, h1, l1);
    __half2 hh; hh.x = h0; hh.y = h1;
    __half2 ll; ll.x = l0; ll.y = l1;
    hp = *(uint32_t*)&hh;
    lp = *(uint32_t*)&ll;
}

// ---------------------------------------------------------------------------
// fp32 -> fp16 conversion: x split hi/lo; weights & Er hi only.
// ---------------------------------------------------------------------------
__global__ void convert_xw_kernel(const float* __restrict__ x,
                                  const float* __restrict__ Wq, const float* __restrict__ Wk,
                                  const float* __restrict__ Wv, const float* __restrict__ Wo,
                                  const float* __restrict__ Er)
{
    const int NX = MTOT * D_MODEL / 4;
    const int NW = D_MODEL * D_MODEL / 4;
    const int NE = ELEN * DK / 4;
    int g = blockIdx.x * blockDim.x + threadIdx.x;
    if (g >= NX + 4 * NW + NE) return;
    if (g < NX) {
        float4 v = *(const float4*)(x + g * 4);
        __half hv[4], lv[4];
        split_h(v.x, hv[0], lv[0]); split_h(v.y, hv[1], lv[1]);
        split_h(v.z, hv[2], lv[2]); split_h(v.w, hv[3], lv[3]);
        *(uint2*)(g_xh + g * 4) = *(uint2*)hv;
        *(uint2*)(g_xl + g * 4) = *(uint2*)lv;
    } else if (g < NX + 4 * NW) {
        int wi = g - NX;
        int which = wi / NW;
        int off = wi - which * NW;
        const float* W = (which == 0) ? Wq : (which == 1) ? Wk : (which == 2) ? Wv : Wo;
        float4 v = *(const float4*)(W + off * 4);
        __half hv[4] = {__float2half_rn(v.x), __float2half_rn(v.y),
                        __float2half_rn(v.z), __float2half_rn(v.w)};
        *(uint2*)(g_wh + (size_t)which * NW * 4 + off * 4) = *(uint2*)hv;
    } else {
        int ei = g - NX - 4 * NW;
        float4 v = *(const float4*)(Er + ei * 4);
        __half hv[4] = {__float2half_rn(v.x), __float2half_rn(v.y),
                        __float2half_rn(v.z), __float2half_rn(v.w)};
        *(uint2*)(g_Eh + ei * 4) = *(uint2*)hv;
    }
}

// ---------------------------------------------------------------------------
// 2-term fp16 mma.sync GEMM: C = (Ah+Al) * Bh^T.  512 threads / 16 warps,
// 128x128 tile, warp tile 32x32, 3-stage cp.async.ca pipeline, BK=32.
// ---------------------------------------------------------------------------
#define HSTR 40
#define MAT_HALVES (128*HSTR)
#define BUF_HALVES (3*MAT_HALVES)              // Ah, Al, Bh
#define GSTAGES 3
#define GEMM_DYN_SMEM (GSTAGES*BUF_HALVES*2)   // 92160 B

__global__ __launch_bounds__(512, 1)
void gemm_f16_kernel(const __half* __restrict__ Ah, const __half* __restrict__ Al,
                     const __half* __restrict__ Bh,
                     const float* __restrict__ bias0, const float* __restrict__ bias1,
                     const float* __restrict__ bias2,
                     float* __restrict__ Cout, int mode)
{
    extern __shared__ __half sm[];

    const int tid  = threadIdx.x;
    const int wid  = tid >> 5;          // 0..15
    const int lane = tid & 31;
    const int warp_m = wid >> 2;        // 0..3
    const int warp_n = wid & 3;         // 0..3
    const int m0 = blockIdx.y * 128;
    const int n0 = blockIdx.x * 128;
    const int which = n0 >> 10;
    const int n0m = n0 & 1023;
    const float* biasm = (which == 0) ? bias0 : (which == 1) ? bias1 : bias2;

    float acc[2][4][4];
#pragma unroll
    for (int f = 0; f < 2; f++)
#pragma unroll
        for (int g = 0; g < 4; g++)
#pragma unroll
            for (int e = 0; e < 4; e++) acc[f][g][e] = 0.f;

    const int lrow = tid >> 2;          // 0..127
    const int lk   = (tid & 3) * 8;     // 0,8,16,24
    const uint32_t smb = smem_u32(sm);

    auto issue = [&](int c) {
        uint32_t bb = smb + (c % GSTAGES) * BUF_HALVES * 2;
        int kg = c * 32 + lk;
        uint32_t doff = (lrow * HSTR + lk) * 2;
        CPA16(bb + 0 * MAT_HALVES * 2 + doff, Ah + (size_t)(m0 + lrow) * 1024 + kg);
        CPA16(bb + 1 * MAT_HALVES * 2 + doff, Al + (size_t)(m0 + lrow) * 1024 + kg);
        CPA16(bb + 2 * MAT_HALVES * 2 + doff, Bh + (size_t)(n0 + lrow) * 1024 + kg);
        CP_COMMIT();
    };

    issue(0);
    issue(1);

    const int a_r   = lane & 15;
    const int a_kof = (lane >> 4) * 8;

    for (int c = 0; c < 32; c++) {
        if (c < 31) CP_WAIT1(); else CP_WAIT0();
        __syncthreads();
        if (c + 2 < 32) issue(c + 2);

        __half* cb = sm + (c % GSTAGES) * BUF_HALVES;
#pragma unroll
        for (int ks = 0; ks < 2; ks++) {
            uint32_t aH[2][4], aL[2][4], bH[2][4];
#pragma unroll
            for (int f = 0; f < 2; f++) {
                int row = warp_m * 32 + f * 16 + a_r;
                uint32_t addrH = smem_u32(&cb[0 * MAT_HALVES + row * HSTR + ks * 16 + a_kof]);
                LDMATRIX_X4(aH[f][0], aH[f][1], aH[f][2], aH[f][3], addrH);
                uint32_t addrL = smem_u32(&cb[1 * MAT_HALVES + row * HSTR + ks * 16 + a_kof]);
                LDMATRIX_X4(aL[f][0], aL[f][1], aL[f][2], aL[f][3], addrL);
            }
            ldmB(&cb[2 * MAT_HALVES], HSTR, warp_n * 32 +  0, ks * 16, lane, bH[0]);
            ldmB(&cb[2 * MAT_HALVES], HSTR, warp_n * 32 + 16, ks * 16, lane, bH[1]);
#pragma unroll
            for (int f = 0; f < 2; f++)
#pragma unroll
                for (int g = 0; g < 4; g++) {
                    const uint32_t* ph = &bH[g >> 1][(g & 1) * 2];
                    MMA_F16(acc[f][g], aH[f], ph);
                    MMA_F16(acc[f][g], aL[f], ph);
                }
        }
        __syncthreads();
    }

    if (mode == 0) {
        const float scale = (which == 0) ? 0.125f : 1.0f;
#pragma unroll
        for (int f = 0; f < 2; f++) {
            int mrow0 = m0 + warp_m * 32 + f * 16 + (lane >> 2);
#pragma unroll
            for (int g = 0; g < 4; g++) {
                int ncol = n0m + warp_n * 32 + g * 8 + (lane & 3) * 2;  // even
#pragma unroll
                for (int ep = 0; ep < 2; ep++) {
                    int m = mrow0 + ep * 8;
                    int b = m >> 10, s = m & 1023;
                    float v0 = (acc[f][g][2 * ep + 0] + biasm[ncol]) * scale;
                    float v1 = (acc[f][g][2 * ep + 1] + biasm[ncol + 1]) * scale;
                    if (which == 2) {
                        int h = ncol >> 6;
#pragma unroll
                        for (int e = 0; e < 2; e++) {
                            int d = (ncol + e) & 63;
                            float val = e ? v1 : v0;
                            size_t idx = ((size_t)(b * NH + h) * DK + d) * SEQ + s;
                            g_Vth[idx] = __float2half_rn(val);
                        }
                    } else if (which == 0) {
                        int h = ncol >> 6, d = ncol & 63;
                        uint32_t hp, lp;
                        split_h2(v0, v1, hp, lp);
                        size_t idx = ((size_t)(b * NH + h) * SEQ + s) * DK + d;
                        *(uint32_t*)&g_Qh[idx] = hp;
                        *(uint32_t*)&g_Ql[idx] = lp;
                    } else {
                        int h = ncol >> 6, d = ncol & 63;
                        __half2 kk = __floats2half2_rn(v0, v1);
                        size_t idx = ((size_t)(b * NH + h) * SEQ + s) * DK + d;
                        *(uint32_t*)&g_Kh[idx] = *(uint32_t*)&kk;
                    }
                }
            }
        }
    } else {
#pragma unroll
        for (int f = 0; f < 2; f++) {
            int mrow0 = m0 + warp_m * 32 + f * 16 + (lane >> 2);
#pragma unroll
            for (int g = 0; g < 4; g++) {
                int ncol = n0 + warp_n * 32 + g * 8 + (lane & 3) * 2;
#pragma unroll
                for (int ep = 0; ep < 2; ep++) {
                    int m = mrow0 + ep * 8;
                    float2 v = make_float2(acc[f][g][2 * ep] + biasm[ncol],
                                           acc[f][g][2 * ep + 1] + biasm[ncol + 1]);
                    *(float2*)&Cout[(size_t)m * D_MODEL + ncol] = v;
                }
            }
        }
    }
}

// ---------------------------------------------------------------------------
// Pipelined MMA flash-attention, fp16 2-term, rolling circular E buffer.
// ---------------------------------------------------------------------------
#define ASTR  72
#define GBSTR 84
#define KV_STAGE_HALVES (2*64*ASTR)             // Kh + Vh
#define ST_KH 0
#define ST_VH (64*ASTR)
#define E_OFF_HALVES (2*KV_STAGE_HALVES)        // 18432
#define EH_OFF E_OFF_HALVES
#define G_OFF_HALVES (E_OFF_HALVES + 256*ASTR)  // 36864
#define ATTN_SMEM (G_OFF_HALVES*2 + 8*16*GBSTR*4)  // 73728 + 43008 = 116736 B

__device__ __forceinline__ void attn_issue_tile(
    uint32_t smb, int jt, int tid, int i0,
    const __half* Khg, const __half* Vhg)
{
    const int j0 = jt * 64;
    const uint32_t kvbase = smb + (jt & 1) * KV_STAGE_HALVES * 2;
    for (int t = tid; t < 512; t += 256) {
        int r = t >> 3, c8 = (t & 7) * 8;
        uint32_t doff = (r * ASTR + c8) * 2;
        CPA16(kvbase + ST_KH * 2 + doff, Khg + (size_t)(j0 + r) * DK + c8);
        CPA16(kvbase + ST_VH * 2 + doff, Vhg + (size_t)r * SEQ + j0 + c8);
    }
    const int rlo = (SEQ - 1) + i0 - j0 - 63;
    const int cnt8 = (jt == 0) ? 1536 : 512;
    for (int t = tid; t < cnt8; t += 256) {
        int r = t >> 3, c8 = (t & 7) * 8;
        int er = rlo + r;
        int ers = (er > ELEN - 1) ? (ELEN - 1) : er;
        uint32_t phys = (uint32_t)er & 255u;
        uint32_t doff = (phys * ASTR + c8) * 2;
        CPA16(smb + EH_OFF * 2 + doff, g_Eh + (size_t)ers * DK + c8);
    }
    CP_COMMIT();
}

__global__ __launch_bounds__(256)
void attn_mma_kernel()
{
    extern __shared__ __half smh[];
    float* sG = (float*)(smh + G_OFF_HALVES);
    __half* sQh = (__half*)sG;                 // staging overlay (36864B<43008B)
    __half* sQl = sQh + 128 * ASTR;
    __half* sEh = smh + EH_OFF;

    const int tid  = threadIdx.x;
    const int lane = tid & 31;
    const int w    = tid >> 5;
    const int bh = blockIdx.y;
    const int i0 = blockIdx.x * 128;
    const int b = bh >> 4, h = bh & 15;

    const __half* Qhg = g_Qh + (size_t)bh * SEQ * DK;
    const __half* Qlg = g_Ql + (size_t)bh * SEQ * DK;
    const __half* Khg = g_Kh + (size_t)bh * SEQ * DK;
    const __half* Vhg = g_Vth + (size_t)bh * DK * SEQ;
    const uint32_t smb = smem_u32(smh);

    for (int t = tid; t < 1024; t += 256) {
        int r = t >> 3, c8 = (t & 7) * 8;
        *(uint4*)&sQh[r * ASTR + c8] = *(const uint4*)(Qhg + (size_t)(i0 + r) * DK + c8);
        *(uint4*)&sQl[r * ASTR + c8] = *(const uint4*)(Qlg + (size_t)(i0 + r) * DK + c8);
    }
    __syncthreads();
    uint32_t qh[4][4], ql[4][4];
#pragma unroll
    for (int ks = 0; ks < 4; ks++) {
        uint32_t aH = smem_u32(&sQh[(w * 16 + (lane & 15)) * ASTR + ks * 16 + (lane >> 4) * 8]);
        LDMATRIX_X4(qh[ks][0], qh[ks][1], qh[ks][2], qh[ks][3], aH);
        uint32_t aL = smem_u32(&sQl[(w * 16 + (lane & 15)) * ASTR + ks * 16 + (lane >> 4) * 8]);
        LDMATRIX_X4(ql[ks][0], ql[ks][1], ql[ks][2], ql[ks][3], aL);
    }
    __syncthreads();

    attn_issue_tile(smb, 0, tid, i0, Khg, Vhg);

    float accO[8][4];
#pragma unroll
    for (int nf = 0; nf < 8; nf++)
#pragma unroll
        for (int e = 0; e < 4; e++) accO[nf][e] = 0.f;
    float rmax0 = -1e30f, rmax1 = -1e30f, rsum0 = 0.f, rsum1 = 0.f;

    const int r0 = lane >> 2;
    const int c0 = (lane & 3) * 2;
    float* sGw = sG + w * 16 * GBSTR;

    for (int jt = 0; jt < 16; jt++) {
        if (jt < 15) {
            attn_issue_tile(smb, jt + 1, tid, i0, Khg, Vhg);
            CP_WAIT1();
        } else {
            CP_WAIT0();
        }
        __syncthreads();

        __half* st = smh + (jt & 1) * KV_STAGE_HALVES;
        __half* sKh = st + ST_KH;
        __half* sVh = st + ST_VH;

        const int rbase = (SEQ - 1) + i0 - jt * 64 - 63;
        const int rb255 = rbase & 255;

        // ---- G = Q * Eband^T, band-limited: nf in [2w, 2w+10) ----
        float gac[10][4];
#pragma unroll
        for (int bi = 0; bi < 10; bi++)
#pragma unroll
            for (int e = 0; e < 4; e++) gac[bi][e] = 0.f;
#pragma unroll
        for (int ks = 0; ks < 4; ks++) {
#pragma unroll
            for (int bp = 0; bp < 5; bp++) {
                uint32_t eh4[4];
                int row0 = (rb255 + (2 * w + 2 * bp) * 8) & 255;
                ldmB(sEh, ASTR, row0, ks * 16, lane, eh4);
                MMA_F16(gac[2 * bp], qh[ks], eh4);
                MMA_F16(gac[2 * bp], ql[ks], eh4);
                MMA_F16(gac[2 * bp + 1], qh[ks], eh4 + 2);
                MMA_F16(gac[2 * bp + 1], ql[ks], eh4 + 2);
            }
        }
#pragma unroll
        for (int bi = 0; bi < 10; bi++) {
            *(float2*)&sGw[r0 * GBSTR + bi * 8 + c0] = make_float2(gac[bi][0], gac[bi][1]);
            *(float2*)&sGw[(r0 + 8) * GBSTR + bi * 8 + c0] = make_float2(gac[bi][2], gac[bi][3]);
        }

        // ---- S = Q * K^T ----
        float s[8][4];
#pragma unroll
        for (int nf = 0; nf < 8; nf++)
#pragma unroll
            for (int e = 0; e < 4; e++) s[nf][e] = 0.f;
#pragma unroll
        for (int ks = 0; ks < 4; ks++) {
#pragma unroll
            for (int gp = 0; gp < 4; gp++) {
                uint32_t kh4[4];
                ldmB(sKh, ASTR, gp * 16, ks * 16, lane, kh4);
                MMA_F16(s[2 * gp], qh[ks], kh4);
                MMA_F16(s[2 * gp], ql[ks], kh4);
                MMA_F16(s[2 * gp + 1], qh[ks], kh4 + 2);
                MMA_F16(s[2 * gp + 1], ql[ks], kh4 + 2);
            }
        }
        __syncwarp();

        // ---- gather BD from G band and add ----
#pragma unroll
        for (int nf = 0; nf < 8; nf++)
#pragma unroll
            for (int e = 0; e < 4; e++) {
                int iw = r0 + ((e >> 1) << 3);
                int jl = nf * 8 + c0 + (e & 1);
                s[nf][e] += sGw[iw * GBSTR + (iw - jl + 63)];
            }

        // ---- online softmax ----
        float mx0 = -1e30f, mx1 = -1e30f;
#pragma unroll
        for (int nf = 0; nf < 8; nf++) {
            mx0 = fmaxf(mx0, fmaxf(s[nf][0], s[nf][1]));
            mx1 = fmaxf(mx1, fmaxf(s[nf][2], s[nf][3]));
        }
#pragma unroll
        for (int o = 1; o <= 2; o <<= 1) {
            mx0 = fmaxf(mx0, __shfl_xor_sync(0xffffffffu, mx0, o));
            mx1 = fmaxf(mx1, __shfl_xor_sync(0xffffffffu, mx1, o));
        }
        float nm0 = fmaxf(rmax0, mx0), nm1 = fmaxf(rmax1, mx1);
        float al0 = __expf(rmax0 - nm0), al1 = __expf(rmax1 - nm1);
        rmax0 = nm0; rmax1 = nm1;
        float ls0 = 0.f, ls1 = 0.f;
#pragma unroll
        for (int nf = 0; nf < 8; nf++) {
            s[nf][0] = __expf(s[nf][0] - nm0);
            s[nf][1] = __expf(s[nf][1] - nm0);
            s[nf][2] = __expf(s[nf][2] - nm1);
            s[nf][3] = __expf(s[nf][3] - nm1);
            ls0 += s[nf][0] + s[nf][1];
            ls1 += s[nf][2] + s[nf][3];
        }
#pragma unroll
        for (int o = 1; o <= 2; o <<= 1) {
            ls0 += __shfl_xor_sync(0xffffffffu, ls0, o);
            ls1 += __shfl_xor_sync(0xffffffffu, ls1, o);
        }
        rsum0 = rsum0 * al0 + ls0;
        rsum1 = rsum1 * al1 + ls1;
#pragma unroll
        for (int nf = 0; nf < 8; nf++) {
            accO[nf][0] *= al0; accO[nf][1] *= al0;
            accO[nf][2] *= al1; accO[nf][3] *= al1;
        }

        // ---- pack P fragments (hi + residual-lo) ----
        uint32_t ph[4][4], pl[4][4];
#pragma unroll
        for (int ks = 0; ks < 4; ks++) {
            int f0 = 2 * ks, f1 = 2 * ks + 1;
            float rlo2[8];
#pragma unroll
            for (int e = 0; e < 4; e++) {
                rlo2[e]     = s[f0][e] - __half2float(__float2half_rn(s[f0][e]));
                rlo2[4 + e] = s[f1][e] - __half2float(__float2half_rn(s[f1][e]));
            }
            ph[ks][0] = pack_h2(s[f0][0], s[f0][1]);
            ph[ks][1] = pack_h2(s[f0][2], s[f0][3]);
            ph[ks][2] = pack_h2(s[f1][0], s[f1][1]);
            ph[ks][3] = pack_h2(s[f1][2], s[f1][3]);
            pl[ks][0] = pack_h2(rlo2[0], rlo2[1]);
            pl[ks][1] = pack_h2(rlo2[2], rlo2[3]);
            pl[ks][2] = pack_h2(rlo2[4], rlo2[5]);
            pl[ks][3] = pack_h2(rlo2[6], rlo2[7]);
        }

        // ---- O += P * V ----
#pragma unroll
        for (int ks = 0; ks < 4; ks++) {
#pragma unroll
            for (int gp = 0; gp < 4; gp++) {
                uint32_t vh4[4];
                ldmB(sVh, ASTR, gp * 16, ks * 16, lane, vh4);
                MMA_F16(accO[2 * gp], ph[ks], vh4);
                MMA_F16(accO[2 * gp], pl[ks], vh4);
                MMA_F16(accO[2 * gp + 1], ph[ks], vh4 + 2);
                MMA_F16(accO[2 * gp + 1], pl[ks], vh4 + 2);
            }
        }
        __syncthreads();
    }

    // ---- epilogue: vectorized pair stores ----
    float inv0 = 1.0f / rsum0, inv1 = 1.0f / rsum1;
#pragma unroll
    for (int nf = 0; nf < 8; nf++)
#pragma unroll
        for (int ep = 0; ep < 2; ep++) {
            int i = i0 + w * 16 + r0 + ep * 8;
            int d = nf * 8 + c0;
            float inv = ep ? inv1 : inv0;
            float v0 = accO[nf][2 * ep + 0] * inv;
            float v1 = accO[nf][2 * ep + 1] * inv;
            uint32_t hp, lp;
            split_h2(v0, v1, hp, lp);
            size_t idx = ((size_t)(b * SEQ + i)) * D_MODEL + h * DK + d;
            *(uint32_t*)&g_oh[idx] = hp;
            *(uint32_t*)&g_ol[idx] = lp;
        }
}

// ---------------------------------------------------------------------------
extern "C" void kernel_launch(void* const* d_in, const int* in_sizes, int n_in,
                              void* d_out, int out_size)
{
    const float* x  = (const float*)d_in[0];
    const float* Wq = (const float*)d_in[1];
    const float* bq = (const float*)d_in[2];
    const float* Wk = (const float*)d_in[3];
    const float* bk = (const float*)d_in[4];
    const float* Wv = (const float*)d_in[5];
    const float* bv = (const float*)d_in[6];
    const float* Wo = (const float*)d_in[7];
    const float* bo = (const float*)d_in[8];
    const float* Er = (const float*)d_in[9];
    float* out = (float*)d_out;

    cudaFuncSetAttribute(gemm_f16_kernel,
                         cudaFuncAttributeMaxDynamicSharedMemorySize, GEMM_DYN_SMEM);
    cudaFuncSetAttribute(attn_mma_kernel,
                         cudaFuncAttributeMaxDynamicSharedMemorySize, ATTN_SMEM);

    __half *xh, *xl, *wh, *oh, *ol;
    cudaGetSymbolAddress((void**)&xh, g_xh);
    cudaGetSymbolAddress((void**)&xl, g_xl);
    cudaGetSymbolAddress((void**)&wh, g_wh);
    cudaGetSymbolAddress((void**)&oh, g_oh);
    cudaGetSymbolAddress((void**)&ol, g_ol);

    // 0) convert: x split fp16; weights & Er hi-only fp16
    {
        int total = (MTOT * D_MODEL + 4 * D_MODEL * D_MODEL + ELEN * DK) / 4;
        convert_xw_kernel<<<(total + 255) / 256, 256>>>(x, Wq, Wk, Wv, Wo, Er);
    }
    // 1) fused QKV projection -> Q split, K hi, V^T hi
    {
        dim3 grid(3072 / 128, MTOT / 128);
        gemm_f16_kernel<<<grid, 512, GEMM_DYN_SMEM>>>(
            xh, xl, wh, bq, bk, bv, nullptr, 0);
    }
    // 2) pipelined MMA attention -> O split
    {
        dim3 grid(SEQ / 128, BHT);           // 8 x 32
        attn_mma_kernel<<<grid, 256, ATTN_SMEM>>>();
    }
    // 3) output projection -> out
    {
        dim3 grid(D_MODEL / 128, MTOT / 128);
        gemm_f16_kernel<<<grid, 512, GEMM_DYN_SMEM>>>(
            oh, ol, wh + (size_t)3 * D_MODEL * D_MODEL,
            bo, bo, bo, out, 1);
    }
}

// round 15
// speedup vs baseline: 1.6815x; 1.0887x over previous
#include <cuda_runtime.h>
#include <cuda_fp16.h>
#include <math.h>
#include <stdint.h>

#define D_MODEL 1024
#define NH      16
#define DK      64
#define BATCH   2
#define SEQ     1024
#define BHT     (BATCH*NH)          // 32
#define MTOT    (BATCH*SEQ)         // 2048
#define ELEN    (2*SEQ-1)           // 2047

// ---------------- scratch (device globals; no allocation allowed) ----------
__device__ __half g_xh[MTOT*D_MODEL];
__device__ __half g_xl[MTOT*D_MODEL];
__device__ __half g_wh[4*D_MODEL*D_MODEL];   // Wq|Wk|Wv|Wo (hi only)
__device__ __half g_oh[MTOT*D_MODEL];        // attention out (hi only)

__device__ __half g_Qh[BHT*SEQ*DK];   // [bh][s][d], pre-scaled 1/8 (split)
__device__ __half g_Ql[BHT*SEQ*DK];
__device__ __half g_Kh[BHT*SEQ*DK];   // hi only
__device__ __half g_Vth[BHT*DK*SEQ];  // [bh][d][s]  transposed, hi only
__device__ __half g_Eh[ELEN*DK];      // hi only

// ---------------- helpers ---------------------------------------------------
__device__ __forceinline__ uint32_t smem_u32(const void* p) {
    uint32_t a;
    asm("{ .reg .u64 t; cvta.to.shared.u64 t, %1; cvt.u32.u64 %0, t; }"
        : "=r"(a) : "l"(p));
    return a;
}

#define CPA16(dst_u32, src_ptr) \
    asm volatile("cp.async.ca.shared.global [%0], [%1], 16;" \
                 :: "r"(dst_u32), "l"(src_ptr) : "memory")
#define CP_COMMIT() asm volatile("cp.async.commit_group;" ::: "memory")
#define CP_WAIT0()  asm volatile("cp.async.wait_group 0;" ::: "memory")
#define CP_WAIT1()  asm volatile("cp.async.wait_group 1;" ::: "memory")

#define LDMATRIX_X4(r0, r1, r2, r3, addr) \
    asm("ldmatrix.sync.aligned.m8n8.x4.shared.b16 {%0,%1,%2,%3}, [%4];" \
        : "=r"(r0), "=r"(r1), "=r"(r2), "=r"(r3) : "r"(addr))

#define MMA_F16(c, a, b) \
    asm("mma.sync.aligned.m16n8k16.row.col.f32.f16.f16.f32 " \
        "{%0,%1,%2,%3}, {%4,%5,%6,%7}, {%8,%9}, {%0,%1,%2,%3};" \
        : "+f"((c)[0]), "+f"((c)[1]), "+f"((c)[2]), "+f"((c)[3]) \
        : "r"((a)[0]), "r"((a)[1]), "r"((a)[2]), "r"((a)[3]), \
          "r"((b)[0]), "r"((b)[1]))

// Load B-fragments for TWO n-frags with one ldmatrix.x4.
__device__ __forceinline__ void ldmB(const __half* base, int stride,
                                     int row0, int kcol, int lane, uint32_t* r)
{
    int sel = (lane >> 4) & 1;
    int row = row0 + sel * 8 + (lane & 7);
    int col = kcol + ((lane >> 3) & 1) * 8;
    uint32_t a = smem_u32(base + row * stride + col);
    LDMATRIX_X4(r[0], r[1], r[2], r[3], a);
}

__device__ __forceinline__ uint32_t pack_h2(float lo, float hi) {
    __half2 t = __floats2half2_rn(lo, hi);
    return *(uint32_t*)&t;
}
__device__ __forceinline__ void split_h(float v, __half& h, __half& l) {
    h = __float2half_rn(v);
    l = __float2half_rn(v - __half2float(h));
}
__device__ __forceinline__ void split_h2(float v0, float v1,
                                         uint32_t& hp, uint32_t& lp) {
    __half h0, l0, h1, l1;
    split_h(v0, h0, l0);
    split_h(v1, h1, l1);
    __half2 hh; hh.x = h0; hh.y = h1;
    __half2 ll; ll.x = l0; ll.y = l1;
    hp = *(uint32_t*)&hh;
    lp = *(uint32_t*)&ll;
}

// ---------------------------------------------------------------------------
// fp32 -> fp16 conversion: x split hi/lo; weights & Er hi only.
// ---------------------------------------------------------------------------
__global__ void convert_xw_kernel(const float* __restrict__ x,
                                  const float* __restrict__ Wq, const float* __restrict__ Wk,
                                  const float* __restrict__ Wv, const float* __restrict__ Wo,
                                  const float* __restrict__ Er)
{
    const int NX = MTOT * D_MODEL / 4;
    const int NW = D_MODEL * D_MODEL / 4;
    const int NE = ELEN * DK / 4;
    int g = blockIdx.x * blockDim.x + threadIdx.x;
    if (g >= NX + 4 * NW + NE) return;
    if (g < NX) {
        float4 v = *(const float4*)(x + g * 4);
        __half hv[4], lv[4];
        split_h(v.x, hv[0], lv[0]); split_h(v.y, hv[1], lv[1]);
        split_h(v.z, hv[2], lv[2]); split_h(v.w, hv[3], lv[3]);
        *(uint2*)(g_xh + g * 4) = *(uint2*)hv;
        *(uint2*)(g_xl + g * 4) = *(uint2*)lv;
    } else if (g < NX + 4 * NW) {
        int wi = g - NX;
        int which = wi / NW;
        int off = wi - which * NW;
        const float* W = (which == 0) ? Wq : (which == 1) ? Wk : (which == 2) ? Wv : Wo;
        float4 v = *(const float4*)(W + off * 4);
        __half hv[4] = {__float2half_rn(v.x), __float2half_rn(v.y),
                        __float2half_rn(v.z), __float2half_rn(v.w)};
        *(uint2*)(g_wh + (size_t)which * NW * 4 + off * 4) = *(uint2*)hv;
    } else {
        int ei = g - NX - 4 * NW;
        float4 v = *(const float4*)(Er + ei * 4);
        __half hv[4] = {__float2half_rn(v.x), __float2half_rn(v.y),
                        __float2half_rn(v.z), __float2half_rn(v.w)};
        *(uint2*)(g_Eh + ei * 4) = *(uint2*)hv;
    }
}

// ---------------------------------------------------------------------------
// fp16 mma.sync GEMM, templated on term count:
//   TWO_TERM=1: C = (Ah+Al)*Bh^T   (QKV path)
//   TWO_TERM=0: C =  Ah    *Bh^T   (out-projection)
// 512 threads / 16 warps, 128x128 tile, warp 32x32, 3-stage cp.async, BK=32.
// ---------------------------------------------------------------------------
#define HSTR 40
#define MAT_HALVES (128*HSTR)
#define BUF_HALVES (3*MAT_HALVES)              // Ah, Al, Bh slots (Al unused if 1-term)
#define GSTAGES 3
#define GEMM_DYN_SMEM (GSTAGES*BUF_HALVES*2)   // 92160 B

template<int TWO_TERM>
__global__ __launch_bounds__(512, 1)
void gemm_f16_kernel(const __half* __restrict__ Ah, const __half* __restrict__ Al,
                     const __half* __restrict__ Bh,
                     const float* __restrict__ bias0, const float* __restrict__ bias1,
                     const float* __restrict__ bias2,
                     float* __restrict__ Cout, int mode)
{
    extern __shared__ __half sm[];

    const int tid  = threadIdx.x;
    const int wid  = tid >> 5;          // 0..15
    const int lane = tid & 31;
    const int warp_m = wid >> 2;        // 0..3
    const int warp_n = wid & 3;         // 0..3
    const int m0 = blockIdx.y * 128;
    const int n0 = blockIdx.x * 128;
    const int which = n0 >> 10;
    const int n0m = n0 & 1023;
    const float* biasm = (which == 0) ? bias0 : (which == 1) ? bias1 : bias2;

    float acc[2][4][4];
#pragma unroll
    for (int f = 0; f < 2; f++)
#pragma unroll
        for (int g = 0; g < 4; g++)
#pragma unroll
            for (int e = 0; e < 4; e++) acc[f][g][e] = 0.f;

    const int lrow = tid >> 2;          // 0..127
    const int lk   = (tid & 3) * 8;     // 0,8,16,24
    const uint32_t smb = smem_u32(sm);

    auto issue = [&](int c) {
        uint32_t bb = smb + (c % GSTAGES) * BUF_HALVES * 2;
        int kg = c * 32 + lk;
        uint32_t doff = (lrow * HSTR + lk) * 2;
        CPA16(bb + 0 * MAT_HALVES * 2 + doff, Ah + (size_t)(m0 + lrow) * 1024 + kg);
        if (TWO_TERM)
            CPA16(bb + 1 * MAT_HALVES * 2 + doff, Al + (size_t)(m0 + lrow) * 1024 + kg);
        CPA16(bb + 2 * MAT_HALVES * 2 + doff, Bh + (size_t)(n0 + lrow) * 1024 + kg);
        CP_COMMIT();
    };

    issue(0);
    issue(1);

    const int a_r   = lane & 15;
    const int a_kof = (lane >> 4) * 8;

    for (int c = 0; c < 32; c++) {
        if (c < 31) CP_WAIT1(); else CP_WAIT0();
        __syncthreads();
        if (c + 2 < 32) issue(c + 2);

        __half* cb = sm + (c % GSTAGES) * BUF_HALVES;
#pragma unroll
        for (int ks = 0; ks < 2; ks++) {
            uint32_t aH[2][4], aL[2][4], bH[2][4];
#pragma unroll
            for (int f = 0; f < 2; f++) {
                int row = warp_m * 32 + f * 16 + a_r;
                uint32_t addrH = smem_u32(&cb[0 * MAT_HALVES + row * HSTR + ks * 16 + a_kof]);
                LDMATRIX_X4(aH[f][0], aH[f][1], aH[f][2], aH[f][3], addrH);
                if (TWO_TERM) {
                    uint32_t addrL = smem_u32(&cb[1 * MAT_HALVES + row * HSTR + ks * 16 + a_kof]);
                    LDMATRIX_X4(aL[f][0], aL[f][1], aL[f][2], aL[f][3], addrL);
                }
            }
            ldmB(&cb[2 * MAT_HALVES], HSTR, warp_n * 32 +  0, ks * 16, lane, bH[0]);
            ldmB(&cb[2 * MAT_HALVES], HSTR, warp_n * 32 + 16, ks * 16, lane, bH[1]);
#pragma unroll
            for (int f = 0; f < 2; f++)
#pragma unroll
                for (int g = 0; g < 4; g++) {
                    const uint32_t* ph = &bH[g >> 1][(g & 1) * 2];
                    MMA_F16(acc[f][g], aH[f], ph);
                    if (TWO_TERM) MMA_F16(acc[f][g], aL[f], ph);
                }
        }
        __syncthreads();
    }

    if (mode == 0) {
        const float scale = (which == 0) ? 0.125f : 1.0f;
#pragma unroll
        for (int f = 0; f < 2; f++) {
            int mrow0 = m0 + warp_m * 32 + f * 16 + (lane >> 2);
#pragma unroll
            for (int g = 0; g < 4; g++) {
                int ncol = n0m + warp_n * 32 + g * 8 + (lane & 3) * 2;  // even
#pragma unroll
                for (int ep = 0; ep < 2; ep++) {
                    int m = mrow0 + ep * 8;
                    int b = m >> 10, s = m & 1023;
                    float v0 = (acc[f][g][2 * ep + 0] + biasm[ncol]) * scale;
                    float v1 = (acc[f][g][2 * ep + 1] + biasm[ncol + 1]) * scale;
                    if (which == 2) {
                        int h = ncol >> 6;
#pragma unroll
                        for (int e = 0; e < 2; e++) {
                            int d = (ncol + e) & 63;
                            float val = e ? v1 : v0;
                            size_t idx = ((size_t)(b * NH + h) * DK + d) * SEQ + s;
                            g_Vth[idx] = __float2half_rn(val);
                        }
                    } else if (which == 0) {
                        int h = ncol >> 6, d = ncol & 63;
                        uint32_t hp, lp;
                        split_h2(v0, v1, hp, lp);
                        size_t idx = ((size_t)(b * NH + h) * SEQ + s) * DK + d;
                        *(uint32_t*)&g_Qh[idx] = hp;
                        *(uint32_t*)&g_Ql[idx] = lp;
                    } else {
                        int h = ncol >> 6, d = ncol & 63;
                        __half2 kk = __floats2half2_rn(v0, v1);
                        size_t idx = ((size_t)(b * NH + h) * SEQ + s) * DK + d;
                        *(uint32_t*)&g_Kh[idx] = *(uint32_t*)&kk;
                    }
                }
            }
        }
    } else {
#pragma unroll
        for (int f = 0; f < 2; f++) {
            int mrow0 = m0 + warp_m * 32 + f * 16 + (lane >> 2);
#pragma unroll
            for (int g = 0; g < 4; g++) {
                int ncol = n0 + warp_n * 32 + g * 8 + (lane & 3) * 2;
#pragma unroll
                for (int ep = 0; ep < 2; ep++) {
                    int m = mrow0 + ep * 8;
                    float2 v = make_float2(acc[f][g][2 * ep] + biasm[ncol],
                                           acc[f][g][2 * ep + 1] + biasm[ncol + 1]);
                    *(float2*)&Cout[(size_t)m * D_MODEL + ncol] = v;
                }
            }
        }
    }
}

// ---------------------------------------------------------------------------
// Pipelined MMA flash-attention, fp16, rolling circular E buffer.
// S: 2-term (Qh+Ql)·K.  G: 1-term Qh·E (BD bias is small; correction ~1e-5).
// PV: 2-term (Ph+Pl)·V.  O stored hi-only.
// ---------------------------------------------------------------------------
#define ASTR  72
#define GBSTR 84
#define KV_STAGE_HALVES (2*64*ASTR)             // Kh + Vh
#define ST_KH 0
#define ST_VH (64*ASTR)
#define E_OFF_HALVES (2*KV_STAGE_HALVES)        // 18432
#define EH_OFF E_OFF_HALVES
#define G_OFF_HALVES (E_OFF_HALVES + 256*ASTR)  // 36864
#define ATTN_SMEM (G_OFF_HALVES*2 + 8*16*GBSTR*4)  // 116736 B

__device__ __forceinline__ void attn_issue_tile(
    uint32_t smb, int jt, int tid, int i0,
    const __half* Khg, const __half* Vhg)
{
    const int j0 = jt * 64;
    const uint32_t kvbase = smb + (jt & 1) * KV_STAGE_HALVES * 2;
    for (int t = tid; t < 512; t += 256) {
        int r = t >> 3, c8 = (t & 7) * 8;
        uint32_t doff = (r * ASTR + c8) * 2;
        CPA16(kvbase + ST_KH * 2 + doff, Khg + (size_t)(j0 + r) * DK + c8);
        CPA16(kvbase + ST_VH * 2 + doff, Vhg + (size_t)r * SEQ + j0 + c8);
    }
    const int rlo = (SEQ - 1) + i0 - j0 - 63;
    const int cnt8 = (jt == 0) ? 1536 : 512;
    for (int t = tid; t < cnt8; t += 256) {
        int r = t >> 3, c8 = (t & 7) * 8;
        int er = rlo + r;
        int ers = (er > ELEN - 1) ? (ELEN - 1) : er;
        uint32_t phys = (uint32_t)er & 255u;
        uint32_t doff = (phys * ASTR + c8) * 2;
        CPA16(smb + EH_OFF * 2 + doff, g_Eh + (size_t)ers * DK + c8);
    }
    CP_COMMIT();
}

__global__ __launch_bounds__(256)
void attn_mma_kernel()
{
    extern __shared__ __half smh[];
    float* sG = (float*)(smh + G_OFF_HALVES);
    __half* sQh = (__half*)sG;                 // staging overlay
    __half* sQl = sQh + 128 * ASTR;
    __half* sEh = smh + EH_OFF;

    const int tid  = threadIdx.x;
    const int lane = tid & 31;
    const int w    = tid >> 5;
    const int bh = blockIdx.y;
    const int i0 = blockIdx.x * 128;
    const int b = bh >> 4, h = bh & 15;

    const __half* Qhg = g_Qh + (size_t)bh * SEQ * DK;
    const __half* Qlg = g_Ql + (size_t)bh * SEQ * DK;
    const __half* Khg = g_Kh + (size_t)bh * SEQ * DK;
    const __half* Vhg = g_Vth + (size_t)bh * DK * SEQ;
    const uint32_t smb = smem_u32(smh);

    for (int t = tid; t < 1024; t += 256) {
        int r = t >> 3, c8 = (t & 7) * 8;
        *(uint4*)&sQh[r * ASTR + c8] = *(const uint4*)(Qhg + (size_t)(i0 + r) * DK + c8);
        *(uint4*)&sQl[r * ASTR + c8] = *(const uint4*)(Qlg + (size_t)(i0 + r) * DK + c8);
    }
    __syncthreads();
    uint32_t qh[4][4], ql[4][4];
#pragma unroll
    for (int ks = 0; ks < 4; ks++) {
        uint32_t aH = smem_u32(&sQh[(w * 16 + (lane & 15)) * ASTR + ks * 16 + (lane >> 4) * 8]);
        LDMATRIX_X4(qh[ks][0], qh[ks][1], qh[ks][2], qh[ks][3], aH);
        uint32_t aL = smem_u32(&sQl[(w * 16 + (lane & 15)) * ASTR + ks * 16 + (lane >> 4) * 8]);
        LDMATRIX_X4(ql[ks][0], ql[ks][1], ql[ks][2], ql[ks][3], aL);
    }
    __syncthreads();

    attn_issue_tile(smb, 0, tid, i0, Khg, Vhg);

    float accO[8][4];
#pragma unroll
    for (int nf = 0; nf < 8; nf++)
#pragma unroll
        for (int e = 0; e < 4; e++) accO[nf][e] = 0.f;
    float rmax0 = -1e30f, rmax1 = -1e30f, rsum0 = 0.f, rsum1 = 0.f;

    const int r0 = lane >> 2;
    const int c0 = (lane & 3) * 2;
    float* sGw = sG + w * 16 * GBSTR;

    for (int jt = 0; jt < 16; jt++) {
        if (jt < 15) {
            attn_issue_tile(smb, jt + 1, tid, i0, Khg, Vhg);
            CP_WAIT1();
        } else {
            CP_WAIT0();
        }
        __syncthreads();

        __half* st = smh + (jt & 1) * KV_STAGE_HALVES;
        __half* sKh = st + ST_KH;
        __half* sVh = st + ST_VH;

        const int rbase = (SEQ - 1) + i0 - jt * 64 - 63;
        const int rb255 = rbase & 255;

        // ---- G = Qh * Eband^T (1-term), band-limited: nf in [2w, 2w+10) ----
        float gac[10][4];
#pragma unroll
        for (int bi = 0; bi < 10; bi++)
#pragma unroll
            for (int e = 0; e < 4; e++) gac[bi][e] = 0.f;
#pragma unroll
        for (int ks = 0; ks < 4; ks++) {
#pragma unroll
            for (int bp = 0; bp < 5; bp++) {
                uint32_t eh4[4];
                int row0 = (rb255 + (2 * w + 2 * bp) * 8) & 255;
                ldmB(sEh, ASTR, row0, ks * 16, lane, eh4);
                MMA_F16(gac[2 * bp], qh[ks], eh4);
                MMA_F16(gac[2 * bp + 1], qh[ks], eh4 + 2);
            }
        }
#pragma unroll
        for (int bi = 0; bi < 10; bi++) {
            *(float2*)&sGw[r0 * GBSTR + bi * 8 + c0] = make_float2(gac[bi][0], gac[bi][1]);
            *(float2*)&sGw[(r0 + 8) * GBSTR + bi * 8 + c0] = make_float2(gac[bi][2], gac[bi][3]);
        }

        // ---- S = Q * K^T (2-term) ----
        float s[8][4];
#pragma unroll
        for (int nf = 0; nf < 8; nf++)
#pragma unroll
            for (int e = 0; e < 4; e++) s[nf][e] = 0.f;
#pragma unroll
        for (int ks = 0; ks < 4; ks++) {
#pragma unroll
            for (int gp = 0; gp < 4; gp++) {
                uint32_t kh4[4];
                ldmB(sKh, ASTR, gp * 16, ks * 16, lane, kh4);
                MMA_F16(s[2 * gp], qh[ks], kh4);
                MMA_F16(s[2 * gp], ql[ks], kh4);
                MMA_F16(s[2 * gp + 1], qh[ks], kh4 + 2);
                MMA_F16(s[2 * gp + 1], ql[ks], kh4 + 2);
            }
        }
        __syncwarp();

        // ---- gather BD from G band and add ----
#pragma unroll
        for (int nf = 0; nf < 8; nf++)
#pragma unroll
            for (int e = 0; e < 4; e++) {
                int iw = r0 + ((e >> 1) << 3);
                int jl = nf * 8 + c0 + (e & 1);
                s[nf][e] += sGw[iw * GBSTR + (iw - jl + 63)];
            }

        // ---- online softmax ----
        float mx0 = -1e30f, mx1 = -1e30f;
#pragma unroll
        for (int nf = 0; nf < 8; nf++) {
            mx0 = fmaxf(mx0, fmaxf(s[nf][0], s[nf][1]));
            mx1 = fmaxf(mx1, fmaxf(s[nf][2], s[nf][3]));
        }
#pragma unroll
        for (int o = 1; o <= 2; o <<= 1) {
            mx0 = fmaxf(mx0, __shfl_xor_sync(0xffffffffu, mx0, o));
            mx1 = fmaxf(mx1, __shfl_xor_sync(0xffffffffu, mx1, o));
        }
        float nm0 = fmaxf(rmax0, mx0), nm1 = fmaxf(rmax1, mx1);
        float al0 = __expf(rmax0 - nm0), al1 = __expf(rmax1 - nm1);
        rmax0 = nm0; rmax1 = nm1;
        float ls0 = 0.f, ls1 = 0.f;
#pragma unroll
        for (int nf = 0; nf < 8; nf++) {
            s[nf][0] = __expf(s[nf][0] - nm0);
            s[nf][1] = __expf(s[nf][1] - nm0);
            s[nf][2] = __expf(s[nf][2] - nm1);
            s[nf][3] = __expf(s[nf][3] - nm1);
            ls0 += s[nf][0] + s[nf][1];
            ls1 += s[nf][2] + s[nf][3];
        }
#pragma unroll
        for (int o = 1; o <= 2; o <<= 1) {
            ls0 += __shfl_xor_sync(0xffffffffu, ls0, o);
            ls1 += __shfl_xor_sync(0xffffffffu, ls1, o);
        }
        rsum0 = rsum0 * al0 + ls0;
        rsum1 = rsum1 * al1 + ls1;
#pragma unroll
        for (int nf = 0; nf < 8; nf++) {
            accO[nf][0] *= al0; accO[nf][1] *= al0;
            accO[nf][2] *= al1; accO[nf][3] *= al1;
        }

        // ---- pack P fragments (hi + residual-lo) ----
        uint32_t ph[4][4], pl[4][4];
#pragma unroll
        for (int ks = 0; ks < 4; ks++) {
            int f0 = 2 * ks, f1 = 2 * ks + 1;
            float rlo2[8];
#pragma unroll
            for (int e = 0; e < 4; e++) {
                rlo2[e]     = s[f0][e] - __half2float(__float2half_rn(s[f0][e]));
                rlo2[4 + e] = s[f1][e] - __half2float(__float2half_rn(s[f1][e]));
            }
            ph[ks][0] = pack_h2(s[f0][0], s[f0][1]);
            ph[ks][1] = pack_h2(s[f0][2], s[f0][3]);
            ph[ks][2] = pack_h2(s[f1][0], s[f1][1]);
            ph[ks][3] = pack_h2(s[f1][2], s[f1][3]);
            pl[ks][0] = pack_h2(rlo2[0], rlo2[1]);
            pl[ks][1] = pack_h2(rlo2[2], rlo2[3]);
            pl[ks][2] = pack_h2(rlo2[4], rlo2[5]);
            pl[ks][3] = pack_h2(rlo2[6], rlo2[7]);
        }

        // ---- O += P * V (2-term) ----
#pragma unroll
        for (int ks = 0; ks < 4; ks++) {
#pragma unroll
            for (int gp = 0; gp < 4; gp++) {
                uint32_t vh4[4];
                ldmB(sVh, ASTR, gp * 16, ks * 16, lane, vh4);
                MMA_F16(accO[2 * gp], ph[ks], vh4);
                MMA_F16(accO[2 * gp], pl[ks], vh4);
                MMA_F16(accO[2 * gp + 1], ph[ks], vh4 + 2);
                MMA_F16(accO[2 * gp + 1], pl[ks], vh4 + 2);
            }
        }
        __syncthreads();
    }

    // ---- epilogue: hi-only vectorized stores ----
    float inv0 = 1.0f / rsum0, inv1 = 1.0f / rsum1;
#pragma unroll
    for (int nf = 0; nf < 8; nf++)
#pragma unroll
        for (int ep = 0; ep < 2; ep++) {
            int i = i0 + w * 16 + r0 + ep * 8;
            int d = nf * 8 + c0;
            float inv = ep ? inv1 : inv0;
            __half2 hh = __floats2half2_rn(accO[nf][2 * ep + 0] * inv,
                                           accO[nf][2 * ep + 1] * inv);
            size_t idx = ((size_t)(b * SEQ + i)) * D_MODEL + h * DK + d;
            *(uint32_t*)&g_oh[idx] = *(uint32_t*)&hh;
        }
}

// ---------------------------------------------------------------------------
extern "C" void kernel_launch(void* const* d_in, const int* in_sizes, int n_in,
                              void* d_out, int out_size)
{
    const float* x  = (const float*)d_in[0];
    const float* Wq = (const float*)d_in[1];
    const float* bq = (const float*)d_in[2];
    const float* Wk = (const float*)d_in[3];
    const float* bk = (const float*)d_in[4];
    const float* Wv = (const float*)d_in[5];
    const float* bv = (const float*)d_in[6];
    const float* Wo = (const float*)d_in[7];
    const float* bo = (const float*)d_in[8];
    const float* Er = (const float*)d_in[9];
    float* out = (float*)d_out;

    cudaFuncSetAttribute(gemm_f16_kernel<1>,
                         cudaFuncAttributeMaxDynamicSharedMemorySize, GEMM_DYN_SMEM);
    cudaFuncSetAttribute(gemm_f16_kernel<0>,
                         cudaFuncAttributeMaxDynamicSharedMemorySize, GEMM_DYN_SMEM);
    cudaFuncSetAttribute(attn_mma_kernel,
                         cudaFuncAttributeMaxDynamicSharedMemorySize, ATTN_SMEM);

    __half *xh, *xl, *wh, *oh;
    cudaGetSymbolAddress((void**)&xh, g_xh);
    cudaGetSymbolAddress((void**)&xl, g_xl);
    cudaGetSymbolAddress((void**)&wh, g_wh);
    cudaGetSymbolAddress((void**)&oh, g_oh);

    // 0) convert: x split fp16; weights & Er hi-only fp16
    {
        int total = (MTOT * D_MODEL + 4 * D_MODEL * D_MODEL + ELEN * DK) / 4;
        convert_xw_kernel<<<(total + 255) / 256, 256>>>(x, Wq, Wk, Wv, Wo, Er);
    }
    // 1) fused QKV projection (2-term) -> Q split, K hi, V^T hi
    {
        dim3 grid(3072 / 128, MTOT / 128);
        gemm_f16_kernel<1><<<grid, 512, GEMM_DYN_SMEM>>>(
            xh, xl, wh, bq, bk, bv, nullptr, 0);
    }
    // 2) pipelined MMA attention -> O hi
    {
        dim3 grid(SEQ / 128, BHT);           // 8 x 32
        attn_mma_kernel<<<grid, 256, ATTN_SMEM>>>();
    }
    // 3) output projection (1-term) -> out
    {
        dim3 grid(D_MODEL / 128, MTOT / 128);
        gemm_f16_kernel<0><<<grid, 512, GEMM_DYN_SMEM>>>(
            oh, oh, wh + (size_t)3 * D_MODEL * D_MODEL,
            bo, bo, bo, out, 1);
    }
}

// round 16
// speedup vs baseline: 1.7642x; 1.0492x over previous
#include <cuda_runtime.h>
#include <cuda_fp16.h>
#include <math.h>
#include <stdint.h>

#define D_MODEL 1024
#define NH      16
#define DK      64
#define BATCH   2
#define SEQ     1024
#define BHT     (BATCH*NH)          // 32
#define MTOT    (BATCH*SEQ)         // 2048
#define ELEN    (2*SEQ-1)           // 2047

// ---------------- scratch (device globals; no allocation allowed) ----------
__device__ __half g_xh[MTOT*D_MODEL];
__device__ __half g_xl[MTOT*D_MODEL];
__device__ __half g_wh[4*D_MODEL*D_MODEL];   // Wq|Wk|Wv|Wo (hi only)
__device__ __half g_oh[MTOT*D_MODEL];        // attention out (hi only)

__device__ __half g_Qh[BHT*SEQ*DK];   // [bh][s][d], pre-scaled 1/8 (split)
__device__ __half g_Ql[BHT*SEQ*DK];
__device__ __half g_Kh[BHT*SEQ*DK];   // hi only
__device__ __half g_Vth[BHT*DK*SEQ];  // [bh][d][s]  transposed, hi only
__device__ __half g_Eh[ELEN*DK];      // hi only

// ---------------- helpers ---------------------------------------------------
__device__ __forceinline__ uint32_t smem_u32(const void* p) {
    uint32_t a;
    asm("{ .reg .u64 t; cvta.to.shared.u64 t, %1; cvt.u32.u64 %0, t; }"
        : "=r"(a) : "l"(p));
    return a;
}

#define CPA16(dst_u32, src_ptr) \
    asm volatile("cp.async.ca.shared.global [%0], [%1], 16;" \
                 :: "r"(dst_u32), "l"(src_ptr) : "memory")
#define CP_COMMIT() asm volatile("cp.async.commit_group;" ::: "memory")
#define CP_WAIT0()  asm volatile("cp.async.wait_group 0;" ::: "memory")
#define CP_WAIT1()  asm volatile("cp.async.wait_group 1;" ::: "memory")

#define LDMATRIX_X4(r0, r1, r2, r3, addr) \
    asm("ldmatrix.sync.aligned.m8n8.x4.shared.b16 {%0,%1,%2,%3}, [%4];" \
        : "=r"(r0), "=r"(r1), "=r"(r2), "=r"(r3) : "r"(addr))

#define MMA_F16(c, a, b) \
    asm("mma.sync.aligned.m16n8k16.row.col.f32.f16.f16.f32 " \
        "{%0,%1,%2,%3}, {%4,%5,%6,%7}, {%8,%9}, {%0,%1,%2,%3};" \
        : "+f"((c)[0]), "+f"((c)[1]), "+f"((c)[2]), "+f"((c)[3]) \
        : "r"((a)[0]), "r"((a)[1]), "r"((a)[2]), "r"((a)[3]), \
          "r"((b)[0]), "r"((b)[1]))

// Load B-fragments for TWO n-frags with one ldmatrix.x4.
__device__ __forceinline__ void ldmB(const __half* base, int stride,
                                     int row0, int kcol, int lane, uint32_t* r)
{
    int sel = (lane >> 4) & 1;
    int row = row0 + sel * 8 + (lane & 7);
    int col = kcol + ((lane >> 3) & 1) * 8;
    uint32_t a = smem_u32(base + row * stride + col);
    LDMATRIX_X4(r[0], r[1], r[2], r[3], a);
}

__device__ __forceinline__ uint32_t pack_h2(float lo, float hi) {
    __half2 t = __floats2half2_rn(lo, hi);
    return *(uint32_t*)&t;
}
__device__ __forceinline__ void split_h(float v, __half& h, __half& l) {
    h = __float2half_rn(v);
    l = __float2half_rn(v - __half2float(h));
}
__device__ __forceinline__ void split_h2(float v0, float v1,
                                         uint32_t& hp, uint32_t& lp) {
    __half h0, l0, h1, l1;
    split_h(v0, h0, l0);
    split_h(v1, h1, l1);
    __half2 hh; hh.x = h0; hh.y = h1;
    __half2 ll; ll.x = l0; ll.y = l1;
    hp = *(uint32_t*)&hh;
    lp = *(uint32_t*)&ll;
}

// ---------------------------------------------------------------------------
// fp32 -> fp16 conversion: x split hi/lo; weights & Er hi only.
// ---------------------------------------------------------------------------
__global__ void convert_xw_kernel(const float* __restrict__ x,
                                  const float* __restrict__ Wq, const float* __restrict__ Wk,
                                  const float* __restrict__ Wv, const float* __restrict__ Wo,
                                  const float* __restrict__ Er)
{
    const int NX = MTOT * D_MODEL / 4;
    const int NW = D_MODEL * D_MODEL / 4;
    const int NE = ELEN * DK / 4;
    int g = blockIdx.x * blockDim.x + threadIdx.x;
    if (g >= NX + 4 * NW + NE) return;
    if (g < NX) {
        float4 v = *(const float4*)(x + g * 4);
        __half hv[4], lv[4];
        split_h(v.x, hv[0], lv[0]); split_h(v.y, hv[1], lv[1]);
        split_h(v.z, hv[2], lv[2]); split_h(v.w, hv[3], lv[3]);
        *(uint2*)(g_xh + g * 4) = *(uint2*)hv;
        *(uint2*)(g_xl + g * 4) = *(uint2*)lv;
    } else if (g < NX + 4 * NW) {
        int wi = g - NX;
        int which = wi / NW;
        int off = wi - which * NW;
        const float* W = (which == 0) ? Wq : (which == 1) ? Wk : (which == 2) ? Wv : Wo;
        float4 v = *(const float4*)(W + off * 4);
        __half hv[4] = {__float2half_rn(v.x), __float2half_rn(v.y),
                        __float2half_rn(v.z), __float2half_rn(v.w)};
        *(uint2*)(g_wh + (size_t)which * NW * 4 + off * 4) = *(uint2*)hv;
    } else {
        int ei = g - NX - 4 * NW;
        float4 v = *(const float4*)(Er + ei * 4);
        __half hv[4] = {__float2half_rn(v.x), __float2half_rn(v.y),
                        __float2half_rn(v.z), __float2half_rn(v.w)};
        *(uint2*)(g_Eh + ei * 4) = *(uint2*)hv;
    }
}

// ---------------------------------------------------------------------------
// fp16 mma.sync GEMM, templated on term count:
//   TWO_TERM=1: C = (Ah+Al)*Bh^T for Q/K; V (which==2) uses 1-term Ah*Bh^T
//   TWO_TERM=0: C =  Ah    *Bh^T   (out-projection)
// 512 threads / 16 warps, 128x128 tile, warp 32x32, 3-stage cp.async, BK=32.
// ---------------------------------------------------------------------------
#define HSTR 40
#define MAT_HALVES (128*HSTR)
#define BUF_HALVES (3*MAT_HALVES)
#define GSTAGES 3
#define GEMM_DYN_SMEM (GSTAGES*BUF_HALVES*2)   // 92160 B

template<int TWO_TERM>
__global__ __launch_bounds__(512, 1)
void gemm_f16_kernel(const __half* __restrict__ Ah, const __half* __restrict__ Al,
                     const __half* __restrict__ Bh,
                     const float* __restrict__ bias0, const float* __restrict__ bias1,
                     const float* __restrict__ bias2,
                     float* __restrict__ Cout, int mode)
{
    extern __shared__ __half sm[];

    const int tid  = threadIdx.x;
    const int wid  = tid >> 5;          // 0..15
    const int lane = tid & 31;
    const int warp_m = wid >> 2;        // 0..3
    const int warp_n = wid & 3;         // 0..3
    const int m0 = blockIdx.y * 128;
    const int n0 = blockIdx.x * 128;
    const int which = n0 >> 10;
    const int n0m = n0 & 1023;
    const float* biasm = (which == 0) ? bias0 : (which == 1) ? bias1 : bias2;
    // V projection (which==2) tolerates 1-term (error path is linear).
    const bool useAl = TWO_TERM && (which != 2);

    float acc[2][4][4];
#pragma unroll
    for (int f = 0; f < 2; f++)
#pragma unroll
        for (int g = 0; g < 4; g++)
#pragma unroll
            for (int e = 0; e < 4; e++) acc[f][g][e] = 0.f;

    const int lrow = tid >> 2;          // 0..127
    const int lk   = (tid & 3) * 8;     // 0,8,16,24
    const uint32_t smb = smem_u32(sm);

    auto issue = [&](int c) {
        uint32_t bb = smb + (c % GSTAGES) * BUF_HALVES * 2;
        int kg = c * 32 + lk;
        uint32_t doff = (lrow * HSTR + lk) * 2;
        CPA16(bb + 0 * MAT_HALVES * 2 + doff, Ah + (size_t)(m0 + lrow) * 1024 + kg);
        if (useAl)
            CPA16(bb + 1 * MAT_HALVES * 2 + doff, Al + (size_t)(m0 + lrow) * 1024 + kg);
        CPA16(bb + 2 * MAT_HALVES * 2 + doff, Bh + (size_t)(n0 + lrow) * 1024 + kg);
        CP_COMMIT();
    };

    issue(0);
    issue(1);

    const int a_r   = lane & 15;
    const int a_kof = (lane >> 4) * 8;

    for (int c = 0; c < 32; c++) {
        if (c < 31) CP_WAIT1(); else CP_WAIT0();
        __syncthreads();
        if (c + 2 < 32) issue(c + 2);

        __half* cb = sm + (c % GSTAGES) * BUF_HALVES;
#pragma unroll
        for (int ks = 0; ks < 2; ks++) {
            uint32_t aH[2][4], aL[2][4], bH[2][4];
#pragma unroll
            for (int f = 0; f < 2; f++) {
                int row = warp_m * 32 + f * 16 + a_r;
                uint32_t addrH = smem_u32(&cb[0 * MAT_HALVES + row * HSTR + ks * 16 + a_kof]);
                LDMATRIX_X4(aH[f][0], aH[f][1], aH[f][2], aH[f][3], addrH);
                if (useAl) {
                    uint32_t addrL = smem_u32(&cb[1 * MAT_HALVES + row * HSTR + ks * 16 + a_kof]);
                    LDMATRIX_X4(aL[f][0], aL[f][1], aL[f][2], aL[f][3], addrL);
                }
            }
            ldmB(&cb[2 * MAT_HALVES], HSTR, warp_n * 32 +  0, ks * 16, lane, bH[0]);
            ldmB(&cb[2 * MAT_HALVES], HSTR, warp_n * 32 + 16, ks * 16, lane, bH[1]);
#pragma unroll
            for (int f = 0; f < 2; f++)
#pragma unroll
                for (int g = 0; g < 4; g++) {
                    const uint32_t* ph = &bH[g >> 1][(g & 1) * 2];
                    MMA_F16(acc[f][g], aH[f], ph);
                    if (useAl) MMA_F16(acc[f][g], aL[f], ph);
                }
        }
        __syncthreads();
    }

    if (mode == 0) {
        const float scale = (which == 0) ? 0.125f : 1.0f;
#pragma unroll
        for (int f = 0; f < 2; f++) {
            int mrow0 = m0 + warp_m * 32 + f * 16 + (lane >> 2);
#pragma unroll
            for (int g = 0; g < 4; g++) {
                int ncol = n0m + warp_n * 32 + g * 8 + (lane & 3) * 2;  // even
#pragma unroll
                for (int ep = 0; ep < 2; ep++) {
                    int m = mrow0 + ep * 8;
                    int b = m >> 10, s = m & 1023;
                    float v0 = (acc[f][g][2 * ep + 0] + biasm[ncol]) * scale;
                    float v1 = (acc[f][g][2 * ep + 1] + biasm[ncol + 1]) * scale;
                    if (which == 2) {
                        int h = ncol >> 6;
#pragma unroll
                        for (int e = 0; e < 2; e++) {
                            int d = (ncol + e) & 63;
                            float val = e ? v1 : v0;
                            size_t idx = ((size_t)(b * NH + h) * DK + d) * SEQ + s;
                            g_Vth[idx] = __float2half_rn(val);
                        }
                    } else if (which == 0) {
                        int h = ncol >> 6, d = ncol & 63;
                        uint32_t hp, lp;
                        split_h2(v0, v1, hp, lp);
                        size_t idx = ((size_t)(b * NH + h) * SEQ + s) * DK + d;
                        *(uint32_t*)&g_Qh[idx] = hp;
                        *(uint32_t*)&g_Ql[idx] = lp;
                    } else {
                        int h = ncol >> 6, d = ncol & 63;
                        __half2 kk = __floats2half2_rn(v0, v1);
                        size_t idx = ((size_t)(b * NH + h) * SEQ + s) * DK + d;
                        *(uint32_t*)&g_Kh[idx] = *(uint32_t*)&kk;
                    }
                }
            }
        }
    } else {
#pragma unroll
        for (int f = 0; f < 2; f++) {
            int mrow0 = m0 + warp_m * 32 + f * 16 + (lane >> 2);
#pragma unroll
            for (int g = 0; g < 4; g++) {
                int ncol = n0 + warp_n * 32 + g * 8 + (lane & 3) * 2;
#pragma unroll
                for (int ep = 0; ep < 2; ep++) {
                    int m = mrow0 + ep * 8;
                    float2 v = make_float2(acc[f][g][2 * ep] + biasm[ncol],
                                           acc[f][g][2 * ep + 1] + biasm[ncol + 1]);
                    *(float2*)&Cout[(size_t)m * D_MODEL + ncol] = v;
                }
            }
        }
    }
}

// ---------------------------------------------------------------------------
// Pipelined MMA flash-attention, fp16, rolling circular E buffer.
// S: 2-term (Qh+Ql)·K.  G: 1-term Qh·E.  PV: 1-term Ph·V.  O hi-only.
// ---------------------------------------------------------------------------
#define ASTR  72
#define GBSTR 84
#define KV_STAGE_HALVES (2*64*ASTR)             // Kh + Vh
#define ST_KH 0
#define ST_VH (64*ASTR)
#define E_OFF_HALVES (2*KV_STAGE_HALVES)        // 18432
#define EH_OFF E_OFF_HALVES
#define G_OFF_HALVES (E_OFF_HALVES + 256*ASTR)  // 36864
#define ATTN_SMEM (G_OFF_HALVES*2 + 8*16*GBSTR*4)  // 116736 B

__device__ __forceinline__ void attn_issue_tile(
    uint32_t smb, int jt, int tid, int i0,
    const __half* Khg, const __half* Vhg)
{
    const int j0 = jt * 64;
    const uint32_t kvbase = smb + (jt & 1) * KV_STAGE_HALVES * 2;
    for (int t = tid; t < 512; t += 256) {
        int r = t >> 3, c8 = (t & 7) * 8;
        uint32_t doff = (r * ASTR + c8) * 2;
        CPA16(kvbase + ST_KH * 2 + doff, Khg + (size_t)(j0 + r) * DK + c8);
        CPA16(kvbase + ST_VH * 2 + doff, Vhg + (size_t)r * SEQ + j0 + c8);
    }
    const int rlo = (SEQ - 1) + i0 - j0 - 63;
    const int cnt8 = (jt == 0) ? 1536 : 512;
    for (int t = tid; t < cnt8; t += 256) {
        int r = t >> 3, c8 = (t & 7) * 8;
        int er = rlo + r;
        int ers = (er > ELEN - 1) ? (ELEN - 1) : er;
        uint32_t phys = (uint32_t)er & 255u;
        uint32_t doff = (phys * ASTR + c8) * 2;
        CPA16(smb + EH_OFF * 2 + doff, g_Eh + (size_t)ers * DK + c8);
    }
    CP_COMMIT();
}

__global__ __launch_bounds__(256)
void attn_mma_kernel()
{
    extern __shared__ __half smh[];
    float* sG = (float*)(smh + G_OFF_HALVES);
    __half* sQh = (__half*)sG;                 // staging overlay
    __half* sQl = sQh + 128 * ASTR;
    __half* sEh = smh + EH_OFF;

    const int tid  = threadIdx.x;
    const int lane = tid & 31;
    const int w    = tid >> 5;
    const int bh = blockIdx.y;
    const int i0 = blockIdx.x * 128;
    const int b = bh >> 4, h = bh & 15;

    const __half* Qhg = g_Qh + (size_t)bh * SEQ * DK;
    const __half* Qlg = g_Ql + (size_t)bh * SEQ * DK;
    const __half* Khg = g_Kh + (size_t)bh * SEQ * DK;
    const __half* Vhg = g_Vth + (size_t)bh * DK * SEQ;
    const uint32_t smb = smem_u32(smh);

    for (int t = tid; t < 1024; t += 256) {
        int r = t >> 3, c8 = (t & 7) * 8;
        *(uint4*)&sQh[r * ASTR + c8] = *(const uint4*)(Qhg + (size_t)(i0 + r) * DK + c8);
        *(uint4*)&sQl[r * ASTR + c8] = *(const uint4*)(Qlg + (size_t)(i0 + r) * DK + c8);
    }
    __syncthreads();
    uint32_t qh[4][4], ql[4][4];
#pragma unroll
    for (int ks = 0; ks < 4; ks++) {
        uint32_t aH = smem_u32(&sQh[(w * 16 + (lane & 15)) * ASTR + ks * 16 + (lane >> 4) * 8]);
        LDMATRIX_X4(qh[ks][0], qh[ks][1], qh[ks][2], qh[ks][3], aH);
        uint32_t aL = smem_u32(&sQl[(w * 16 + (lane & 15)) * ASTR + ks * 16 + (lane >> 4) * 8]);
        LDMATRIX_X4(ql[ks][0], ql[ks][1], ql[ks][2], ql[ks][3], aL);
    }
    __syncthreads();

    attn_issue_tile(smb, 0, tid, i0, Khg, Vhg);

    float accO[8][4];
#pragma unroll
    for (int nf = 0; nf < 8; nf++)
#pragma unroll
        for (int e = 0; e < 4; e++) accO[nf][e] = 0.f;
    float rmax0 = -1e30f, rmax1 = -1e30f, rsum0 = 0.f, rsum1 = 0.f;

    const int r0 = lane >> 2;
    const int c0 = (lane & 3) * 2;
    float* sGw = sG + w * 16 * GBSTR;

    for (int jt = 0; jt < 16; jt++) {
        if (jt < 15) {
            attn_issue_tile(smb, jt + 1, tid, i0, Khg, Vhg);
            CP_WAIT1();
        } else {
            CP_WAIT0();
        }
        __syncthreads();

        __half* st = smh + (jt & 1) * KV_STAGE_HALVES;
        __half* sKh = st + ST_KH;
        __half* sVh = st + ST_VH;

        const int rbase = (SEQ - 1) + i0 - jt * 64 - 63;
        const int rb255 = rbase & 255;

        // ---- G = Qh * Eband^T (1-term), band-limited: nf in [2w, 2w+10) ----
        float gac[10][4];
#pragma unroll
        for (int bi = 0; bi < 10; bi++)
#pragma unroll
            for (int e = 0; e < 4; e++) gac[bi][e] = 0.f;
#pragma unroll
        for (int ks = 0; ks < 4; ks++) {
#pragma unroll
            for (int bp = 0; bp < 5; bp++) {
                uint32_t eh4[4];
                int row0 = (rb255 + (2 * w + 2 * bp) * 8) & 255;
                ldmB(sEh, ASTR, row0, ks * 16, lane, eh4);
                MMA_F16(gac[2 * bp], qh[ks], eh4);
                MMA_F16(gac[2 * bp + 1], qh[ks], eh4 + 2);
            }
        }
#pragma unroll
        for (int bi = 0; bi < 10; bi++) {
            *(float2*)&sGw[r0 * GBSTR + bi * 8 + c0] = make_float2(gac[bi][0], gac[bi][1]);
            *(float2*)&sGw[(r0 + 8) * GBSTR + bi * 8 + c0] = make_float2(gac[bi][2], gac[bi][3]);
        }

        // ---- S = Q * K^T (2-term) ----
        float s[8][4];
#pragma unroll
        for (int nf = 0; nf < 8; nf++)
#pragma unroll
            for (int e = 0; e < 4; e++) s[nf][e] = 0.f;
#pragma unroll
        for (int ks = 0; ks < 4; ks++) {
#pragma unroll
            for (int gp = 0; gp < 4; gp++) {
                uint32_t kh4[4];
                ldmB(sKh, ASTR, gp * 16, ks * 16, lane, kh4);
                MMA_F16(s[2 * gp], qh[ks], kh4);
                MMA_F16(s[2 * gp], ql[ks], kh4);
                MMA_F16(s[2 * gp + 1], qh[ks], kh4 + 2);
                MMA_F16(s[2 * gp + 1], ql[ks], kh4 + 2);
            }
        }
        __syncwarp();

        // ---- gather BD from G band and add ----
#pragma unroll
        for (int nf = 0; nf < 8; nf++)
#pragma unroll
            for (int e = 0; e < 4; e++) {
                int iw = r0 + ((e >> 1) << 3);
                int jl = nf * 8 + c0 + (e & 1);
                s[nf][e] += sGw[iw * GBSTR + (iw - jl + 63)];
            }

        // ---- online softmax ----
        float mx0 = -1e30f, mx1 = -1e30f;
#pragma unroll
        for (int nf = 0; nf < 8; nf++) {
            mx0 = fmaxf(mx0, fmaxf(s[nf][0], s[nf][1]));
            mx1 = fmaxf(mx1, fmaxf(s[nf][2], s[nf][3]));
        }
#pragma unroll
        for (int o = 1; o <= 2; o <<= 1) {
            mx0 = fmaxf(mx0, __shfl_xor_sync(0xffffffffu, mx0, o));
            mx1 = fmaxf(mx1, __shfl_xor_sync(0xffffffffu, mx1, o));
        }
        float nm0 = fmaxf(rmax0, mx0), nm1 = fmaxf(rmax1, mx1);
        float al0 = __expf(rmax0 - nm0), al1 = __expf(rmax1 - nm1);
        rmax0 = nm0; rmax1 = nm1;
        float ls0 = 0.f, ls1 = 0.f;
#pragma unroll
        for (int nf = 0; nf < 8; nf++) {
            s[nf][0] = __expf(s[nf][0] - nm0);
            s[nf][1] = __expf(s[nf][1] - nm0);
            s[nf][2] = __expf(s[nf][2] - nm1);
            s[nf][3] = __expf(s[nf][3] - nm1);
            ls0 += s[nf][0] + s[nf][1];
            ls1 += s[nf][2] + s[nf][3];
        }
#pragma unroll
        for (int o = 1; o <= 2; o <<= 1) {
            ls0 += __shfl_xor_sync(0xffffffffu, ls0, o);
            ls1 += __shfl_xor_sync(0xffffffffu, ls1, o);
        }
        rsum0 = rsum0 * al0 + ls0;
        rsum1 = rsum1 * al1 + ls1;
#pragma unroll
        for (int nf = 0; nf < 8; nf++) {
            accO[nf][0] *= al0; accO[nf][1] *= al0;
            accO[nf][2] *= al1; accO[nf][3] *= al1;
        }

        // ---- pack P fragments (hi only) ----
        uint32_t ph[4][4];
#pragma unroll
        for (int ks = 0; ks < 4; ks++) {
            int f0 = 2 * ks, f1 = 2 * ks + 1;
            ph[ks][0] = pack_h2(s[f0][0], s[f0][1]);
            ph[ks][1] = pack_h2(s[f0][2], s[f0][3]);
            ph[ks][2] = pack_h2(s[f1][0], s[f1][1]);
            ph[ks][3] = pack_h2(s[f1][2], s[f1][3]);
        }

        // ---- O += P * V (1-term) ----
#pragma unroll
        for (int ks = 0; ks < 4; ks++) {
#pragma unroll
            for (int gp = 0; gp < 4; gp++) {
                uint32_t vh4[4];
                ldmB(sVh, ASTR, gp * 16, ks * 16, lane, vh4);
                MMA_F16(accO[2 * gp], ph[ks], vh4);
                MMA_F16(accO[2 * gp + 1], ph[ks], vh4 + 2);
            }
        }
        __syncthreads();
    }

    // ---- epilogue: hi-only vectorized stores ----
    float inv0 = 1.0f / rsum0, inv1 = 1.0f / rsum1;
#pragma unroll
    for (int nf = 0; nf < 8; nf++)
#pragma unroll
        for (int ep = 0; ep < 2; ep++) {
            int i = i0 + w * 16 + r0 + ep * 8;
            int d = nf * 8 + c0;
            float inv = ep ? inv1 : inv0;
            __half2 hh = __floats2half2_rn(accO[nf][2 * ep + 0] * inv,
                                           accO[nf][2 * ep + 1] * inv);
            size_t idx = ((size_t)(b * SEQ + i)) * D_MODEL + h * DK + d;
            *(uint32_t*)&g_oh[idx] = *(uint32_t*)&hh;
        }
}

// ---------------------------------------------------------------------------
extern "C" void kernel_launch(void* const* d_in, const int* in_sizes, int n_in,
                              void* d_out, int out_size)
{
    const float* x  = (const float*)d_in[0];
    const float* Wq = (const float*)d_in[1];
    const float* bq = (const float*)d_in[2];
    const float* Wk = (const float*)d_in[3];
    const float* bk = (const float*)d_in[4];
    const float* Wv = (const float*)d_in[5];
    const float* bv = (const float*)d_in[6];
    const float* Wo = (const float*)d_in[7];
    const float* bo = (const float*)d_in[8];
    const float* Er = (const float*)d_in[9];
    float* out = (float*)d_out;

    cudaFuncSetAttribute(gemm_f16_kernel<1>,
                         cudaFuncAttributeMaxDynamicSharedMemorySize, GEMM_DYN_SMEM);
    cudaFuncSetAttribute(gemm_f16_kernel<0>,
                         cudaFuncAttributeMaxDynamicSharedMemorySize, GEMM_DYN_SMEM);
    cudaFuncSetAttribute(attn_mma_kernel,
                         cudaFuncAttributeMaxDynamicSharedMemorySize, ATTN_SMEM);

    __half *xh, *xl, *wh, *oh;
    cudaGetSymbolAddress((void**)&xh, g_xh);
    cudaGetSymbolAddress((void**)&xl, g_xl);
    cudaGetSymbolAddress((void**)&wh, g_wh);
    cudaGetSymbolAddress((void**)&oh, g_oh);

    // 0) convert: x split fp16; weights & Er hi-only fp16
    {
        int total = (MTOT * D_MODEL + 4 * D_MODEL * D_MODEL + ELEN * DK) / 4;
        convert_xw_kernel<<<(total + 255) / 256, 256>>>(x, Wq, Wk, Wv, Wo, Er);
    }
    // 1) fused QKV projection (Q/K 2-term, V 1-term) -> Q split, K hi, V^T hi
    {
        dim3 grid(3072 / 128, MTOT / 128);
        gemm_f16_kernel<1><<<grid, 512, GEMM_DYN_SMEM>>>(
            xh, xl, wh, bq, bk, bv, nullptr, 0);
    }
    // 2) pipelined MMA attention -> O hi
    {
        dim3 grid(SEQ / 128, BHT);           // 8 x 32
        attn_mma_kernel<<<grid, 256, ATTN_SMEM>>>();
    }
    // 3) output projection (1-term) -> out
    {
        dim3 grid(D_MODEL / 128, MTOT / 128);
        gemm_f16_kernel<0><<<grid, 512, GEMM_DYN_SMEM>>>(
            oh, oh, wh + (size_t)3 * D_MODEL * D_MODEL,
            bo, bo, bo, out, 1);
    }
}

// round 17
// speedup vs baseline: 2.0308x; 1.1512x over previous
#include <cuda_runtime.h>
#include <cuda_fp16.h>
#include <math.h>
#include <stdint.h>

#define D_MODEL 1024
#define NH      16
#define DK      64
#define BATCH   2
#define SEQ     1024
#define BHT     (BATCH*NH)          // 32
#define MTOT    (BATCH*SEQ)         // 2048
#define ELEN    (2*SEQ-1)           // 2047

// ---------------- scratch (device globals; no allocation allowed) ----------
__device__ __half g_xh[MTOT*D_MODEL];        // x hi only
__device__ __half g_wh[4*D_MODEL*D_MODEL];   // Wq|Wk|Wv|Wo (hi only)
__device__ __half g_oh[MTOT*D_MODEL];        // attention out (hi only)

__device__ __half g_Qh[BHT*SEQ*DK];   // [bh][s][d], pre-scaled 1/8 (split)
__device__ __half g_Ql[BHT*SEQ*DK];
__device__ __half g_Kh[BHT*SEQ*DK];   // hi only
__device__ __half g_Vth[BHT*DK*SEQ];  // [bh][d][s]  transposed, hi only
__device__ __half g_Eh[ELEN*DK];      // hi only

// ---------------- helpers ---------------------------------------------------
__device__ __forceinline__ uint32_t smem_u32(const void* p) {
    uint32_t a;
    asm("{ .reg .u64 t; cvta.to.shared.u64 t, %1; cvt.u32.u64 %0, t; }"
        : "=r"(a) : "l"(p));
    return a;
}

#define CPA16(dst_u32, src_ptr) \
    asm volatile("cp.async.ca.shared.global [%0], [%1], 16;" \
                 :: "r"(dst_u32), "l"(src_ptr) : "memory")
#define CP_COMMIT() asm volatile("cp.async.commit_group;" ::: "memory")
#define CP_WAIT0()  asm volatile("cp.async.wait_group 0;" ::: "memory")
#define CP_WAIT1()  asm volatile("cp.async.wait_group 1;" ::: "memory")

#define LDMATRIX_X4(r0, r1, r2, r3, addr) \
    asm("ldmatrix.sync.aligned.m8n8.x4.shared.b16 {%0,%1,%2,%3}, [%4];" \
        : "=r"(r0), "=r"(r1), "=r"(r2), "=r"(r3) : "r"(addr))

#define MMA_F16(c, a, b) \
    asm("mma.sync.aligned.m16n8k16.row.col.f32.f16.f16.f32 " \
        "{%0,%1,%2,%3}, {%4,%5,%6,%7}, {%8,%9}, {%0,%1,%2,%3};" \
        : "+f"((c)[0]), "+f"((c)[1]), "+f"((c)[2]), "+f"((c)[3]) \
        : "r"((a)[0]), "r"((a)[1]), "r"((a)[2]), "r"((a)[3]), \
          "r"((b)[0]), "r"((b)[1]))

// Load B-fragments for TWO n-frags with one ldmatrix.x4.
__device__ __forceinline__ void ldmB(const __half* base, int stride,
                                     int row0, int kcol, int lane, uint32_t* r)
{
    int sel = (lane >> 4) & 1;
    int row = row0 + sel * 8 + (lane & 7);
    int col = kcol + ((lane >> 3) & 1) * 8;
    uint32_t a = smem_u32(base + row * stride + col);
    LDMATRIX_X4(r[0], r[1], r[2], r[3], a);
}

__device__ __forceinline__ uint32_t pack_h2(float lo, float hi) {
    __half2 t = __floats2half2_rn(lo, hi);
    return *(uint32_t*)&t;
}
__device__ __forceinline__ void split_h(float v, __half& h, __half& l) {
    h = __float2half_rn(v);
    l = __float2half_rn(v - __half2float(h));
}
__device__ __forceinline__ void split_h2(float v0, float v1,
                                         uint32_t& hp, uint32_t& lp) {
    __half h0, l0, h1, l1;
    split_h(v0, h0, l0);
    split_h(v1, h1, l1);
    __half2 hh; hh.x = h0; hh.y = h1;
    __half2 ll; ll.x = l0; ll.y = l1;
    hp = *(uint32_t*)&hh;
    lp = *(uint32_t*)&ll;
}

// ---------------------------------------------------------------------------
// fp32 -> fp16 hi conversion (x, weights, Er).
// ---------------------------------------------------------------------------
__global__ void convert_xw_kernel(const float* __restrict__ x,
                                  const float* __restrict__ Wq, const float* __restrict__ Wk,
                                  const float* __restrict__ Wv, const float* __restrict__ Wo,
                                  const float* __restrict__ Er)
{
    const int NX = MTOT * D_MODEL / 4;
    const int NW = D_MODEL * D_MODEL / 4;
    const int NE = ELEN * DK / 4;
    int g = blockIdx.x * blockDim.x + threadIdx.x;
    if (g >= NX + 4 * NW + NE) return;
    const float* src;
    __half* dst;
    if (g < NX) { src = x + g * 4; dst = g_xh + g * 4; }
    else if (g < NX + 4 * NW) {
        int wi = g - NX;
        int which = wi / NW;
        int off = wi - which * NW;
        const float* W = (which == 0) ? Wq : (which == 1) ? Wk : (which == 2) ? Wv : Wo;
        src = W + off * 4;
        dst = g_wh + (size_t)which * NW * 4 + off * 4;
    } else {
        int ei = g - NX - 4 * NW;
        src = Er + ei * 4; dst = g_Eh + ei * 4;
    }
    float4 v = *(const float4*)src;
    __half hv[4] = {__float2half_rn(v.x), __float2half_rn(v.y),
                    __float2half_rn(v.z), __float2half_rn(v.w)};
    *(uint2*)dst = *(uint2*)hv;
}

// ---------------------------------------------------------------------------
// 1-term fp16 mma.sync GEMM: C = Ah * Bh^T.
// 512 threads / 16 warps, 128x128 tile, warp 32x32, 3-stage cp.async, BK=32.
// mode 0: epilogue -> Q split / K hi / V^T hi.  mode 1: -> fp32 out + bias.
// ---------------------------------------------------------------------------
#define HSTR 40
#define MAT_HALVES (128*HSTR)
#define BUF_HALVES (2*MAT_HALVES)              // Ah, Bh
#define GSTAGES 3
#define GEMM_DYN_SMEM (GSTAGES*BUF_HALVES*2)   // 61440 B

__global__ __launch_bounds__(512, 1)
void gemm_f16_kernel(const __half* __restrict__ Ah, const __half* __restrict__ Bh,
                     const float* __restrict__ bias0, const float* __restrict__ bias1,
                     const float* __restrict__ bias2,
                     float* __restrict__ Cout, int mode)
{
    extern __shared__ __half sm[];

    const int tid  = threadIdx.x;
    const int wid  = tid >> 5;          // 0..15
    const int lane = tid & 31;
    const int warp_m = wid >> 2;        // 0..3
    const int warp_n = wid & 3;         // 0..3
    const int m0 = blockIdx.y * 128;
    const int n0 = blockIdx.x * 128;
    const int which = n0 >> 10;
    const int n0m = n0 & 1023;
    const float* biasm = (which == 0) ? bias0 : (which == 1) ? bias1 : bias2;

    float acc[2][4][4];
#pragma unroll
    for (int f = 0; f < 2; f++)
#pragma unroll
        for (int g = 0; g < 4; g++)
#pragma unroll
            for (int e = 0; e < 4; e++) acc[f][g][e] = 0.f;

    const int lrow = tid >> 2;          // 0..127
    const int lk   = (tid & 3) * 8;     // 0,8,16,24
    const uint32_t smb = smem_u32(sm);

    auto issue = [&](int c) {
        uint32_t bb = smb + (c % GSTAGES) * BUF_HALVES * 2;
        int kg = c * 32 + lk;
        uint32_t doff = (lrow * HSTR + lk) * 2;
        CPA16(bb + 0 * MAT_HALVES * 2 + doff, Ah + (size_t)(m0 + lrow) * 1024 + kg);
        CPA16(bb + 1 * MAT_HALVES * 2 + doff, Bh + (size_t)(n0 + lrow) * 1024 + kg);
        CP_COMMIT();
    };

    issue(0);
    issue(1);

    const int a_r   = lane & 15;
    const int a_kof = (lane >> 4) * 8;

    for (int c = 0; c < 32; c++) {
        if (c < 31) CP_WAIT1(); else CP_WAIT0();
        __syncthreads();
        if (c + 2 < 32) issue(c + 2);

        __half* cb = sm + (c % GSTAGES) * BUF_HALVES;
#pragma unroll
        for (int ks = 0; ks < 2; ks++) {
            uint32_t aH[2][4], bH[2][4];
#pragma unroll
            for (int f = 0; f < 2; f++) {
                int row = warp_m * 32 + f * 16 + a_r;
                uint32_t addrH = smem_u32(&cb[0 * MAT_HALVES + row * HSTR + ks * 16 + a_kof]);
                LDMATRIX_X4(aH[f][0], aH[f][1], aH[f][2], aH[f][3], addrH);
            }
            ldmB(&cb[1 * MAT_HALVES], HSTR, warp_n * 32 +  0, ks * 16, lane, bH[0]);
            ldmB(&cb[1 * MAT_HALVES], HSTR, warp_n * 32 + 16, ks * 16, lane, bH[1]);
#pragma unroll
            for (int f = 0; f < 2; f++)
#pragma unroll
                for (int g = 0; g < 4; g++) {
                    const uint32_t* ph = &bH[g >> 1][(g & 1) * 2];
                    MMA_F16(acc[f][g], aH[f], ph);
                }
        }
        __syncthreads();
    }

    if (mode == 0) {
        const float scale = (which == 0) ? 0.125f : 1.0f;
#pragma unroll
        for (int f = 0; f < 2; f++) {
            int mrow0 = m0 + warp_m * 32 + f * 16 + (lane >> 2);
#pragma unroll
            for (int g = 0; g < 4; g++) {
                int ncol = n0m + warp_n * 32 + g * 8 + (lane & 3) * 2;  // even
#pragma unroll
                for (int ep = 0; ep < 2; ep++) {
                    int m = mrow0 + ep * 8;
                    int b = m >> 10, s = m & 1023;
                    float v0 = (acc[f][g][2 * ep + 0] + biasm[ncol]) * scale;
                    float v1 = (acc[f][g][2 * ep + 1] + biasm[ncol + 1]) * scale;
                    if (which == 2) {
                        int h = ncol >> 6;
#pragma unroll
                        for (int e = 0; e < 2; e++) {
                            int d = (ncol + e) & 63;
                            float val = e ? v1 : v0;
                            size_t idx = ((size_t)(b * NH + h) * DK + d) * SEQ + s;
                            g_Vth[idx] = __float2half_rn(val);
                        }
                    } else if (which == 0) {
                        int h = ncol >> 6, d = ncol & 63;
                        uint32_t hp, lp;
                        split_h2(v0, v1, hp, lp);
                        size_t idx = ((size_t)(b * NH + h) * SEQ + s) * DK + d;
                        *(uint32_t*)&g_Qh[idx] = hp;
                        *(uint32_t*)&g_Ql[idx] = lp;
                    } else {
                        int h = ncol >> 6, d = ncol & 63;
                        __half2 kk = __floats2half2_rn(v0, v1);
                        size_t idx = ((size_t)(b * NH + h) * SEQ + s) * DK + d;
                        *(uint32_t*)&g_Kh[idx] = *(uint32_t*)&kk;
                    }
                }
            }
        }
    } else {
#pragma unroll
        for (int f = 0; f < 2; f++) {
            int mrow0 = m0 + warp_m * 32 + f * 16 + (lane >> 2);
#pragma unroll
            for (int g = 0; g < 4; g++) {
                int ncol = n0 + warp_n * 32 + g * 8 + (lane & 3) * 2;
#pragma unroll
                for (int ep = 0; ep < 2; ep++) {
                    int m = mrow0 + ep * 8;
                    float2 v = make_float2(acc[f][g][2 * ep] + biasm[ncol],
                                           acc[f][g][2 * ep + 1] + biasm[ncol + 1]);
                    *(float2*)&Cout[(size_t)m * D_MODEL + ncol] = v;
                }
            }
        }
    }
}

// ---------------------------------------------------------------------------
// Pipelined MMA flash-attention, fp16, rolling circular E buffer.
// S: 2-term (Qh+Ql)·K.  G: 1-term Qh·E.  PV: 1-term Ph·V.  O hi-only.
// ---------------------------------------------------------------------------
#define ASTR  72
#define GBSTR 84
#define KV_STAGE_HALVES (2*64*ASTR)             // Kh + Vh
#define ST_KH 0
#define ST_VH (64*ASTR)
#define E_OFF_HALVES (2*KV_STAGE_HALVES)        // 18432
#define EH_OFF E_OFF_HALVES
#define G_OFF_HALVES (E_OFF_HALVES + 256*ASTR)  // 36864
#define ATTN_SMEM (G_OFF_HALVES*2 + 8*16*GBSTR*4)  // 116736 B

__device__ __forceinline__ void attn_issue_tile(
    uint32_t smb, int jt, int tid, int i0,
    const __half* Khg, const __half* Vhg)
{
    const int j0 = jt * 64;
    const uint32_t kvbase = smb + (jt & 1) * KV_STAGE_HALVES * 2;
    for (int t = tid; t < 512; t += 256) {
        int r = t >> 3, c8 = (t & 7) * 8;
        uint32_t doff = (r * ASTR + c8) * 2;
        CPA16(kvbase + ST_KH * 2 + doff, Khg + (size_t)(j0 + r) * DK + c8);
        CPA16(kvbase + ST_VH * 2 + doff, Vhg + (size_t)r * SEQ + j0 + c8);
    }
    const int rlo = (SEQ - 1) + i0 - j0 - 63;
    const int cnt8 = (jt == 0) ? 1536 : 512;
    for (int t = tid; t < cnt8; t += 256) {
        int r = t >> 3, c8 = (t & 7) * 8;
        int er = rlo + r;
        int ers = (er > ELEN - 1) ? (ELEN - 1) : er;
        uint32_t phys = (uint32_t)er & 255u;
        uint32_t doff = (phys * ASTR + c8) * 2;
        CPA16(smb + EH_OFF * 2 + doff, g_Eh + (size_t)ers * DK + c8);
    }
    CP_COMMIT();
}

__global__ __launch_bounds__(256)
void attn_mma_kernel()
{
    extern __shared__ __half smh[];
    float* sG = (float*)(smh + G_OFF_HALVES);
    __half* sQh = (__half*)sG;                 // staging overlay
    __half* sQl = sQh + 128 * ASTR;
    __half* sEh = smh + EH_OFF;

    const int tid  = threadIdx.x;
    const int lane = tid & 31;
    const int w    = tid >> 5;
    const int bh = blockIdx.y;
    const int i0 = blockIdx.x * 128;
    const int b = bh >> 4, h = bh & 15;

    const __half* Qhg = g_Qh + (size_t)bh * SEQ * DK;
    const __half* Qlg = g_Ql + (size_t)bh * SEQ * DK;
    const __half* Khg = g_Kh + (size_t)bh * SEQ * DK;
    const __half* Vhg = g_Vth + (size_t)bh * DK * SEQ;
    const uint32_t smb = smem_u32(smh);

    for (int t = tid; t < 1024; t += 256) {
        int r = t >> 3, c8 = (t & 7) * 8;
        *(uint4*)&sQh[r * ASTR + c8] = *(const uint4*)(Qhg + (size_t)(i0 + r) * DK + c8);
        *(uint4*)&sQl[r * ASTR + c8] = *(const uint4*)(Qlg + (size_t)(i0 + r) * DK + c8);
    }
    __syncthreads();
    uint32_t qh[4][4], ql[4][4];
#pragma unroll
    for (int ks = 0; ks < 4; ks++) {
        uint32_t aH = smem_u32(&sQh[(w * 16 + (lane & 15)) * ASTR + ks * 16 + (lane >> 4) * 8]);
        LDMATRIX_X4(qh[ks][0], qh[ks][1], qh[ks][2], qh[ks][3], aH);
        uint32_t aL = smem_u32(&sQl[(w * 16 + (lane & 15)) * ASTR + ks * 16 + (lane >> 4) * 8]);
        LDMATRIX_X4(ql[ks][0], ql[ks][1], ql[ks][2], ql[ks][3], aL);
    }
    __syncthreads();

    attn_issue_tile(smb, 0, tid, i0, Khg, Vhg);

    float accO[8][4];
#pragma unroll
    for (int nf = 0; nf < 8; nf++)
#pragma unroll
        for (int e = 0; e < 4; e++) accO[nf][e] = 0.f;
    float rmax0 = -1e30f, rmax1 = -1e30f, rsum0 = 0.f, rsum1 = 0.f;

    const int r0 = lane >> 2;
    const int c0 = (lane & 3) * 2;
    float* sGw = sG + w * 16 * GBSTR;

    for (int jt = 0; jt < 16; jt++) {
        if (jt < 15) {
            attn_issue_tile(smb, jt + 1, tid, i0, Khg, Vhg);
            CP_WAIT1();
        } else {
            CP_WAIT0();
        }
        __syncthreads();

        __half* st = smh + (jt & 1) * KV_STAGE_HALVES;
        __half* sKh = st + ST_KH;
        __half* sVh = st + ST_VH;

        const int rbase = (SEQ - 1) + i0 - jt * 64 - 63;
        const int rb255 = rbase & 255;

        // ---- G = Qh * Eband^T (1-term), band-limited: nf in [2w, 2w+10) ----
        float gac[10][4];
#pragma unroll
        for (int bi = 0; bi < 10; bi++)
#pragma unroll
            for (int e = 0; e < 4; e++) gac[bi][e] = 0.f;
#pragma unroll
        for (int ks = 0; ks < 4; ks++) {
#pragma unroll
            for (int bp = 0; bp < 5; bp++) {
                uint32_t eh4[4];
                int row0 = (rb255 + (2 * w + 2 * bp) * 8) & 255;
                ldmB(sEh, ASTR, row0, ks * 16, lane, eh4);
                MMA_F16(gac[2 * bp], qh[ks], eh4);
                MMA_F16(gac[2 * bp + 1], qh[ks], eh4 + 2);
            }
        }
#pragma unroll
        for (int bi = 0; bi < 10; bi++) {
            *(float2*)&sGw[r0 * GBSTR + bi * 8 + c0] = make_float2(gac[bi][0], gac[bi][1]);
            *(float2*)&sGw[(r0 + 8) * GBSTR + bi * 8 + c0] = make_float2(gac[bi][2], gac[bi][3]);
        }

        // ---- S = Q * K^T (2-term) ----
        float s[8][4];
#pragma unroll
        for (int nf = 0; nf < 8; nf++)
#pragma unroll
            for (int e = 0; e < 4; e++) s[nf][e] = 0.f;
#pragma unroll
        for (int ks = 0; ks < 4; ks++) {
#pragma unroll
            for (int gp = 0; gp < 4; gp++) {
                uint32_t kh4[4];
                ldmB(sKh, ASTR, gp * 16, ks * 16, lane, kh4);
                MMA_F16(s[2 * gp], qh[ks], kh4);
                MMA_F16(s[2 * gp], ql[ks], kh4);
                MMA_F16(s[2 * gp + 1], qh[ks], kh4 + 2);
                MMA_F16(s[2 * gp + 1], ql[ks], kh4 + 2);
            }
        }
        __syncwarp();

        // ---- gather BD from G band and add ----
#pragma unroll
        for (int nf = 0; nf < 8; nf++)
#pragma unroll
            for (int e = 0; e < 4; e++) {
                int iw = r0 + ((e >> 1) << 3);
                int jl = nf * 8 + c0 + (e & 1);
                s[nf][e] += sGw[iw * GBSTR + (iw - jl + 63)];
            }

        // ---- online softmax ----
        float mx0 = -1e30f, mx1 = -1e30f;
#pragma unroll
        for (int nf = 0; nf < 8; nf++) {
            mx0 = fmaxf(mx0, fmaxf(s[nf][0], s[nf][1]));
            mx1 = fmaxf(mx1, fmaxf(s[nf][2], s[nf][3]));
        }
#pragma unroll
        for (int o = 1; o <= 2; o <<= 1) {
            mx0 = fmaxf(mx0, __shfl_xor_sync(0xffffffffu, mx0, o));
            mx1 = fmaxf(mx1, __shfl_xor_sync(0xffffffffu, mx1, o));
        }
        float nm0 = fmaxf(rmax0, mx0), nm1 = fmaxf(rmax1, mx1);
        float al0 = __expf(rmax0 - nm0), al1 = __expf(rmax1 - nm1);
        rmax0 = nm0; rmax1 = nm1;
        float ls0 = 0.f, ls1 = 0.f;
#pragma unroll
        for (int nf = 0; nf < 8; nf++) {
            s[nf][0] = __expf(s[nf][0] - nm0);
            s[nf][1] = __expf(s[nf][1] - nm0);
            s[nf][2] = __expf(s[nf][2] - nm1);
            s[nf][3] = __expf(s[nf][3] - nm1);
            ls0 += s[nf][0] + s[nf][1];
            ls1 += s[nf][2] + s[nf][3];
        }
#pragma unroll
        for (int o = 1; o <= 2; o <<= 1) {
            ls0 += __shfl_xor_sync(0xffffffffu, ls0, o);
            ls1 += __shfl_xor_sync(0xffffffffu, ls1, o);
        }
        rsum0 = rsum0 * al0 + ls0;
        rsum1 = rsum1 * al1 + ls1;
#pragma unroll
        for (int nf = 0; nf < 8; nf++) {
            accO[nf][0] *= al0; accO[nf][1] *= al0;
            accO[nf][2] *= al1; accO[nf][3] *= al1;
        }

        // ---- pack P fragments (hi only) ----
        uint32_t ph[4][4];
#pragma unroll
        for (int ks = 0; ks < 4; ks++) {
            int f0 = 2 * ks, f1 = 2 * ks + 1;
            ph[ks][0] = pack_h2(s[f0][0], s[f0][1]);
            ph[ks][1] = pack_h2(s[f0][2], s[f0][3]);
            ph[ks][2] = pack_h2(s[f1][0], s[f1][1]);
            ph[ks][3] = pack_h2(s[f1][2], s[f1][3]);
        }

        // ---- O += P * V (1-term) ----
#pragma unroll
        for (int ks = 0; ks < 4; ks++) {
#pragma unroll
            for (int gp = 0; gp < 4; gp++) {
                uint32_t vh4[4];
                ldmB(sVh, ASTR, gp * 16, ks * 16, lane, vh4);
                MMA_F16(accO[2 * gp], ph[ks], vh4);
                MMA_F16(accO[2 * gp + 1], ph[ks], vh4 + 2);
            }
        }
        __syncthreads();
    }

    // ---- epilogue: hi-only vectorized stores ----
    float inv0 = 1.0f / rsum0, inv1 = 1.0f / rsum1;
#pragma unroll
    for (int nf = 0; nf < 8; nf++)
#pragma unroll
        for (int ep = 0; ep < 2; ep++) {
            int i = i0 + w * 16 + r0 + ep * 8;
            int d = nf * 8 + c0;
            float inv = ep ? inv1 : inv0;
            __half2 hh = __floats2half2_rn(accO[nf][2 * ep + 0] * inv,
                                           accO[nf][2 * ep + 1] * inv);
            size_t idx = ((size_t)(b * SEQ + i)) * D_MODEL + h * DK + d;
            *(uint32_t*)&g_oh[idx] = *(uint32_t*)&hh;
        }
}

// ---------------------------------------------------------------------------
extern "C" void kernel_launch(void* const* d_in, const int* in_sizes, int n_in,
                              void* d_out, int out_size)
{
    const float* x  = (const float*)d_in[0];
    const float* Wq = (const float*)d_in[1];
    const float* bq = (const float*)d_in[2];
    const float* Wk = (const float*)d_in[3];
    const float* bk = (const float*)d_in[4];
    const float* Wv = (const float*)d_in[5];
    const float* bv = (const float*)d_in[6];
    const float* Wo = (const float*)d_in[7];
    const float* bo = (const float*)d_in[8];
    const float* Er = (const float*)d_in[9];
    float* out = (float*)d_out;

    cudaFuncSetAttribute(gemm_f16_kernel,
                         cudaFuncAttributeMaxDynamicSharedMemorySize, GEMM_DYN_SMEM);
    cudaFuncSetAttribute(attn_mma_kernel,
                         cudaFuncAttributeMaxDynamicSharedMemorySize, ATTN_SMEM);

    __half *xh, *wh, *oh;
    cudaGetSymbolAddress((void**)&xh, g_xh);
    cudaGetSymbolAddress((void**)&wh, g_wh);
    cudaGetSymbolAddress((void**)&oh, g_oh);

    // 0) convert x, weights, Er to fp16 (hi)
    {
        int total = (MTOT * D_MODEL + 4 * D_MODEL * D_MODEL + ELEN * DK) / 4;
        convert_xw_kernel<<<(total + 255) / 256, 256>>>(x, Wq, Wk, Wv, Wo, Er);
    }
    // 1) fused QKV projection (1-term) -> Q split, K hi, V^T hi
    {
        dim3 grid(3072 / 128, MTOT / 128);
        gemm_f16_kernel<<<grid, 512, GEMM_DYN_SMEM>>>(
            xh, wh, bq, bk, bv, nullptr, 0);
    }
    // 2) pipelined MMA attention -> O hi
    {
        dim3 grid(SEQ / 128, BHT);           // 8 x 32
        attn_mma_kernel<<<grid, 256, ATTN_SMEM>>>();
    }
    // 3) output projection (1-term) -> out
    {
        dim3 grid(D_MODEL / 128, MTOT / 128);
        gemm_f16_kernel<<<grid, 512, GEMM_DYN_SMEM>>>(
            oh, wh + (size_t)3 * D_MODEL * D_MODEL,
            bo, bo, bo, out, 1);
    }
}